// round 3
// baseline (speedup 1.0000x reference)
#include <cuda_runtime.h>

// Problem constants: B=2, S=1024, D=1024, H=16, KVH=4, HD=64, TOT=1536
// Inputs (metadata order):
//  0 local_c (2,1024,1024) 1 global_c 2 freqs_cos (1024,32) 3 freqs_sin
//  4 W_lc (1536,1024) 5 W_gc 6 g_q_lc (1024) 7 g_k_lc (256) 8 g_q_gc 9 g_k_gc
// 10 W_local (1024,2048) 11 b_local (1024) 12 g_lc_out (1024)
// 13 W_global 14 b_global 15 g_gc_out
// Output: concat(x_lc, x_gc) = 2 * (2*1024*1024) floats.

typedef unsigned long long ull;

// ---------------- f32x2 packed-FMA helpers (sm_100+) ----------------
static __device__ __forceinline__ ull pack2(float lo, float hi){
  ull r; asm("mov.b64 %0, {%1, %2};" : "=l"(r) : "f"(lo), "f"(hi)); return r;
}
static __device__ __forceinline__ float2 unpack2(ull v){
  float2 f; asm("mov.b64 {%0, %1}, %2;" : "=f"(f.x), "=f"(f.y) : "l"(v)); return f;
}
static __device__ __forceinline__ ull ffma2(ull a, ull b, ull c){
  ull d; asm("fma.rn.f32x2 %0, %1, %2, %3;" : "=l"(d) : "l"(a), "l"(b), "l"(c)); return d;
}

// ---------------- scratch (device globals: no allocation allowed) ----------------
__device__ float g_comb_lc[2048*1536];
__device__ float g_comb_gc[2048*1536];
__device__ float g_qp[2*16*1024*128];          // [b][h][s][128]  (lc 0..63 | gc 64..127)
__device__ float g_kp[2*4*1024*128];           // [b][kvh][s][128]
__device__ float g_vp[2*4*1024*128];           // [b][kvh][s][128]
__device__ float g_scr[33554432];              // scores [b*H+h][s][s]  (2*16*1024*1024)
__device__ float g_ao[2048*2048];              // attn out [b][s][h*128+d]
__device__ float g_yy[2*2048*1024];            // proj outputs: lc rows then gc rows

// ---------------- generic batched GEMM: C = cscale*(A @ op(B)) + bias ----------------
// A: [M,K] row-major (lda). BNT=true: B is [N,K] row-major (NT). BNT=false: B is [K,N] (NN).
// batch z: A += z*sA;  B += (z/zDivB)*sB;  C += (z/zDivC)*sC1 + (z%zDivC)*sC2.
// M,N,K multiples of 128/128/16 (guaranteed by caller).
#define BM 128
#define BN 128
#define BK 16

template<bool BNT>
__global__ __launch_bounds__(256, 2)
void gemm_f32(const float* __restrict__ A, const float* __restrict__ Bm,
              float* __restrict__ C, const float* __restrict__ bias,
              int M, int N, int K, int lda, int ldb, int ldc,
              long long sA, long long sB, int zDivB,
              long long sC1, long long sC2, int zDivC,
              float cscale)
{
  __shared__ __align__(16) float As[BK][BM+4];
  __shared__ __align__(16) float Bs[BK][BN+4];
  const int z = blockIdx.z;
  A  += (long long)z * sA;
  Bm += (long long)(z / zDivB) * sB;
  C  += (long long)(z / zDivC) * sC1 + (long long)(z % zDivC) * sC2;

  const int m0 = blockIdx.y * BM, n0 = blockIdx.x * BN;
  const int tid = threadIdx.x, tx = tid & 15, ty = tid >> 4;

  ull acc[8][4];
#pragma unroll
  for (int i=0;i<8;i++)
#pragma unroll
    for (int j=0;j<4;j++) acc[i][j] = 0ull;

  for (int k0 = 0; k0 < K; k0 += BK){
    // A tile: 128x16, transposed into As[k][m]
#pragma unroll
    for (int i=0;i<2;i++){
      int f = tid + i*256;
      int m = f >> 2, k4 = (f & 3) << 2;
      float4 v = *(const float4*)(A + (long long)(m0+m)*lda + (k0 + k4));
      As[k4+0][m]=v.x; As[k4+1][m]=v.y; As[k4+2][m]=v.z; As[k4+3][m]=v.w;
    }
    if (BNT){
#pragma unroll
      for (int i=0;i<2;i++){
        int f = tid + i*256;
        int n = f >> 2, k4 = (f & 3) << 2;
        float4 v = *(const float4*)(Bm + (long long)(n0+n)*ldb + (k0 + k4));
        Bs[k4+0][n]=v.x; Bs[k4+1][n]=v.y; Bs[k4+2][n]=v.z; Bs[k4+3][n]=v.w;
      }
    } else {
#pragma unroll
      for (int i=0;i<2;i++){
        int f = tid + i*256;
        int kr = f >> 5, n4 = (f & 31) << 2;
        float4 v = *(const float4*)(Bm + (long long)(k0+kr)*ldb + (n0 + n4));
        *(float4*)&Bs[kr][n4] = v;
      }
    }
    __syncthreads();
#pragma unroll
    for (int kk=0; kk<BK; kk++){
      float4 a0 = *(const float4*)&As[kk][ty*4];
      float4 a1 = *(const float4*)&As[kk][64 + ty*4];
      float4 b0 = *(const float4*)&Bs[kk][tx*4];
      float4 b1 = *(const float4*)&Bs[kk][64 + tx*4];
      ull bp0 = pack2(b0.x,b0.y), bp1 = pack2(b0.z,b0.w);
      ull bp2 = pack2(b1.x,b1.y), bp3 = pack2(b1.z,b1.w);
      float av[8] = {a0.x,a0.y,a0.z,a0.w,a1.x,a1.y,a1.z,a1.w};
#pragma unroll
      for (int i=0;i<8;i++){
        ull ap = pack2(av[i], av[i]);
        acc[i][0]=ffma2(ap,bp0,acc[i][0]);
        acc[i][1]=ffma2(ap,bp1,acc[i][1]);
        acc[i][2]=ffma2(ap,bp2,acc[i][2]);
        acc[i][3]=ffma2(ap,bp3,acc[i][3]);
      }
    }
    __syncthreads();
  }
#pragma unroll
  for (int i=0;i<8;i++){
    int m = m0 + ((i<4) ? (ty*4+i) : (64+ty*4+i-4));
#pragma unroll
    for (int jh=0;jh<2;jh++){
      int n = n0 + (jh ? (64+tx*4) : (tx*4));
      float2 lo = unpack2(acc[i][jh*2+0]);
      float2 hi = unpack2(acc[i][jh*2+1]);
      float4 v = make_float4(lo.x*cscale, lo.y*cscale, hi.x*cscale, hi.y*cscale);
      if (bias){ v.x+=bias[n]; v.y+=bias[n+1]; v.z+=bias[n+2]; v.w+=bias[n+3]; }
      *(float4*)(C + (long long)m*ldc + n) = v;
    }
  }
}

// ---------------- RMSNorm (full-row) + RoPE + GQA pack ----------------
// One block per (b,s) row of both streams' comb (1536 each: 1024 q | 256 k | 256 v).
__global__ __launch_bounds__(256)
void norm_rope_pack(const float* __restrict__ cl, const float* __restrict__ cg,
                    const float* __restrict__ cosT, const float* __restrict__ sinT,
                    const float* __restrict__ gql, const float* __restrict__ gkl,
                    const float* __restrict__ gqg, const float* __restrict__ gkg,
                    float* __restrict__ qp, float* __restrict__ kp, float* __restrict__ vp)
{
  const int bs = blockIdx.x;
  const int b = bs >> 10, s = bs & 1023;
  const int t = threadIdx.x;
  const float* rl = cl + (long long)bs*1536;
  const float* rg = cg + (long long)bs*1536;

  float sql=0.f, sqg=0.f;
#pragma unroll
  for (int i=t;i<1024;i+=256){ float x=rl[i]; sql+=x*x; float y=rg[i]; sqg+=y*y; }
  float xk=rl[1024+t], yk=rg[1024+t];
  float skl = xk*xk, skg = yk*yk;

  __shared__ float4 red[8];
  float4 v4 = make_float4(sql,sqg,skl,skg);
#pragma unroll
  for (int o=16;o;o>>=1){
    v4.x += __shfl_xor_sync(0xffffffffu, v4.x, o);
    v4.y += __shfl_xor_sync(0xffffffffu, v4.y, o);
    v4.z += __shfl_xor_sync(0xffffffffu, v4.z, o);
    v4.w += __shfl_xor_sync(0xffffffffu, v4.w, o);
  }
  const int w = t>>5, l = t&31;
  if (!l) red[w]=v4;
  __syncthreads();
  if (t==0){
    float4 a = red[0];
    for (int i=1;i<8;i++){ a.x+=red[i].x; a.y+=red[i].y; a.z+=red[i].z; a.w+=red[i].w; }
    red[0]=a;
  }
  __syncthreads();
  float4 tot = red[0];
  const float rql = rsqrtf(tot.x*(1.f/1024.f)+1e-5f);
  const float rqg = rsqrtf(tot.y*(1.f/1024.f)+1e-5f);
  const float rkl = rsqrtf(tot.z*(1.f/256.f)+1e-5f);
  const float rkg = rsqrtf(tot.w*(1.f/256.f)+1e-5f);

  // q: 512 rope-pairs per stream
#pragma unroll
  for (int pp=t; pp<512; pp+=256){
    int h = pp>>5, p = pp&31;
    float c = cosT[s*32+p], sn = sinT[s*32+p];
    int d0 = h*64 + 2*p;
    long long base = (((long long)(b*16+h))*1024 + s)*128;
    float x0 = rl[d0]*rql*gql[d0];
    float x1 = rl[d0+1]*rql*gql[d0+1];
    qp[base+2*p]   = x0*c - x1*sn;
    qp[base+2*p+1] = x0*sn + x1*c;
    float y0 = rg[d0]*rqg*gqg[d0];
    float y1 = rg[d0+1]*rqg*gqg[d0+1];
    qp[base+64+2*p]   = y0*c - y1*sn;
    qp[base+64+2*p+1] = y0*sn + y1*c;
  }
  // k: 128 rope-pairs per stream
  if (t < 128){
    int kh = t>>5, p = t&31;
    float c = cosT[s*32+p], sn = sinT[s*32+p];
    int gd = kh*64 + 2*p;
    long long base = (((long long)(b*4+kh))*1024 + s)*128;
    float x0 = rl[1024+gd]*rkl*gkl[gd];
    float x1 = rl[1024+gd+1]*rkl*gkl[gd+1];
    kp[base+2*p]   = x0*c - x1*sn;
    kp[base+2*p+1] = x0*sn + x1*c;
    float y0 = rg[1024+gd]*rkg*gkg[gd];
    float y1 = rg[1024+gd+1]*rkg*gkg[gd+1];
    kp[base+64+2*p]   = y0*c - y1*sn;
    kp[base+64+2*p+1] = y0*sn + y1*c;
  }
  // v: raw copy, 256 elems per stream
  {
    int kh = t>>6, d = t&63;
    long long base = (((long long)(b*4+kh))*1024 + s)*128;
    vp[base+d]    = rl[1280+t];
    vp[base+64+d] = rg[1280+t];
  }
}

// ---------------- row softmax over 1024 (in place) ----------------
__global__ __launch_bounds__(128)
void softmax_rows(float* __restrict__ S)
{
  float* r = S + (long long)blockIdx.x * 1024;
  const int t = threadIdx.x;
  float4 a  = ((const float4*)r)[t];
  float4 b2 = ((const float4*)r)[t+128];
  float mx = fmaxf(fmaxf(fmaxf(a.x,a.y),fmaxf(a.z,a.w)),
                   fmaxf(fmaxf(b2.x,b2.y),fmaxf(b2.z,b2.w)));
  __shared__ float sm[4];
#pragma unroll
  for (int o=16;o;o>>=1) mx = fmaxf(mx, __shfl_xor_sync(0xffffffffu,mx,o));
  const int w=t>>5, l=t&31;
  if (!l) sm[w]=mx;
  __syncthreads();
  mx = fmaxf(fmaxf(sm[0],sm[1]),fmaxf(sm[2],sm[3]));
  __syncthreads();
  a.x=__expf(a.x-mx);  a.y=__expf(a.y-mx);  a.z=__expf(a.z-mx);  a.w=__expf(a.w-mx);
  b2.x=__expf(b2.x-mx); b2.y=__expf(b2.y-mx); b2.z=__expf(b2.z-mx); b2.w=__expf(b2.w-mx);
  float s = a.x+a.y+a.z+a.w+b2.x+b2.y+b2.z+b2.w;
#pragma unroll
  for (int o=16;o;o>>=1) s += __shfl_xor_sync(0xffffffffu,s,o);
  if (!l) sm[w]=s;
  __syncthreads();
  const float inv = 1.f/(sm[0]+sm[1]+sm[2]+sm[3]);
  a.x*=inv;  a.y*=inv;  a.z*=inv;  a.w*=inv;
  b2.x*=inv; b2.y*=inv; b2.z*=inv; b2.w*=inv;
  ((float4*)r)[t]=a; ((float4*)r)[t+128]=b2;
}

// ---------------- final RMSNorm -> d_out (rows 0..2047 lc, 2048..4095 gc) ----------------
__global__ __launch_bounds__(256)
void rmsnorm_out(const float* __restrict__ y, const float* __restrict__ glc,
                 const float* __restrict__ ggc, float* __restrict__ out)
{
  const int row = blockIdx.x;
  const float* g = (row < 2048) ? glc : ggc;
  const float* r = y + (long long)row*1024;
  float* o = out + (long long)row*1024;
  const int t = threadIdx.x;
  float4 v = ((const float4*)r)[t];
  float ss = v.x*v.x + v.y*v.y + v.z*v.z + v.w*v.w;
  __shared__ float sm[8];
#pragma unroll
  for (int o2=16;o2;o2>>=1) ss += __shfl_xor_sync(0xffffffffu,ss,o2);
  const int w=t>>5, l=t&31;
  if (!l) sm[w]=ss;
  __syncthreads();
  ss = sm[0]+sm[1]+sm[2]+sm[3]+sm[4]+sm[5]+sm[6]+sm[7];
  const float rsq = rsqrtf(ss*(1.f/1024.f)+1e-5f);
  float4 gv = ((const float4*)g)[t];
  float4 ov = make_float4(v.x*rsq*gv.x, v.y*rsq*gv.y, v.z*rsq*gv.z, v.w*rsq*gv.w);
  ((float4*)o)[t]=ov;
}

// ---------------- launch ----------------
extern "C" void kernel_launch(void* const* d_in, const int* in_sizes, int n_in,
                              void* d_out, int out_size)
{
  (void)in_sizes; (void)n_in; (void)out_size;
  const float* local_c  = (const float*)d_in[0];
  const float* global_c = (const float*)d_in[1];
  const float* fcos     = (const float*)d_in[2];
  const float* fsin     = (const float*)d_in[3];
  const float* W_lc     = (const float*)d_in[4];
  const float* W_gc     = (const float*)d_in[5];
  const float* g_q_lc   = (const float*)d_in[6];
  const float* g_k_lc   = (const float*)d_in[7];
  const float* g_q_gc   = (const float*)d_in[8];
  const float* g_k_gc   = (const float*)d_in[9];
  const float* W_local  = (const float*)d_in[10];
  const float* b_local  = (const float*)d_in[11];
  const float* g_lc_out = (const float*)d_in[12];
  const float* W_global = (const float*)d_in[13];
  const float* b_global = (const float*)d_in[14];
  const float* g_gc_out = (const float*)d_in[15];

  float *comb_lc, *comb_gc, *qp, *kp, *vp, *sc, *ao, *yy;
  cudaGetSymbolAddress((void**)&comb_lc, g_comb_lc);
  cudaGetSymbolAddress((void**)&comb_gc, g_comb_gc);
  cudaGetSymbolAddress((void**)&qp, g_qp);
  cudaGetSymbolAddress((void**)&kp, g_kp);
  cudaGetSymbolAddress((void**)&vp, g_vp);
  cudaGetSymbolAddress((void**)&sc, g_scr);
  cudaGetSymbolAddress((void**)&ao, g_ao);
  cudaGetSymbolAddress((void**)&yy, g_yy);

  // 1,2) QKV projections: comb = x @ W^T   (M=2048, N=1536, K=1024)
  gemm_f32<true><<<dim3(12,16,1),256>>>(local_c,  W_lc, comb_lc, nullptr,
     2048,1536,1024, 1024,1024,1536, 0,0,1, 0,0,1, 1.f);
  gemm_f32<true><<<dim3(12,16,1),256>>>(global_c, W_gc, comb_gc, nullptr,
     2048,1536,1024, 1024,1024,1536, 0,0,1, 0,0,1, 1.f);

  // 3) rmsnorm + rope + pack q/k/v
  norm_rope_pack<<<2048,256>>>(comb_lc, comb_gc, fcos, fsin,
                               g_q_lc, g_k_lc, g_q_gc, g_k_gc, qp, kp, vp);

  // 4) scores = (Q @ K^T)/8, batched over z = b*H+h (kv batch = z/4)
  gemm_f32<true><<<dim3(8,8,32),256>>>(qp, kp, sc, nullptr,
     1024,1024,128, 128,128,1024,
     131072LL, 131072LL, 4,
     1048576LL, 0LL, 1, 0.125f);

  // 5) softmax over rows
  softmax_rows<<<32768,128>>>(sc);

  // 6) attn_out = P @ V (NN), scattered into [b][s][h*128+d]
  gemm_f32<false><<<dim3(1,8,32),256>>>(sc, vp, ao, nullptr,
     1024,128,1024, 1024,128,2048,
     1048576LL, 131072LL, 4,
     2097152LL, 128LL, 16, 1.f);

  // 7,8) output projections + bias
  gemm_f32<true><<<dim3(8,16,1),256>>>(ao, W_local,  yy,                     b_local,
     2048,1024,2048, 2048,2048,1024, 0,0,1, 0,0,1, 1.f);
  gemm_f32<true><<<dim3(8,16,1),256>>>(ao, W_global, yy + (long long)2048*1024, b_global,
     2048,1024,2048, 2048,2048,1024, 0,0,1, 0,0,1, 1.f);

  // 9) final rmsnorm -> d_out (x_lc then x_gc)
  rmsnorm_out<<<4096,256>>>(yy, g_lc_out, g_gc_out, (float*)d_out);
}

// round 5
// speedup vs baseline: 1.5288x; 1.5288x over previous
#include <cuda_runtime.h>
#include <cuda_bf16.h>
#include <cstdint>

// B=2, S=1024, D=1024, H=16, KVH=4, HD=64, TOT=1536
// All GEMMs on tensor cores via mma.sync bf16 (sm_80+ path; tcgen05 rejected by
// the family-generic compute_103 build). fp32-level accuracy via 2-term split:
//   A packed [hi|lo|hi], B packed [hi|hi|lo]  => hi*hi + lo*hi + hi*lo, K' = 3K.

typedef unsigned long long ull;
#define DEVFN static __device__ __forceinline__

// ---------------- PTX helpers ----------------
DEVFN uint32_t smem_u32(const void* p){
  uint32_t a; asm("{ .reg .u64 t; cvta.to.shared.u64 t, %1; cvt.u32.u64 %0, t; }":"=r"(a):"l"(p)); return a;
}
DEVFN void ldsm_x4(uint32_t* r, uint32_t addr){
  asm volatile("ldmatrix.sync.aligned.m8n8.x4.shared.b16 {%0,%1,%2,%3}, [%4];"
    : "=r"(r[0]),"=r"(r[1]),"=r"(r[2]),"=r"(r[3]) : "r"(addr));
}
DEVFN void mma16816(float* c, const uint32_t* a, const uint32_t* b){
  asm volatile("mma.sync.aligned.m16n8k16.row.col.f32.bf16.bf16.f32 "
    "{%0,%1,%2,%3}, {%4,%5,%6,%7}, {%8,%9}, {%0,%1,%2,%3};"
    : "+f"(c[0]),"+f"(c[1]),"+f"(c[2]),"+f"(c[3])
    : "r"(a[0]),"r"(a[1]),"r"(a[2]),"r"(a[3]), "r"(b[0]),"r"(b[1]));
}
DEVFN void cp_async16(uint32_t dst, const void* src){
  asm volatile("cp.async.cg.shared.global [%0], [%1], 16;" :: "r"(dst), "l"(src));
}
#define CP_COMMIT() asm volatile("cp.async.commit_group;" ::: "memory")
#define CP_WAIT0()  asm volatile("cp.async.wait_group 0;" ::: "memory")
#define CP_WAIT1()  asm volatile("cp.async.wait_group 1;" ::: "memory")

DEVFN void bsplit(float x, __nv_bfloat16 &hi, __nv_bfloat16 &lo){
  hi = __float2bfloat16(x);
  lo = __float2bfloat16(x - __bfloat162float(hi));
}

// ---------------- scratch (device globals) ----------------
__device__ __align__(128) __nv_bfloat16 g_xl_pack [2048u*3072u];
__device__ __align__(128) __nv_bfloat16 g_xg_pack [2048u*3072u];
__device__ __align__(128) __nv_bfloat16 g_wlc_pack[1536u*3072u];
__device__ __align__(128) __nv_bfloat16 g_wgc_pack[1536u*3072u];
__device__ __align__(128) __nv_bfloat16 g_wlo_pack[1024u*6144u];
__device__ __align__(128) __nv_bfloat16 g_wgo_pack[1024u*6144u];
__device__ __align__(128) float g_comb_lc[2048u*1536u];
__device__ __align__(128) float g_comb_gc[2048u*1536u];
__device__ __align__(128) __nv_bfloat16 g_q_pack [32u*1024u*384u];
__device__ __align__(128) __nv_bfloat16 g_k_pack [8u*1024u*384u];
__device__ __align__(128) __nv_bfloat16 g_vT_pack[8u*128u*3072u];
__device__ __align__(128) float g_scr[33554432u];                  // scores f32
__device__ __align__(128) __nv_bfloat16 g_P_pack[32u*1024u*3072u]; // probs [hi|lo|hi]
__device__ __align__(128) __nv_bfloat16 g_ao_pack[2048u*6144u];    // attn-out [hi|lo|hi]
__device__ __align__(128) float g_yy[4096u*1024u];

// ---------------- generic pack: f32 [R x K] -> bf16 [R x 3K] ----------------
template<bool AFORM>  // true: [hi|lo|hi] (A), false: [hi|hi|lo] (B)
__global__ __launch_bounds__(256)
void packK(const float* __restrict__ src, __nv_bfloat16* __restrict__ dst, int K, int total)
{
  int idx = (blockIdx.x*256 + threadIdx.x)*4;
  if (idx >= total) return;
  float4 v = *(const float4*)(src + idx);
  int r = idx / K, k = idx - r*K;
  __nv_bfloat16* d = dst + (long long)r*3*K + k;
  float vv[4] = {v.x, v.y, v.z, v.w};
#pragma unroll
  for (int i=0;i<4;i++){
    __nv_bfloat16 hi, lo; bsplit(vv[i], hi, lo);
    d[i] = hi;
    d[K+i]   = AFORM ? lo : hi;
    d[2*K+i] = AFORM ? hi : lo;
  }
}

// ---------------- mma.sync GEMM ----------------
// C[m][n] = cscale * sum_k A[m][k]*B[n][k] (+bias[n]); operands bf16 K-major.
// batch z: A += z*sA; B += (z/zDivB)*sB; C base += (z/zDivC)*sC1 + (z%zDivC)*sC2.
// Tile 128x128, K-chunk 32, double-buffered cp.async.
// SMEM rows padded to 80B (64B data + 16B): ldmatrix phase banks (5r+c)%8 conflict-free.
#define ROWB 80
#define STAGEB 20480   // A(10240) + B(10240)

template<bool PACK_OUT>
__global__ __launch_bounds__(256, 2)
void gemm_mma(const __nv_bfloat16* __restrict__ A, const __nv_bfloat16* __restrict__ B,
              float* __restrict__ Cf, __nv_bfloat16* __restrict__ Cp,
              const float* __restrict__ bias,
              int Kp, int lda, int ldb, int ldc,
              long long sA, long long sB, int zDivB,
              long long sC1, long long sC2, int zDivC,
              float cscale)
{
  extern __shared__ char smem[];
  const uint32_t sb = smem_u32(smem);
  const int tid = threadIdx.x, wid = tid>>5, lane = tid&31;
  const int z = blockIdx.z;
  const int m0 = blockIdx.y*128, n0 = blockIdx.x*128;
  A += (long long)z*sA + (long long)m0*lda;
  B += (long long)(z/zDivB)*sB + (long long)n0*ldb;
  const long long coff = (long long)(z/zDivC)*sC1 + (long long)(z%zDivC)*sC2;

  const int wm = wid>>1, wn = wid&1;   // warp grid 4(M) x 2(N): 32x64 per warp

  float acc[2][8][4];
#pragma unroll
  for (int i=0;i<2;i++)
#pragma unroll
    for (int j=0;j<8;j++)
#pragma unroll
      for (int q=0;q<4;q++) acc[i][j][q]=0.f;

  const int nch = Kp >> 5;

  auto loadStage = [&](int c, int s){
    const __nv_bfloat16* Ak = A + c*32;
    const __nv_bfloat16* Bk = B + c*32;
    uint32_t abase = sb + s*STAGEB;
    uint32_t bbase = abase + 10240;
#pragma unroll
    for (int i=0;i<2;i++){
      int f = tid + i*256;
      int r = f>>2, q = f&3;
      cp_async16(abase + r*ROWB + q*16, (const char*)(Ak + (long long)r*lda) + q*16);
      cp_async16(bbase + r*ROWB + q*16, (const char*)(Bk + (long long)r*ldb) + q*16);
    }
  };

  loadStage(0, 0); CP_COMMIT();

  for (int c=0; c<nch; c++){
    const int cur = c & 1;
    if (c+1 < nch){ loadStage(c+1, cur^1); CP_COMMIT(); CP_WAIT1(); }
    else          { CP_WAIT0(); }
    __syncthreads();

    const uint32_t abase = sb + cur*STAGEB;
    const uint32_t bbase = abase + 10240;
#pragma unroll
    for (int kk=0; kk<32; kk+=16){
      uint32_t a[2][4], b[4][4];
#pragma unroll
      for (int h=0; h<2; h++){
        uint32_t addr = abase + (wm*32 + h*16 + (lane&15))*ROWB
                               + (kk + ((lane>>4)<<3))*2;
        ldsm_x4(a[h], addr);
      }
#pragma unroll
      for (int p=0; p<4; p++){
        uint32_t addr = bbase + (wn*64 + p*16 + ((lane>>4)&1)*8 + (lane&7))*ROWB
                               + (kk + (((lane>>3)&1)<<3))*2;
        ldsm_x4(b[p], addr);
      }
#pragma unroll
      for (int mi=0; mi<2; mi++)
#pragma unroll
        for (int p=0; p<4; p++){
          mma16816(acc[mi][2*p+0], a[mi], &b[p][0]);
          mma16816(acc[mi][2*p+1], a[mi], &b[p][2]);
        }
    }
    __syncthreads();
  }

  // ---- epilogue: registers -> gmem ----
#pragma unroll
  for (int mi=0; mi<2; mi++){
#pragma unroll
    for (int ni=0; ni<8; ni++){
      int mrow = m0 + wm*32 + mi*16 + (lane>>2);
      int ncol = n0 + wn*64 + ni*8 + (lane&3)*2;
#pragma unroll
      for (int hh=0; hh<2; hh++){
        int m = mrow + hh*8;
        float v0 = acc[mi][ni][2*hh+0]*cscale;
        float v1 = acc[mi][ni][2*hh+1]*cscale;
        if (PACK_OUT){
          __nv_bfloat16 h0,l0,h1,l1;
          bsplit(v0,h0,l0); bsplit(v1,h1,l1);
          __nv_bfloat16* d = Cp + coff + (long long)m*ldc + ncol;
          *(__nv_bfloat162*)(d)        = __nv_bfloat162(h0,h1);
          *(__nv_bfloat162*)(d+2048)   = __nv_bfloat162(l0,l1);
          *(__nv_bfloat162*)(d+4096)   = __nv_bfloat162(h0,h1);
        } else {
          if (bias){ v0 += bias[ncol]; v1 += bias[ncol+1]; }
          *(float2*)(Cf + coff + (long long)m*ldc + ncol) = make_float2(v0,v1);
        }
      }
    }
  }
}

// ---------------- RMSNorm + RoPE + split-pack q/k/vT ----------------
__global__ __launch_bounds__(256)
void norm_rope_pack(const float* __restrict__ cl, const float* __restrict__ cg,
                    const float* __restrict__ cosT, const float* __restrict__ sinT,
                    const float* __restrict__ gql, const float* __restrict__ gkl,
                    const float* __restrict__ gqg, const float* __restrict__ gkg,
                    __nv_bfloat16* __restrict__ qp, __nv_bfloat16* __restrict__ kp,
                    __nv_bfloat16* __restrict__ vp)
{
  const int bs = blockIdx.x;
  const int b = bs >> 10, s = bs & 1023;
  const int t = threadIdx.x;
  const float* rl = cl + (long long)bs*1536;
  const float* rg = cg + (long long)bs*1536;

  float sql=0.f, sqg=0.f;
#pragma unroll
  for (int i=t;i<1024;i+=256){ float x=rl[i]; sql+=x*x; float y=rg[i]; sqg+=y*y; }
  float xk=rl[1024+t], yk=rg[1024+t];
  float skl = xk*xk, skg = yk*yk;

  __shared__ float4 red[8];
  float4 v4 = make_float4(sql,sqg,skl,skg);
#pragma unroll
  for (int o=16;o;o>>=1){
    v4.x += __shfl_xor_sync(0xffffffffu, v4.x, o);
    v4.y += __shfl_xor_sync(0xffffffffu, v4.y, o);
    v4.z += __shfl_xor_sync(0xffffffffu, v4.z, o);
    v4.w += __shfl_xor_sync(0xffffffffu, v4.w, o);
  }
  const int w = t>>5, l = t&31;
  if (!l) red[w]=v4;
  __syncthreads();
  if (t==0){
    float4 a = red[0];
    for (int i=1;i<8;i++){ a.x+=red[i].x; a.y+=red[i].y; a.z+=red[i].z; a.w+=red[i].w; }
    red[0]=a;
  }
  __syncthreads();
  float4 tot = red[0];
  const float rql = rsqrtf(tot.x*(1.f/1024.f)+1e-5f);
  const float rqg = rsqrtf(tot.y*(1.f/1024.f)+1e-5f);
  const float rkl = rsqrtf(tot.z*(1.f/256.f)+1e-5f);
  const float rkg = rsqrtf(tot.w*(1.f/256.f)+1e-5f);

  // q rows: [(b*16+h)*1024+s] x 384 in [hi|lo|hi]
#pragma unroll
  for (int pp=t; pp<512; pp+=256){
    int h = pp>>5, p = pp&31;
    float c = cosT[s*32+p], sn = sinT[s*32+p];
    int d0 = h*64 + 2*p;
    long long base = (((long long)(b*16+h))*1024 + s)*384;
    float x0 = rl[d0]*rql*gql[d0];
    float x1 = rl[d0+1]*rql*gql[d0+1];
    float y0 = rg[d0]*rqg*gqg[d0];
    float y1 = rg[d0+1]*rqg*gqg[d0+1];
    float o[4] = { x0*c - x1*sn, x0*sn + x1*c, y0*c - y1*sn, y0*sn + y1*c };
    int col[4] = { 2*p, 2*p+1, 64+2*p, 64+2*p+1 };
#pragma unroll
    for (int i=0;i<4;i++){
      __nv_bfloat16 hi, lo; bsplit(o[i], hi, lo);
      qp[base + col[i]]       = hi;
      qp[base + 128 + col[i]] = lo;
      qp[base + 256 + col[i]] = hi;
    }
  }
  // k rows: [(b*4+kh)*1024+s] x 384 in [hi|hi|lo]
  if (t < 128){
    int kh = t>>5, p = t&31;
    float c = cosT[s*32+p], sn = sinT[s*32+p];
    int gd = kh*64 + 2*p;
    long long base = (((long long)(b*4+kh))*1024 + s)*384;
    float x0 = rl[1024+gd]*rkl*gkl[gd];
    float x1 = rl[1024+gd+1]*rkl*gkl[gd+1];
    float y0 = rg[1024+gd]*rkg*gkg[gd];
    float y1 = rg[1024+gd+1]*rkg*gkg[gd+1];
    float o[4] = { x0*c - x1*sn, x0*sn + x1*c, y0*c - y1*sn, y0*sn + y1*c };
    int col[4] = { 2*p, 2*p+1, 64+2*p, 64+2*p+1 };
#pragma unroll
    for (int i=0;i<4;i++){
      __nv_bfloat16 hi, lo; bsplit(o[i], hi, lo);
      kp[base + col[i]]       = hi;
      kp[base + 128 + col[i]] = hi;
      kp[base + 256 + col[i]] = lo;
    }
  }
  // vT rows: [(b*4+kh)*128 + d] x 3072 in [hi|hi|lo], column = s
  {
    int kh = t>>6, d = t&63;
    long long rowl = ((long long)(b*4+kh))*128 + d;
    long long rowg = rowl + 64;
    __nv_bfloat16 hi, lo;
    bsplit(rl[1280+t], hi, lo);
    vp[rowl*3072 + s] = hi; vp[rowl*3072 + 1024 + s] = hi; vp[rowl*3072 + 2048 + s] = lo;
    bsplit(rg[1280+t], hi, lo);
    vp[rowg*3072 + s] = hi; vp[rowg*3072 + 1024 + s] = hi; vp[rowg*3072 + 2048 + s] = lo;
  }
}

// ---------------- softmax row(1024) f32 -> bf16 split pack [hi|lo|hi] ----------------
__global__ __launch_bounds__(128)
void softmax_pack(const float* __restrict__ S, __nv_bfloat16* __restrict__ P)
{
  const float* r = S + (long long)blockIdx.x * 1024;
  __nv_bfloat16* o = P + (long long)blockIdx.x * 3072;
  const int t = threadIdx.x;
  float4 a  = ((const float4*)r)[t];
  float4 b2 = ((const float4*)r)[t+128];
  float mx = fmaxf(fmaxf(fmaxf(a.x,a.y),fmaxf(a.z,a.w)),
                   fmaxf(fmaxf(b2.x,b2.y),fmaxf(b2.z,b2.w)));
  __shared__ float sm[4];
#pragma unroll
  for (int off=16;off;off>>=1) mx = fmaxf(mx, __shfl_xor_sync(0xffffffffu,mx,off));
  const int w=t>>5, l=t&31;
  if (!l) sm[w]=mx;
  __syncthreads();
  mx = fmaxf(fmaxf(sm[0],sm[1]),fmaxf(sm[2],sm[3]));
  __syncthreads();
  a.x=__expf(a.x-mx);  a.y=__expf(a.y-mx);  a.z=__expf(a.z-mx);  a.w=__expf(a.w-mx);
  b2.x=__expf(b2.x-mx); b2.y=__expf(b2.y-mx); b2.z=__expf(b2.z-mx); b2.w=__expf(b2.w-mx);
  float s = a.x+a.y+a.z+a.w+b2.x+b2.y+b2.z+b2.w;
#pragma unroll
  for (int off=16;off;off>>=1) s += __shfl_xor_sync(0xffffffffu,s,off);
  if (!l) sm[w]=s;
  __syncthreads();
  const float inv = 1.f/(sm[0]+sm[1]+sm[2]+sm[3]);
  float va[8] = {a.x*inv,a.y*inv,a.z*inv,a.w*inv,b2.x*inv,b2.y*inv,b2.z*inv,b2.w*inv};
  int   ca[8] = {4*t,4*t+1,4*t+2,4*t+3,512+4*t,512+4*t+1,512+4*t+2,512+4*t+3};
#pragma unroll
  for (int i=0;i<8;i++){
    __nv_bfloat16 hi, lo; bsplit(va[i], hi, lo);
    o[ca[i]] = hi; o[1024+ca[i]] = lo; o[2048+ca[i]] = hi;
  }
}

// ---------------- final RMSNorm -> d_out ----------------
__global__ __launch_bounds__(256)
void rmsnorm_out(const float* __restrict__ y, const float* __restrict__ glc,
                 const float* __restrict__ ggc, float* __restrict__ out)
{
  const int row = blockIdx.x;
  const float* g = (row < 2048) ? glc : ggc;
  const float* r = y + (long long)row*1024;
  float* o = out + (long long)row*1024;
  const int t = threadIdx.x;
  float4 v = ((const float4*)r)[t];
  float ss = v.x*v.x + v.y*v.y + v.z*v.z + v.w*v.w;
  __shared__ float sm[8];
#pragma unroll
  for (int o2=16;o2;o2>>=1) ss += __shfl_xor_sync(0xffffffffu,ss,o2);
  const int w=t>>5, l=t&31;
  if (!l) sm[w]=ss;
  __syncthreads();
  ss = sm[0]+sm[1]+sm[2]+sm[3]+sm[4]+sm[5]+sm[6]+sm[7];
  const float rsq = rsqrtf(ss*(1.f/1024.f)+1e-5f);
  float4 gv = ((const float4*)g)[t];
  float4 ov = make_float4(v.x*rsq*gv.x, v.y*rsq*gv.y, v.z*rsq*gv.z, v.w*rsq*gv.w);
  ((float4*)o)[t]=ov;
}

// ---------------- launch ----------------
extern "C" void kernel_launch(void* const* d_in, const int* in_sizes, int n_in,
                              void* d_out, int out_size)
{
  (void)in_sizes; (void)n_in; (void)out_size;
  const float* local_c  = (const float*)d_in[0];
  const float* global_c = (const float*)d_in[1];
  const float* fcos     = (const float*)d_in[2];
  const float* fsin     = (const float*)d_in[3];
  const float* W_lc     = (const float*)d_in[4];
  const float* W_gc     = (const float*)d_in[5];
  const float* g_q_lc   = (const float*)d_in[6];
  const float* g_k_lc   = (const float*)d_in[7];
  const float* g_q_gc   = (const float*)d_in[8];
  const float* g_k_gc   = (const float*)d_in[9];
  const float* W_local  = (const float*)d_in[10];
  const float* b_local  = (const float*)d_in[11];
  const float* g_lc_out = (const float*)d_in[12];
  const float* W_global = (const float*)d_in[13];
  const float* b_global = (const float*)d_in[14];
  const float* g_gc_out = (const float*)d_in[15];

  __nv_bfloat16 *xlp,*xgp,*wlcp,*wgcp,*wlop,*wgop,*qp,*kp,*vtp,*Pp,*aop;
  float *comb_lc,*comb_gc,*sc,*yy;
  cudaGetSymbolAddress((void**)&xlp,  g_xl_pack);
  cudaGetSymbolAddress((void**)&xgp,  g_xg_pack);
  cudaGetSymbolAddress((void**)&wlcp, g_wlc_pack);
  cudaGetSymbolAddress((void**)&wgcp, g_wgc_pack);
  cudaGetSymbolAddress((void**)&wlop, g_wlo_pack);
  cudaGetSymbolAddress((void**)&wgop, g_wgo_pack);
  cudaGetSymbolAddress((void**)&comb_lc, g_comb_lc);
  cudaGetSymbolAddress((void**)&comb_gc, g_comb_gc);
  cudaGetSymbolAddress((void**)&qp,  g_q_pack);
  cudaGetSymbolAddress((void**)&kp,  g_k_pack);
  cudaGetSymbolAddress((void**)&vtp, g_vT_pack);
  cudaGetSymbolAddress((void**)&sc,  g_scr);
  cudaGetSymbolAddress((void**)&Pp,  g_P_pack);
  cudaGetSymbolAddress((void**)&aop, g_ao_pack);
  cudaGetSymbolAddress((void**)&yy,  g_yy);

  const int SMEMSZ = 2*STAGEB;  // 40960

  // 0) operand packs
  packK<true ><<<2048,256>>>(local_c,  xlp,  1024, 2048*1024);
  packK<true ><<<2048,256>>>(global_c, xgp,  1024, 2048*1024);
  packK<false><<<1536,256>>>(W_lc,     wlcp, 1024, 1536*1024);
  packK<false><<<1536,256>>>(W_gc,     wgcp, 1024, 1536*1024);
  packK<false><<<2048,256>>>(W_local,  wlop, 2048, 1024*2048);
  packK<false><<<2048,256>>>(W_global, wgop, 2048, 1024*2048);

  // 1,2) QKV projections: comb = x @ W^T  (M=2048,N=1536,K'=3072)
  gemm_mma<false><<<dim3(12,16,1),256,SMEMSZ>>>(xlp, wlcp, comb_lc, nullptr, nullptr,
     3072, 3072,3072,1536, 0,0,1, 0,0,1, 1.f);
  gemm_mma<false><<<dim3(12,16,1),256,SMEMSZ>>>(xgp, wgcp, comb_gc, nullptr, nullptr,
     3072, 3072,3072,1536, 0,0,1, 0,0,1, 1.f);

  // 3) rmsnorm + rope + split-pack
  norm_rope_pack<<<2048,256>>>(comb_lc, comb_gc, fcos, fsin,
                               g_q_lc, g_k_lc, g_q_gc, g_k_gc, qp, kp, vtp);

  // 4) scores = (Q @ K^T)/8  (per z=b*16+h: M=1024,N=1024,K'=384)
  gemm_mma<false><<<dim3(8,8,32),256,SMEMSZ>>>(qp, kp, sc, nullptr, nullptr,
     384, 384,384,1024, 393216LL, 393216LL, 4, 1048576LL, 0LL, 1, 0.125f);

  // 5) softmax -> packed P
  softmax_pack<<<32768,128>>>(sc, Pp);

  // 6) attn_out = P @ V  (per z: M=1024,N=128,K'=3072) -> packed ao [hi|lo|hi]
  gemm_mma<true ><<<dim3(1,8,32),256,SMEMSZ>>>(Pp, vtp, nullptr, aop, nullptr,
     3072, 3072,3072,6144, 3145728LL, 393216LL, 4, 6291456LL, 128LL, 16, 1.f);

  // 7,8) output projections + bias  (M=2048,N=1024,K'=6144)
  gemm_mma<false><<<dim3(8,16,1),256,SMEMSZ>>>(aop, wlop, yy, nullptr, b_local,
     6144, 6144,6144,1024, 0,0,1, 0,0,1, 1.f);
  gemm_mma<false><<<dim3(8,16,1),256,SMEMSZ>>>(aop, wgop, yy + (long long)2048*1024, nullptr, b_global,
     6144, 6144,6144,1024, 0,0,1, 0,0,1, 1.f);

  // 9) final rmsnorm -> d_out
  rmsnorm_out<<<4096,256>>>(yy, g_lc_out, g_gc_out, (float*)d_out);
}

// round 6
// speedup vs baseline: 1.7342x; 1.1343x over previous
#include <cuda_runtime.h>
#include <cuda_bf16.h>
#include <cstdint>

// B=2, S=1024, D=1024, H=16, KVH=4, HD=64, TOT=1536
// GEMMs on mma.sync bf16 tensor cores; fp32-level accuracy via 2-term split:
//   A packed [hi|lo|hi], B packed [hi|hi|lo]  => hi*hi + lo*hi + hi*lo, K' = 3K.
// Attention (QK^T -> softmax -> PV) fused into one flash kernel (no scores/P scratch).

typedef unsigned long long ull;
#define DEVFN static __device__ __forceinline__

// ---------------- PTX helpers ----------------
DEVFN uint32_t smem_u32(const void* p){
  uint32_t a; asm("{ .reg .u64 t; cvta.to.shared.u64 t, %1; cvt.u32.u64 %0, t; }":"=r"(a):"l"(p)); return a;
}
DEVFN void ldsm_x4(uint32_t* r, uint32_t addr){
  asm volatile("ldmatrix.sync.aligned.m8n8.x4.shared.b16 {%0,%1,%2,%3}, [%4];"
    : "=r"(r[0]),"=r"(r[1]),"=r"(r[2]),"=r"(r[3]) : "r"(addr));
}
DEVFN void mma16816(float* c, const uint32_t* a, const uint32_t* b){
  asm volatile("mma.sync.aligned.m16n8k16.row.col.f32.bf16.bf16.f32 "
    "{%0,%1,%2,%3}, {%4,%5,%6,%7}, {%8,%9}, {%0,%1,%2,%3};"
    : "+f"(c[0]),"+f"(c[1]),"+f"(c[2]),"+f"(c[3])
    : "r"(a[0]),"r"(a[1]),"r"(a[2]),"r"(a[3]), "r"(b[0]),"r"(b[1]));
}
DEVFN void cp_async16(uint32_t dst, const void* src){
  asm volatile("cp.async.cg.shared.global [%0], [%1], 16;" :: "r"(dst), "l"(src));
}
#define CP_COMMIT() asm volatile("cp.async.commit_group;" ::: "memory")
#define CP_WAIT0()  asm volatile("cp.async.wait_group 0;" ::: "memory")
#define CP_WAIT1()  asm volatile("cp.async.wait_group 1;" ::: "memory")

DEVFN void bsplit(float x, __nv_bfloat16 &hi, __nv_bfloat16 &lo){
  hi = __float2bfloat16(x);
  lo = __float2bfloat16(x - __bfloat162float(hi));
}
DEVFN uint32_t packb2(__nv_bfloat16 a, __nv_bfloat16 b){
  __nv_bfloat162 t(a, b); return *(uint32_t*)&t;
}

// ---------------- scratch (device globals) ----------------
__device__ __align__(128) __nv_bfloat16 g_xl_pack [2048u*3072u];
__device__ __align__(128) __nv_bfloat16 g_xg_pack [2048u*3072u];
__device__ __align__(128) __nv_bfloat16 g_wlc_pack[1536u*3072u];
__device__ __align__(128) __nv_bfloat16 g_wgc_pack[1536u*3072u];
__device__ __align__(128) __nv_bfloat16 g_wlo_pack[1024u*6144u];
__device__ __align__(128) __nv_bfloat16 g_wgo_pack[1024u*6144u];
__device__ __align__(128) float g_comb_lc[2048u*1536u];
__device__ __align__(128) float g_comb_gc[2048u*1536u];
__device__ __align__(128) __nv_bfloat16 g_q_pack [32u*1024u*384u];  // q/8, [hi|lo|hi]
__device__ __align__(128) __nv_bfloat16 g_k_pack [8u*1024u*384u];   // [hi|hi|lo]
__device__ __align__(128) __nv_bfloat16 g_vT_pack[8u*128u*3072u];   // V^T [hi|hi|lo]
__device__ __align__(128) __nv_bfloat16 g_ao_pack[2048u*6144u];     // attn-out [hi|lo|hi]
__device__ __align__(128) float g_yy[4096u*1024u];

// ---------------- generic pack: f32 [R x K] -> bf16 [R x 3K] ----------------
template<bool AFORM>  // true: [hi|lo|hi] (A), false: [hi|hi|lo] (B)
__global__ __launch_bounds__(256)
void packK(const float* __restrict__ src, __nv_bfloat16* __restrict__ dst, int K, int total)
{
  int idx = (blockIdx.x*256 + threadIdx.x)*4;
  if (idx >= total) return;
  float4 v = *(const float4*)(src + idx);
  int r = idx / K, k = idx - r*K;
  __nv_bfloat16* d = dst + (long long)r*3*K + k;
  float vv[4] = {v.x, v.y, v.z, v.w};
#pragma unroll
  for (int i=0;i<4;i++){
    __nv_bfloat16 hi, lo; bsplit(vv[i], hi, lo);
    d[i] = hi;
    d[K+i]   = AFORM ? lo : hi;
    d[2*K+i] = AFORM ? hi : lo;
  }
}

// ---------------- mma.sync GEMM (projections) ----------------
#define ROWB 80
#define STAGEB 20480   // A(10240) + B(10240)

template<bool PACK_OUT>
__global__ __launch_bounds__(256, 2)
void gemm_mma(const __nv_bfloat16* __restrict__ A, const __nv_bfloat16* __restrict__ B,
              float* __restrict__ Cf, __nv_bfloat16* __restrict__ Cp,
              const float* __restrict__ bias,
              int Kp, int lda, int ldb, int ldc,
              long long sA, long long sB, int zDivB,
              long long sC1, long long sC2, int zDivC,
              float cscale)
{
  extern __shared__ char smem[];
  const uint32_t sb = smem_u32(smem);
  const int tid = threadIdx.x, wid = tid>>5, lane = tid&31;
  const int z = blockIdx.z;
  const int m0 = blockIdx.y*128, n0 = blockIdx.x*128;
  A += (long long)z*sA + (long long)m0*lda;
  B += (long long)(z/zDivB)*sB + (long long)n0*ldb;
  const long long coff = (long long)(z/zDivC)*sC1 + (long long)(z%zDivC)*sC2;

  const int wm = wid>>1, wn = wid&1;

  float acc[2][8][4];
#pragma unroll
  for (int i=0;i<2;i++)
#pragma unroll
    for (int j=0;j<8;j++)
#pragma unroll
      for (int q=0;q<4;q++) acc[i][j][q]=0.f;

  const int nch = Kp >> 5;

  auto loadStage = [&](int c, int s){
    const __nv_bfloat16* Ak = A + c*32;
    const __nv_bfloat16* Bk = B + c*32;
    uint32_t abase = sb + s*STAGEB;
    uint32_t bbase = abase + 10240;
#pragma unroll
    for (int i=0;i<2;i++){
      int f = tid + i*256;
      int r = f>>2, q = f&3;
      cp_async16(abase + r*ROWB + q*16, (const char*)(Ak + (long long)r*lda) + q*16);
      cp_async16(bbase + r*ROWB + q*16, (const char*)(Bk + (long long)r*ldb) + q*16);
    }
  };

  loadStage(0, 0); CP_COMMIT();

  for (int c=0; c<nch; c++){
    const int cur = c & 1;
    if (c+1 < nch){ loadStage(c+1, cur^1); CP_COMMIT(); CP_WAIT1(); }
    else          { CP_WAIT0(); }
    __syncthreads();

    const uint32_t abase = sb + cur*STAGEB;
    const uint32_t bbase = abase + 10240;
#pragma unroll
    for (int kk=0; kk<32; kk+=16){
      uint32_t a[2][4], b[4][4];
#pragma unroll
      for (int h=0; h<2; h++){
        uint32_t addr = abase + (wm*32 + h*16 + (lane&15))*ROWB
                               + (kk + ((lane>>4)<<3))*2;
        ldsm_x4(a[h], addr);
      }
#pragma unroll
      for (int p=0; p<4; p++){
        uint32_t addr = bbase + (wn*64 + p*16 + ((lane>>4)&1)*8 + (lane&7))*ROWB
                               + (kk + (((lane>>3)&1)<<3))*2;
        ldsm_x4(b[p], addr);
      }
#pragma unroll
      for (int mi=0; mi<2; mi++)
#pragma unroll
        for (int p=0; p<4; p++){
          mma16816(acc[mi][2*p+0], a[mi], &b[p][0]);
          mma16816(acc[mi][2*p+1], a[mi], &b[p][2]);
        }
    }
    __syncthreads();
  }

#pragma unroll
  for (int mi=0; mi<2; mi++){
#pragma unroll
    for (int ni=0; ni<8; ni++){
      int mrow = m0 + wm*32 + mi*16 + (lane>>2);
      int ncol = n0 + wn*64 + ni*8 + (lane&3)*2;
#pragma unroll
      for (int hh=0; hh<2; hh++){
        int m = mrow + hh*8;
        float v0 = acc[mi][ni][2*hh+0]*cscale;
        float v1 = acc[mi][ni][2*hh+1]*cscale;
        if (PACK_OUT){
          __nv_bfloat16 h0,l0,h1,l1;
          bsplit(v0,h0,l0); bsplit(v1,h1,l1);
          __nv_bfloat16* d = Cp + coff + (long long)m*ldc + ncol;
          *(__nv_bfloat162*)(d)        = __nv_bfloat162(h0,h1);
          *(__nv_bfloat162*)(d+2048)   = __nv_bfloat162(l0,l1);
          *(__nv_bfloat162*)(d+4096)   = __nv_bfloat162(h0,h1);
        } else {
          if (bias){ v0 += bias[ncol]; v1 += bias[ncol+1]; }
          *(float2*)(Cf + coff + (long long)m*ldc + ncol) = make_float2(v0,v1);
        }
      }
    }
  }
}

// ---------------- fused flash attention ----------------
// grid (8, 32): x = q-row block (128 rows), y = z = b*16+h.
// Warp w owns S/O rows [w*16, w*16+16). S via 3-term bf16 mma over K'=384.
// Online softmax in registers; P split hi/lo in registers feeds 3-term PV mma
// against V^T hi/lo smem tiles. Output written as [hi|lo|hi] pack to aop.
#define QROWB 784   // 768B data + 16 pad (49*16 -> odd -> ldsm conflict-free)
#define KROWB 80
#define VROWB 272   // 256B data + 16 pad (17*16)
#define OFF_K  100352
#define OFF_VH 120832
#define OFF_VL 155648
#define FSMEM  190464

__global__ __launch_bounds__(256, 1)
void flash_attn(const __nv_bfloat16* __restrict__ qp,
                const __nv_bfloat16* __restrict__ kp,
                const __nv_bfloat16* __restrict__ vtp,
                __nv_bfloat16* __restrict__ aop)
{
  extern __shared__ char smem[];
  const uint32_t sb = smem_u32(smem);
  const int tid = threadIdx.x, wid = tid>>5, lane = tid&31;
  const int z = blockIdx.y, b = z>>4, h = z&15;
  const int s0 = blockIdx.x*128;
  const __nv_bfloat16* Qb = qp + ((long long)z*1024 + s0)*384;
  const __nv_bfloat16* Kb = kp + (long long)(z>>2)*1024*384;
  const __nv_bfloat16* Vb = vtp + (long long)(z>>2)*128*3072;

  // Q tile (128 x 384 bf16) -> smem, own cp.async group
#pragma unroll
  for (int i=0;i<24;i++){
    int f = tid + i*256;
    int r = f/48, c = f - r*48;
    cp_async16(sb + r*QROWB + c*16, (const char*)(Qb + (long long)r*384) + c*16);
  }
  CP_COMMIT();

  float m0=-1e30f, m1=-1e30f, l0=0.f, l1=0.f;
  float o[16][4];
#pragma unroll
  for (int ni=0;ni<16;ni++){ o[ni][0]=0.f;o[ni][1]=0.f;o[ni][2]=0.f;o[ni][3]=0.f; }

  for (int nc=0; nc<8; nc++){
    const __nv_bfloat16* Kc = Kb + (long long)(nc*128)*384;
    // V^T hi/lo tiles (128 hd x 128 seq each) + K chunk 0 -> one group
#pragma unroll
    for (int i=0;i<8;i++){
      int f = tid + i*256;
      int d = f>>4, c = f&15;
      const char* base = (const char*)(Vb + (long long)d*3072 + nc*128);
      cp_async16(sb + OFF_VH + d*VROWB + c*16, base + c*16);
      cp_async16(sb + OFF_VL + d*VROWB + c*16, base + 2048*2 + c*16);
    }
#pragma unroll
    for (int i=0;i<2;i++){
      int f = tid + i*256;
      int r = f>>2, q4 = f&3;
      cp_async16(sb + OFF_K + r*KROWB + q4*16, (const char*)(Kc + (long long)r*384) + q4*16);
    }
    CP_COMMIT();

    float acc[16][4];
#pragma unroll
    for (int ni=0;ni<16;ni++){ acc[ni][0]=0.f;acc[ni][1]=0.f;acc[ni][2]=0.f;acc[ni][3]=0.f; }

    for (int kc=0; kc<12; kc++){
      if (kc+1 < 12){
        uint32_t kb2 = sb + OFF_K + ((kc+1)&1)*10240;
#pragma unroll
        for (int i=0;i<2;i++){
          int f = tid + i*256;
          int r = f>>2, q4 = f&3;
          cp_async16(kb2 + r*KROWB + q4*16,
                     (const char*)(Kc + (long long)r*384 + (kc+1)*32) + q4*16);
        }
        CP_COMMIT(); CP_WAIT1();
      } else { CP_WAIT0(); }
      __syncthreads();

      const uint32_t kb = sb + OFF_K + (kc&1)*10240;
#pragma unroll
      for (int kk=0; kk<32; kk+=16){
        uint32_t a[4];
        ldsm_x4(a, sb + (wid*16 + (lane&15))*QROWB + (kc*32 + kk + ((lane>>4)<<3))*2);
        uint32_t bf[8][4];
#pragma unroll
        for (int p=0;p<8;p++)
          ldsm_x4(bf[p], kb + (p*16 + ((lane>>4)&1)*8 + (lane&7))*KROWB
                            + (kk + (((lane>>3)&1)<<3))*2);
#pragma unroll
        for (int p=0;p<8;p++){
          mma16816(acc[2*p+0], a, &bf[p][0]);
          mma16816(acc[2*p+1], a, &bf[p][2]);
        }
      }
      __syncthreads();
    }

    // ---- online softmax (all in registers; quad shuffles) ----
    float cm0=-1e30f, cm1=-1e30f;
#pragma unroll
    for (int ni=0;ni<16;ni++){
      cm0 = fmaxf(cm0, fmaxf(acc[ni][0], acc[ni][1]));
      cm1 = fmaxf(cm1, fmaxf(acc[ni][2], acc[ni][3]));
    }
    cm0 = fmaxf(cm0, __shfl_xor_sync(0xffffffffu, cm0, 1));
    cm0 = fmaxf(cm0, __shfl_xor_sync(0xffffffffu, cm0, 2));
    cm1 = fmaxf(cm1, __shfl_xor_sync(0xffffffffu, cm1, 1));
    cm1 = fmaxf(cm1, __shfl_xor_sync(0xffffffffu, cm1, 2));
    float mn0 = fmaxf(m0, cm0), mn1 = fmaxf(m1, cm1);
    float sc0 = __expf(m0 - mn0), sc1 = __expf(m1 - mn1);
    m0 = mn0; m1 = mn1;
    float rs0=0.f, rs1=0.f;
#pragma unroll
    for (int ni=0;ni<16;ni++){
      acc[ni][0]=__expf(acc[ni][0]-m0); acc[ni][1]=__expf(acc[ni][1]-m0);
      acc[ni][2]=__expf(acc[ni][2]-m1); acc[ni][3]=__expf(acc[ni][3]-m1);
      rs0 += acc[ni][0]+acc[ni][1];
      rs1 += acc[ni][2]+acc[ni][3];
    }
    rs0 += __shfl_xor_sync(0xffffffffu, rs0, 1);
    rs0 += __shfl_xor_sync(0xffffffffu, rs0, 2);
    rs1 += __shfl_xor_sync(0xffffffffu, rs1, 1);
    rs1 += __shfl_xor_sync(0xffffffffu, rs1, 2);
    l0 = l0*sc0 + rs0;
    l1 = l1*sc1 + rs1;
#pragma unroll
    for (int ni=0;ni<16;ni++){
      o[ni][0]*=sc0; o[ni][1]*=sc0; o[ni][2]*=sc1; o[ni][3]*=sc1;
    }

    // ---- PV: 3-term (Phi*Vhi + Plo*Vhi + Phi*Vlo) ----
#pragma unroll
    for (int kg=0; kg<8; kg++){
      uint32_t ahi[4], alo[4];
      {
        __nv_bfloat16 x0,y0,x1,y1;
        bsplit(acc[2*kg][0],x0,y0);   bsplit(acc[2*kg][1],x1,y1);
        ahi[0]=packb2(x0,x1); alo[0]=packb2(y0,y1);
        bsplit(acc[2*kg][2],x0,y0);   bsplit(acc[2*kg][3],x1,y1);
        ahi[1]=packb2(x0,x1); alo[1]=packb2(y0,y1);
        bsplit(acc[2*kg+1][0],x0,y0); bsplit(acc[2*kg+1][1],x1,y1);
        ahi[2]=packb2(x0,x1); alo[2]=packb2(y0,y1);
        bsplit(acc[2*kg+1][2],x0,y0); bsplit(acc[2*kg+1][3],x1,y1);
        ahi[3]=packb2(x0,x1); alo[3]=packb2(y0,y1);
      }
#pragma unroll
      for (int p=0;p<8;p++){
        uint32_t rowoff = (p*16 + ((lane>>4)&1)*8 + (lane&7))*VROWB
                        + (kg*16 + (((lane>>3)&1)<<3))*2;
        uint32_t bh[4], bl[4];
        ldsm_x4(bh, sb + OFF_VH + rowoff);
        ldsm_x4(bl, sb + OFF_VL + rowoff);
        mma16816(o[2*p+0], ahi, &bh[0]);
        mma16816(o[2*p+0], alo, &bh[0]);
        mma16816(o[2*p+0], ahi, &bl[0]);
        mma16816(o[2*p+1], ahi, &bh[2]);
        mma16816(o[2*p+1], alo, &bh[2]);
        mma16816(o[2*p+1], ahi, &bl[2]);
      }
    }
    __syncthreads();   // protect K/V smem before next chunk's loads
  }

  // ---- epilogue: normalize + [hi|lo|hi] pack ----
  const float inv0 = 1.f/l0, inv1 = 1.f/l1;
  const int qrow0 = s0 + wid*16 + (lane>>2);
  const long long rb0 = ((long long)(b*1024 + qrow0))*6144 + h*128;
  const long long rb1 = rb0 + 8LL*6144;
#pragma unroll
  for (int ni=0;ni<16;ni++){
    int col = ni*8 + (lane&3)*2;
    {
      float v0 = o[ni][0]*inv0, v1 = o[ni][1]*inv0;
      __nv_bfloat16 h0,l0b,h1,l1b; bsplit(v0,h0,l0b); bsplit(v1,h1,l1b);
      __nv_bfloat16* d = aop + rb0 + col;
      *(__nv_bfloat162*)(d)      = __nv_bfloat162(h0,h1);
      *(__nv_bfloat162*)(d+2048) = __nv_bfloat162(l0b,l1b);
      *(__nv_bfloat162*)(d+4096) = __nv_bfloat162(h0,h1);
    }
    {
      float v0 = o[ni][2]*inv1, v1 = o[ni][3]*inv1;
      __nv_bfloat16 h0,l0b,h1,l1b; bsplit(v0,h0,l0b); bsplit(v1,h1,l1b);
      __nv_bfloat16* d = aop + rb1 + col;
      *(__nv_bfloat162*)(d)      = __nv_bfloat162(h0,h1);
      *(__nv_bfloat162*)(d+2048) = __nv_bfloat162(l0b,l1b);
      *(__nv_bfloat162*)(d+4096) = __nv_bfloat162(h0,h1);
    }
  }
}

// ---------------- RMSNorm + RoPE + split-pack q/k/vT ----------------
__global__ __launch_bounds__(256)
void norm_rope_pack(const float* __restrict__ cl, const float* __restrict__ cg,
                    const float* __restrict__ cosT, const float* __restrict__ sinT,
                    const float* __restrict__ gql, const float* __restrict__ gkl,
                    const float* __restrict__ gqg, const float* __restrict__ gkg,
                    __nv_bfloat16* __restrict__ qp, __nv_bfloat16* __restrict__ kp,
                    __nv_bfloat16* __restrict__ vp)
{
  const int bs = blockIdx.x;
  const int b = bs >> 10, s = bs & 1023;
  const int t = threadIdx.x;
  const float* rl = cl + (long long)bs*1536;
  const float* rg = cg + (long long)bs*1536;

  float sql=0.f, sqg=0.f;
#pragma unroll
  for (int i=t;i<1024;i+=256){ float x=rl[i]; sql+=x*x; float y=rg[i]; sqg+=y*y; }
  float xk=rl[1024+t], yk=rg[1024+t];
  float skl = xk*xk, skg = yk*yk;

  __shared__ float4 red[8];
  float4 v4 = make_float4(sql,sqg,skl,skg);
#pragma unroll
  for (int o=16;o;o>>=1){
    v4.x += __shfl_xor_sync(0xffffffffu, v4.x, o);
    v4.y += __shfl_xor_sync(0xffffffffu, v4.y, o);
    v4.z += __shfl_xor_sync(0xffffffffu, v4.z, o);
    v4.w += __shfl_xor_sync(0xffffffffu, v4.w, o);
  }
  const int w = t>>5, l = t&31;
  if (!l) red[w]=v4;
  __syncthreads();
  if (t==0){
    float4 a = red[0];
    for (int i=1;i<8;i++){ a.x+=red[i].x; a.y+=red[i].y; a.z+=red[i].z; a.w+=red[i].w; }
    red[0]=a;
  }
  __syncthreads();
  float4 tot = red[0];
  const float rql = rsqrtf(tot.x*(1.f/1024.f)+1e-5f) * 0.125f;  // fold scores /8 into q
  const float rqg = rsqrtf(tot.y*(1.f/1024.f)+1e-5f) * 0.125f;
  const float rkl = rsqrtf(tot.z*(1.f/256.f)+1e-5f);
  const float rkg = rsqrtf(tot.w*(1.f/256.f)+1e-5f);

  // q rows: [(b*16+h)*1024+s] x 384 in [hi|lo|hi]
#pragma unroll
  for (int pp=t; pp<512; pp+=256){
    int h = pp>>5, p = pp&31;
    float c = cosT[s*32+p], sn = sinT[s*32+p];
    int d0 = h*64 + 2*p;
    long long base = (((long long)(b*16+h))*1024 + s)*384;
    float x0 = rl[d0]*rql*gql[d0];
    float x1 = rl[d0+1]*rql*gql[d0+1];
    float y0 = rg[d0]*rqg*gqg[d0];
    float y1 = rg[d0+1]*rqg*gqg[d0+1];
    float o[4] = { x0*c - x1*sn, x0*sn + x1*c, y0*c - y1*sn, y0*sn + y1*c };
    int col[4] = { 2*p, 2*p+1, 64+2*p, 64+2*p+1 };
#pragma unroll
    for (int i=0;i<4;i++){
      __nv_bfloat16 hi, lo; bsplit(o[i], hi, lo);
      qp[base + col[i]]       = hi;
      qp[base + 128 + col[i]] = lo;
      qp[base + 256 + col[i]] = hi;
    }
  }
  // k rows: [(b*4+kh)*1024+s] x 384 in [hi|hi|lo]
  if (t < 128){
    int kh = t>>5, p = t&31;
    float c = cosT[s*32+p], sn = sinT[s*32+p];
    int gd = kh*64 + 2*p;
    long long base = (((long long)(b*4+kh))*1024 + s)*384;
    float x0 = rl[1024+gd]*rkl*gkl[gd];
    float x1 = rl[1024+gd+1]*rkl*gkl[gd+1];
    float y0 = rg[1024+gd]*rkg*gkg[gd];
    float y1 = rg[1024+gd+1]*rkg*gkg[gd+1];
    float o[4] = { x0*c - x1*sn, x0*sn + x1*c, y0*c - y1*sn, y0*sn + y1*c };
    int col[4] = { 2*p, 2*p+1, 64+2*p, 64+2*p+1 };
#pragma unroll
    for (int i=0;i<4;i++){
      __nv_bfloat16 hi, lo; bsplit(o[i], hi, lo);
      kp[base + col[i]]       = hi;
      kp[base + 128 + col[i]] = hi;
      kp[base + 256 + col[i]] = lo;
    }
  }
  // vT rows: [(b*4+kh)*128 + d] x 3072 in [hi|hi|lo], column = s
  {
    int kh = t>>6, d = t&63;
    long long rowl = ((long long)(b*4+kh))*128 + d;
    long long rowg = rowl + 64;
    __nv_bfloat16 hi, lo;
    bsplit(rl[1280+t], hi, lo);
    vp[rowl*3072 + s] = hi; vp[rowl*3072 + 1024 + s] = hi; vp[rowl*3072 + 2048 + s] = lo;
    bsplit(rg[1280+t], hi, lo);
    vp[rowg*3072 + s] = hi; vp[rowg*3072 + 1024 + s] = hi; vp[rowg*3072 + 2048 + s] = lo;
  }
}

// ---------------- final RMSNorm -> d_out ----------------
__global__ __launch_bounds__(256)
void rmsnorm_out(const float* __restrict__ y, const float* __restrict__ glc,
                 const float* __restrict__ ggc, float* __restrict__ out)
{
  const int row = blockIdx.x;
  const float* g = (row < 2048) ? glc : ggc;
  const float* r = y + (long long)row*1024;
  float* o = out + (long long)row*1024;
  const int t = threadIdx.x;
  float4 v = ((const float4*)r)[t];
  float ss = v.x*v.x + v.y*v.y + v.z*v.z + v.w*v.w;
  __shared__ float sm[8];
#pragma unroll
  for (int o2=16;o2;o2>>=1) ss += __shfl_xor_sync(0xffffffffu,ss,o2);
  const int w=t>>5, l=t&31;
  if (!l) sm[w]=ss;
  __syncthreads();
  ss = sm[0]+sm[1]+sm[2]+sm[3]+sm[4]+sm[5]+sm[6]+sm[7];
  const float rsq = rsqrtf(ss*(1.f/1024.f)+1e-5f);
  float4 gv = ((const float4*)g)[t];
  float4 ov = make_float4(v.x*rsq*gv.x, v.y*rsq*gv.y, v.z*rsq*gv.z, v.w*rsq*gv.w);
  ((float4*)o)[t]=ov;
}

// ---------------- launch ----------------
extern "C" void kernel_launch(void* const* d_in, const int* in_sizes, int n_in,
                              void* d_out, int out_size)
{
  (void)in_sizes; (void)n_in; (void)out_size;
  const float* local_c  = (const float*)d_in[0];
  const float* global_c = (const float*)d_in[1];
  const float* fcos     = (const float*)d_in[2];
  const float* fsin     = (const float*)d_in[3];
  const float* W_lc     = (const float*)d_in[4];
  const float* W_gc     = (const float*)d_in[5];
  const float* g_q_lc   = (const float*)d_in[6];
  const float* g_k_lc   = (const float*)d_in[7];
  const float* g_q_gc   = (const float*)d_in[8];
  const float* g_k_gc   = (const float*)d_in[9];
  const float* W_local  = (const float*)d_in[10];
  const float* b_local  = (const float*)d_in[11];
  const float* g_lc_out = (const float*)d_in[12];
  const float* W_global = (const float*)d_in[13];
  const float* b_global = (const float*)d_in[14];
  const float* g_gc_out = (const float*)d_in[15];

  __nv_bfloat16 *xlp,*xgp,*wlcp,*wgcp,*wlop,*wgop,*qp,*kp,*vtp,*aop;
  float *comb_lc,*comb_gc,*yy;
  cudaGetSymbolAddress((void**)&xlp,  g_xl_pack);
  cudaGetSymbolAddress((void**)&xgp,  g_xg_pack);
  cudaGetSymbolAddress((void**)&wlcp, g_wlc_pack);
  cudaGetSymbolAddress((void**)&wgcp, g_wgc_pack);
  cudaGetSymbolAddress((void**)&wlop, g_wlo_pack);
  cudaGetSymbolAddress((void**)&wgop, g_wgo_pack);
  cudaGetSymbolAddress((void**)&comb_lc, g_comb_lc);
  cudaGetSymbolAddress((void**)&comb_gc, g_comb_gc);
  cudaGetSymbolAddress((void**)&qp,  g_q_pack);
  cudaGetSymbolAddress((void**)&kp,  g_k_pack);
  cudaGetSymbolAddress((void**)&vtp, g_vT_pack);
  cudaGetSymbolAddress((void**)&aop, g_ao_pack);
  cudaGetSymbolAddress((void**)&yy,  g_yy);

  const int SMEMSZ = 2*STAGEB;  // 40960
  static int attr_done = 0;
  if (!attr_done){
    cudaFuncSetAttribute(flash_attn, cudaFuncAttributeMaxDynamicSharedMemorySize, FSMEM);
    attr_done = 1;
  }

  // 0) operand packs
  packK<true ><<<2048,256>>>(local_c,  xlp,  1024, 2048*1024);
  packK<true ><<<2048,256>>>(global_c, xgp,  1024, 2048*1024);
  packK<false><<<1536,256>>>(W_lc,     wlcp, 1024, 1536*1024);
  packK<false><<<1536,256>>>(W_gc,     wgcp, 1024, 1536*1024);
  packK<false><<<2048,256>>>(W_local,  wlop, 2048, 1024*2048);
  packK<false><<<2048,256>>>(W_global, wgop, 2048, 1024*2048);

  // 1,2) QKV projections: comb = x @ W^T  (M=2048,N=1536,K'=3072)
  gemm_mma<false><<<dim3(12,16,1),256,SMEMSZ>>>(xlp, wlcp, comb_lc, nullptr, nullptr,
     3072, 3072,3072,1536, 0,0,1, 0,0,1, 1.f);
  gemm_mma<false><<<dim3(12,16,1),256,SMEMSZ>>>(xgp, wgcp, comb_gc, nullptr, nullptr,
     3072, 3072,3072,1536, 0,0,1, 0,0,1, 1.f);

  // 3) rmsnorm + rope + split-pack (q scaled by 1/8)
  norm_rope_pack<<<2048,256>>>(comb_lc, comb_gc, fcos, fsin,
                               g_q_lc, g_k_lc, g_q_gc, g_k_gc, qp, kp, vtp);

  // 4-6) fused attention -> aop [hi|lo|hi]
  flash_attn<<<dim3(8,32),256,FSMEM>>>(qp, kp, vtp, aop);

  // 7,8) output projections + bias  (M=2048,N=1024,K'=6144)
  gemm_mma<false><<<dim3(8,16,1),256,SMEMSZ>>>(aop, wlop, yy, nullptr, b_local,
     6144, 6144,6144,1024, 0,0,1, 0,0,1, 1.f);
  gemm_mma<false><<<dim3(8,16,1),256,SMEMSZ>>>(aop, wgop, yy + (long long)2048*1024, nullptr, b_global,
     6144, 6144,6144,1024, 0,0,1, 0,0,1, 1.f);

  // 9) final rmsnorm -> d_out
  rmsnorm_out<<<4096,256>>>(yy, g_lc_out, g_gc_out, (float*)d_out);
}

// round 7
// speedup vs baseline: 2.3760x; 1.3701x over previous
#include <cuda_runtime.h>
#include <cuda_bf16.h>
#include <cstdint>

// B=2, S=1024, D=1024, H=16, KVH=4, HD=64, TOT=1536
// GEMMs on mma.sync bf16 tensor cores; fp32-level accuracy via 2-term split:
//   A packed [hi|lo|hi], B packed [hi|hi|lo]  => hi*hi + lo*hi + hi*lo, K' = 3K.
// Flash-fused attention; K-chunk-64 single-barrier pipelines everywhere.

typedef unsigned long long ull;
typedef long long ll;
#define DEVFN static __device__ __forceinline__

// ---------------- PTX helpers ----------------
DEVFN uint32_t smem_u32(const void* p){
  uint32_t a; asm("{ .reg .u64 t; cvta.to.shared.u64 t, %1; cvt.u32.u64 %0, t; }":"=r"(a):"l"(p)); return a;
}
DEVFN void ldsm_x4(uint32_t* r, uint32_t addr){
  asm volatile("ldmatrix.sync.aligned.m8n8.x4.shared.b16 {%0,%1,%2,%3}, [%4];"
    : "=r"(r[0]),"=r"(r[1]),"=r"(r[2]),"=r"(r[3]) : "r"(addr));
}
DEVFN void mma16816(float* c, const uint32_t* a, const uint32_t* b){
  asm volatile("mma.sync.aligned.m16n8k16.row.col.f32.bf16.bf16.f32 "
    "{%0,%1,%2,%3}, {%4,%5,%6,%7}, {%8,%9}, {%0,%1,%2,%3};"
    : "+f"(c[0]),"+f"(c[1]),"+f"(c[2]),"+f"(c[3])
    : "r"(a[0]),"r"(a[1]),"r"(a[2]),"r"(a[3]), "r"(b[0]),"r"(b[1]));
}
DEVFN void cp_async16(uint32_t dst, const void* src){
  asm volatile("cp.async.cg.shared.global [%0], [%1], 16;" :: "r"(dst), "l"(src));
}
#define CP_COMMIT() asm volatile("cp.async.commit_group;" ::: "memory")
#define CP_WAIT0()  asm volatile("cp.async.wait_group 0;" ::: "memory")

DEVFN void bsplit(float x, __nv_bfloat16 &hi, __nv_bfloat16 &lo){
  hi = __float2bfloat16(x);
  lo = __float2bfloat16(x - __bfloat162float(hi));
}
DEVFN uint32_t packb2(__nv_bfloat16 a, __nv_bfloat16 b){
  __nv_bfloat162 t(a, b); return *(uint32_t*)&t;
}

// ---------------- scratch (device globals) ----------------
__device__ __align__(128) __nv_bfloat16 g_x_pack   [2u*2048u*3072u];  // [lc|gc]
__device__ __align__(128) __nv_bfloat16 g_wqkv_pack[2u*1536u*3072u];  // [W_lc|W_gc]
__device__ __align__(128) __nv_bfloat16 g_wpr_pack [2u*1024u*6144u];  // [W_local|W_global]
__device__ __align__(128) float g_comb[2u*2048u*1536u];               // [lc|gc]
__device__ __align__(128) __nv_bfloat16 g_q_pack [32u*1024u*384u];    // q/8, [hi|lo|hi]
__device__ __align__(128) __nv_bfloat16 g_k_pack [8u*1024u*384u];     // [hi|hi|lo]
__device__ __align__(128) __nv_bfloat16 g_vT_pack[8u*128u*3072u];     // V^T [hi|hi|lo]
__device__ __align__(128) __nv_bfloat16 g_ao_pack[2048u*6144u];       // attn-out [hi|lo|hi]
__device__ __align__(128) float g_yy[4096u*1024u];

// ---------------- pack: f32 [R x K] -> bf16 [R x 3K], 8 elems/thread ----------------
template<bool AFORM>  // true: [hi|lo|hi] (A), false: [hi|hi|lo] (B)
__global__ __launch_bounds__(256)
void packK(const float* __restrict__ src, __nv_bfloat16* __restrict__ dst, int K, int total)
{
  int idx = (blockIdx.x*256 + threadIdx.x)*8;
  if (idx >= total) return;
  float4 v0 = *(const float4*)(src + idx);
  float4 v1 = *(const float4*)(src + idx + 4);
  int r = idx / K, k = idx - r*K;
  __nv_bfloat16* d = dst + (ll)r*3*K + k;
  float vv[8] = {v0.x,v0.y,v0.z,v0.w,v1.x,v1.y,v1.z,v1.w};
  uint32_t hw[4], lw[4];
#pragma unroll
  for (int i=0;i<4;i++){
    __nv_bfloat16 h0,l0,h1,l1;
    bsplit(vv[2*i],h0,l0); bsplit(vv[2*i+1],h1,l1);
    hw[i] = packb2(h0,h1); lw[i] = packb2(l0,l1);
  }
  uint4 hv = make_uint4(hw[0],hw[1],hw[2],hw[3]);
  uint4 lv = make_uint4(lw[0],lw[1],lw[2],lw[3]);
  *(uint4*)(d)       = hv;
  *(uint4*)(d + K)   = AFORM ? lv : hv;
  *(uint4*)(d + 2*K) = AFORM ? hv : lv;
}

// ---------------- mma.sync GEMM, K-chunk 64, single-barrier pipeline ----------------
// C[m][n] = cscale*sum_k A[m][k]*B[n][k]; batch z: A+=z*sA, B+=z*sB, C+=z*sC.
// SPLIT_N: N=2048 output split into two 1024-wide f32 matrices (ldc=1024),
//          second half offset by 2048*1024, per-half bias0/bias1.
#define ROWB2 144     // 128B data + 16B pad (9x16 -> conflict-free ldsm)
#define STG 36864     // (128+128)*144

template<bool SPLIT_N>
__global__ __launch_bounds__(256, 2)
void gemm_mma(const __nv_bfloat16* __restrict__ A, const __nv_bfloat16* __restrict__ B,
              float* __restrict__ Cf,
              const float* __restrict__ bias0, const float* __restrict__ bias1,
              int Kp, int lda, int ldb, int ldc,
              ll sA, ll sB, ll sC, float cscale)
{
  extern __shared__ char smem[];
  const uint32_t sb = smem_u32(smem);
  const int tid = threadIdx.x, wid = tid>>5, lane = tid&31;
  const int z = blockIdx.z;
  const int m0 = blockIdx.y*128, n0 = blockIdx.x*128;
  A += z*sA + (ll)m0*lda;
  B += z*sB + (ll)n0*ldb;
  Cf += z*sC;

  const int wm = wid>>1, wn = wid&1;  // 4(M) x 2(N) warps: 32x64 per warp

  float acc[2][8][4];
#pragma unroll
  for (int i=0;i<2;i++)
#pragma unroll
    for (int j=0;j<8;j++)
#pragma unroll
      for (int q=0;q<4;q++) acc[i][j][q]=0.f;

  const int nch = Kp >> 6;

  auto loadStage = [&](int c, int s){
    const __nv_bfloat16* Ak = A + c*64;
    const __nv_bfloat16* Bk = B + c*64;
    uint32_t abase = sb + s*STG;
    uint32_t bbase = abase + 18432;
#pragma unroll
    for (int i=0;i<4;i++){
      int f = tid + i*256;
      int r = f>>3, q = f&7;
      cp_async16(abase + r*ROWB2 + q*16, (const char*)(Ak + (ll)r*lda) + q*16);
      cp_async16(bbase + r*ROWB2 + q*16, (const char*)(Bk + (ll)r*ldb) + q*16);
    }
  };

  loadStage(0, 0); CP_COMMIT();

  for (int c=0; c<nch; c++){
    CP_WAIT0();
    __syncthreads();
    if (c+1 < nch){ loadStage(c+1, (c+1)&1); CP_COMMIT(); }

    const uint32_t abase = sb + (c&1)*STG;
    const uint32_t bbase = abase + 18432;
#pragma unroll
    for (int kk=0; kk<64; kk+=16){
      uint32_t a[2][4], b[4][4];
#pragma unroll
      for (int h=0; h<2; h++)
        ldsm_x4(a[h], abase + (wm*32 + h*16 + (lane&15))*ROWB2
                             + (kk + ((lane>>4)<<3))*2);
#pragma unroll
      for (int p=0; p<4; p++)
        ldsm_x4(b[p], bbase + (wn*64 + p*16 + ((lane>>4)&1)*8 + (lane&7))*ROWB2
                             + (kk + (((lane>>3)&1)<<3))*2);
#pragma unroll
      for (int mi=0; mi<2; mi++)
#pragma unroll
        for (int p=0; p<4; p++){
          mma16816(acc[mi][2*p+0], a[mi], &b[p][0]);
          mma16816(acc[mi][2*p+1], a[mi], &b[p][2]);
        }
    }
  }

#pragma unroll
  for (int mi=0; mi<2; mi++){
#pragma unroll
    for (int ni=0; ni<8; ni++){
      int mrow = m0 + wm*32 + mi*16 + (lane>>2);
      int ncol = n0 + wn*64 + ni*8 + (lane&3)*2;
#pragma unroll
      for (int hh=0; hh<2; hh++){
        int m = mrow + hh*8;
        float v0 = acc[mi][ni][2*hh+0]*cscale;
        float v1 = acc[mi][ni][2*hh+1]*cscale;
        if (SPLIT_N){
          int nl = ncol & 1023;
          const float* bs = (ncol >= 1024) ? bias1 : bias0;
          v0 += bs[nl]; v1 += bs[nl+1];
          float* dst = Cf + ((ncol >= 1024) ? 2097152LL : 0LL) + (ll)m*1024 + nl;
          *(float2*)dst = make_float2(v0,v1);
        } else {
          *(float2*)(Cf + (ll)m*ldc + ncol) = make_float2(v0,v1);
        }
      }
    }
  }
}

// ---------------- fused flash attention (K-chunk 64, single-barrier) ----------------
#define QROWB 784     // 768B + 16 pad
#define KROWB 144     // 128B + 16 pad
#define VROWB 272     // 256B + 16 pad
#define OFF_K  100352
#define OFF_V  137216
#define OFF_VL 172032
#define FSMEM  206848

__global__ __launch_bounds__(256, 1)
void flash_attn(const __nv_bfloat16* __restrict__ qp,
                const __nv_bfloat16* __restrict__ kp,
                const __nv_bfloat16* __restrict__ vtp,
                __nv_bfloat16* __restrict__ aop)
{
  extern __shared__ char smem[];
  const uint32_t sb = smem_u32(smem);
  const int tid = threadIdx.x, wid = tid>>5, lane = tid&31;
  const int z = blockIdx.y, b = z>>4, h = z&15;
  const int s0 = blockIdx.x*128;
  const __nv_bfloat16* Qb = qp + ((ll)z*1024 + s0)*384;
  const __nv_bfloat16* Kb = kp + (ll)(z>>2)*1024*384;
  const __nv_bfloat16* Vb = vtp + (ll)(z>>2)*128*3072;

  // Q tile (128 x 384 bf16)
#pragma unroll
  for (int i=0;i<24;i++){
    int f = tid + i*256;
    int r = f/48, c = f - r*48;
    cp_async16(sb + r*QROWB + c*16, (const char*)(Qb + (ll)r*384) + c*16);
  }
  CP_COMMIT();

  float m0=-1e30f, m1=-1e30f, l0=0.f, l1=0.f;
  float o[16][4];
#pragma unroll
  for (int ni=0;ni<16;ni++){ o[ni][0]=0.f;o[ni][1]=0.f;o[ni][2]=0.f;o[ni][3]=0.f; }

  for (int nc=0; nc<8; nc++){
    const __nv_bfloat16* Kc = Kb + (ll)(nc*128)*384;
    // K chunk 0 + V hi/lo tiles -> one group
#pragma unroll
    for (int i=0;i<4;i++){
      int f = tid + i*256;
      int r = f>>3, q = f&7;
      cp_async16(sb + OFF_K + r*KROWB + q*16, (const char*)(Kc + (ll)r*384) + q*16);
    }
#pragma unroll
    for (int i=0;i<8;i++){
      int f = tid + i*256;
      int d = f>>4, c = f&15;
      const char* base = (const char*)(Vb + (ll)d*3072 + nc*128);
      cp_async16(sb + OFF_V  + d*VROWB + c*16, base + c*16);
      cp_async16(sb + OFF_VL + d*VROWB + c*16, base + 2048*2 + c*16);
    }
    CP_COMMIT();

    float acc[16][4];
#pragma unroll
    for (int ni=0;ni<16;ni++){ acc[ni][0]=0.f;acc[ni][1]=0.f;acc[ni][2]=0.f;acc[ni][3]=0.f; }

    for (int kc=0; kc<6; kc++){
      CP_WAIT0();
      __syncthreads();
      if (kc+1 < 6){
        uint32_t kb2 = sb + OFF_K + ((kc+1)&1)*18432;
#pragma unroll
        for (int i=0;i<4;i++){
          int f = tid + i*256;
          int r = f>>3, q = f&7;
          cp_async16(kb2 + r*KROWB + q*16,
                     (const char*)(Kc + (ll)r*384 + (kc+1)*64) + q*16);
        }
        CP_COMMIT();
      }

      const uint32_t kb = sb + OFF_K + (kc&1)*18432;
#pragma unroll
      for (int kk=0; kk<64; kk+=16){
        uint32_t a[4];
        ldsm_x4(a, sb + (wid*16 + (lane&15))*QROWB + (kc*64 + kk + ((lane>>4)<<3))*2);
        uint32_t bf[8][4];
#pragma unroll
        for (int p=0;p<8;p++)
          ldsm_x4(bf[p], kb + (p*16 + ((lane>>4)&1)*8 + (lane&7))*KROWB
                            + (kk + (((lane>>3)&1)<<3))*2);
#pragma unroll
        for (int p=0;p<8;p++){
          mma16816(acc[2*p+0], a, &bf[p][0]);
          mma16816(acc[2*p+1], a, &bf[p][2]);
        }
      }
    }

    // ---- online softmax (registers + quad shuffles) ----
    float cm0=-1e30f, cm1=-1e30f;
#pragma unroll
    for (int ni=0;ni<16;ni++){
      cm0 = fmaxf(cm0, fmaxf(acc[ni][0], acc[ni][1]));
      cm1 = fmaxf(cm1, fmaxf(acc[ni][2], acc[ni][3]));
    }
    cm0 = fmaxf(cm0, __shfl_xor_sync(0xffffffffu, cm0, 1));
    cm0 = fmaxf(cm0, __shfl_xor_sync(0xffffffffu, cm0, 2));
    cm1 = fmaxf(cm1, __shfl_xor_sync(0xffffffffu, cm1, 1));
    cm1 = fmaxf(cm1, __shfl_xor_sync(0xffffffffu, cm1, 2));
    float mn0 = fmaxf(m0, cm0), mn1 = fmaxf(m1, cm1);
    float sc0 = __expf(m0 - mn0), sc1 = __expf(m1 - mn1);
    m0 = mn0; m1 = mn1;
    float rs0=0.f, rs1=0.f;
#pragma unroll
    for (int ni=0;ni<16;ni++){
      acc[ni][0]=__expf(acc[ni][0]-m0); acc[ni][1]=__expf(acc[ni][1]-m0);
      acc[ni][2]=__expf(acc[ni][2]-m1); acc[ni][3]=__expf(acc[ni][3]-m1);
      rs0 += acc[ni][0]+acc[ni][1];
      rs1 += acc[ni][2]+acc[ni][3];
    }
    rs0 += __shfl_xor_sync(0xffffffffu, rs0, 1);
    rs0 += __shfl_xor_sync(0xffffffffu, rs0, 2);
    rs1 += __shfl_xor_sync(0xffffffffu, rs1, 1);
    rs1 += __shfl_xor_sync(0xffffffffu, rs1, 2);
    l0 = l0*sc0 + rs0;
    l1 = l1*sc1 + rs1;
#pragma unroll
    for (int ni=0;ni<16;ni++){
      o[ni][0]*=sc0; o[ni][1]*=sc0; o[ni][2]*=sc1; o[ni][3]*=sc1;
    }

    // ---- PV: Phi*Vhi + Plo*Vhi + Phi*Vlo ----
#pragma unroll
    for (int kg=0; kg<8; kg++){
      uint32_t ahi[4], alo[4];
      {
        __nv_bfloat16 x0,y0,x1,y1;
        bsplit(acc[2*kg][0],x0,y0);   bsplit(acc[2*kg][1],x1,y1);
        ahi[0]=packb2(x0,x1); alo[0]=packb2(y0,y1);
        bsplit(acc[2*kg][2],x0,y0);   bsplit(acc[2*kg][3],x1,y1);
        ahi[1]=packb2(x0,x1); alo[1]=packb2(y0,y1);
        bsplit(acc[2*kg+1][0],x0,y0); bsplit(acc[2*kg+1][1],x1,y1);
        ahi[2]=packb2(x0,x1); alo[2]=packb2(y0,y1);
        bsplit(acc[2*kg+1][2],x0,y0); bsplit(acc[2*kg+1][3],x1,y1);
        ahi[3]=packb2(x0,x1); alo[3]=packb2(y0,y1);
      }
#pragma unroll
      for (int p=0;p<8;p++){
        uint32_t rowoff = (p*16 + ((lane>>4)&1)*8 + (lane&7))*VROWB
                        + (kg*16 + (((lane>>3)&1)<<3))*2;
        uint32_t bh[4], bl[4];
        ldsm_x4(bh, sb + OFF_V  + rowoff);
        ldsm_x4(bl, sb + OFF_VL + rowoff);
        mma16816(o[2*p+0], ahi, &bh[0]);
        mma16816(o[2*p+0], alo, &bh[0]);
        mma16816(o[2*p+0], ahi, &bl[0]);
        mma16816(o[2*p+1], ahi, &bh[2]);
        mma16816(o[2*p+1], alo, &bh[2]);
        mma16816(o[2*p+1], ahi, &bl[2]);
      }
    }
    __syncthreads();   // protect K/V smem before next chunk's loads
  }

  // ---- epilogue: normalize + [hi|lo|hi] pack ----
  const float inv0 = 1.f/l0, inv1 = 1.f/l1;
  const int qrow0 = s0 + wid*16 + (lane>>2);
  const ll rb0 = ((ll)(b*1024 + qrow0))*6144 + h*128;
  const ll rb1 = rb0 + 8LL*6144;
#pragma unroll
  for (int ni=0;ni<16;ni++){
    int col = ni*8 + (lane&3)*2;
    {
      float v0 = o[ni][0]*inv0, v1 = o[ni][1]*inv0;
      __nv_bfloat16 h0,l0b,h1,l1b; bsplit(v0,h0,l0b); bsplit(v1,h1,l1b);
      __nv_bfloat16* d = aop + rb0 + col;
      *(__nv_bfloat162*)(d)      = __nv_bfloat162(h0,h1);
      *(__nv_bfloat162*)(d+2048) = __nv_bfloat162(l0b,l1b);
      *(__nv_bfloat162*)(d+4096) = __nv_bfloat162(h0,h1);
    }
    {
      float v0 = o[ni][2]*inv1, v1 = o[ni][3]*inv1;
      __nv_bfloat16 h0,l0b,h1,l1b; bsplit(v0,h0,l0b); bsplit(v1,h1,l1b);
      __nv_bfloat16* d = aop + rb1 + col;
      *(__nv_bfloat162*)(d)      = __nv_bfloat162(h0,h1);
      *(__nv_bfloat162*)(d+2048) = __nv_bfloat162(l0b,l1b);
      *(__nv_bfloat162*)(d+4096) = __nv_bfloat162(h0,h1);
    }
  }
}

// ---------------- RMSNorm + RoPE + split-pack q/k/vT ----------------
__global__ __launch_bounds__(256)
void norm_rope_pack(const float* __restrict__ cl, const float* __restrict__ cg,
                    const float* __restrict__ cosT, const float* __restrict__ sinT,
                    const float* __restrict__ gql, const float* __restrict__ gkl,
                    const float* __restrict__ gqg, const float* __restrict__ gkg,
                    __nv_bfloat16* __restrict__ qp, __nv_bfloat16* __restrict__ kp,
                    __nv_bfloat16* __restrict__ vp)
{
  const int bs = blockIdx.x;
  const int b = bs >> 10, s = bs & 1023;
  const int t = threadIdx.x;
  const float* rl = cl + (ll)bs*1536;
  const float* rg = cg + (ll)bs*1536;

  float sql=0.f, sqg=0.f;
#pragma unroll
  for (int i=t;i<1024;i+=256){ float x=rl[i]; sql+=x*x; float y=rg[i]; sqg+=y*y; }
  float xk=rl[1024+t], yk=rg[1024+t];
  float skl = xk*xk, skg = yk*yk;

  __shared__ float4 red[8];
  float4 v4 = make_float4(sql,sqg,skl,skg);
#pragma unroll
  for (int off=16;off;off>>=1){
    v4.x += __shfl_xor_sync(0xffffffffu, v4.x, off);
    v4.y += __shfl_xor_sync(0xffffffffu, v4.y, off);
    v4.z += __shfl_xor_sync(0xffffffffu, v4.z, off);
    v4.w += __shfl_xor_sync(0xffffffffu, v4.w, off);
  }
  const int w = t>>5, l = t&31;
  if (!l) red[w]=v4;
  __syncthreads();
  if (t==0){
    float4 a = red[0];
    for (int i=1;i<8;i++){ a.x+=red[i].x; a.y+=red[i].y; a.z+=red[i].z; a.w+=red[i].w; }
    red[0]=a;
  }
  __syncthreads();
  float4 tot = red[0];
  const float rql = rsqrtf(tot.x*(1.f/1024.f)+1e-5f) * 0.125f;  // fold /8 into q
  const float rqg = rsqrtf(tot.y*(1.f/1024.f)+1e-5f) * 0.125f;
  const float rkl = rsqrtf(tot.z*(1.f/256.f)+1e-5f);
  const float rkg = rsqrtf(tot.w*(1.f/256.f)+1e-5f);

  // q rows: [(b*16+h)*1024+s] x 384 in [hi|lo|hi]
#pragma unroll
  for (int pp=t; pp<512; pp+=256){
    int h = pp>>5, p = pp&31;
    float c = cosT[s*32+p], sn = sinT[s*32+p];
    int d0 = h*64 + 2*p;
    ll base = (((ll)(b*16+h))*1024 + s)*384;
    float x0 = rl[d0]*rql*gql[d0];
    float x1 = rl[d0+1]*rql*gql[d0+1];
    float y0 = rg[d0]*rqg*gqg[d0];
    float y1 = rg[d0+1]*rqg*gqg[d0+1];
    float o0 = x0*c - x1*sn, o1 = x0*sn + x1*c;
    float o2 = y0*c - y1*sn, o3 = y0*sn + y1*c;
    __nv_bfloat16 h0,l0,h1,l1,h2,l2,h3,l3;
    bsplit(o0,h0,l0); bsplit(o1,h1,l1); bsplit(o2,h2,l2); bsplit(o3,h3,l3);
    *(__nv_bfloat162*)(qp+base+2*p)        = __nv_bfloat162(h0,h1);
    *(__nv_bfloat162*)(qp+base+128+2*p)    = __nv_bfloat162(l0,l1);
    *(__nv_bfloat162*)(qp+base+256+2*p)    = __nv_bfloat162(h0,h1);
    *(__nv_bfloat162*)(qp+base+64+2*p)     = __nv_bfloat162(h2,h3);
    *(__nv_bfloat162*)(qp+base+128+64+2*p) = __nv_bfloat162(l2,l3);
    *(__nv_bfloat162*)(qp+base+256+64+2*p) = __nv_bfloat162(h2,h3);
  }
  // k rows: [(b*4+kh)*1024+s] x 384 in [hi|hi|lo]
  if (t < 128){
    int kh = t>>5, p = t&31;
    float c = cosT[s*32+p], sn = sinT[s*32+p];
    int gd = kh*64 + 2*p;
    ll base = (((ll)(b*4+kh))*1024 + s)*384;
    float x0 = rl[1024+gd]*rkl*gkl[gd];
    float x1 = rl[1024+gd+1]*rkl*gkl[gd+1];
    float y0 = rg[1024+gd]*rkg*gkg[gd];
    float y1 = rg[1024+gd+1]*rkg*gkg[gd+1];
    float o0 = x0*c - x1*sn, o1 = x0*sn + x1*c;
    float o2 = y0*c - y1*sn, o3 = y0*sn + y1*c;
    __nv_bfloat16 h0,l0,h1,l1,h2,l2,h3,l3;
    bsplit(o0,h0,l0); bsplit(o1,h1,l1); bsplit(o2,h2,l2); bsplit(o3,h3,l3);
    *(__nv_bfloat162*)(kp+base+2*p)        = __nv_bfloat162(h0,h1);
    *(__nv_bfloat162*)(kp+base+128+2*p)    = __nv_bfloat162(h0,h1);
    *(__nv_bfloat162*)(kp+base+256+2*p)    = __nv_bfloat162(l0,l1);
    *(__nv_bfloat162*)(kp+base+64+2*p)     = __nv_bfloat162(h2,h3);
    *(__nv_bfloat162*)(kp+base+128+64+2*p) = __nv_bfloat162(h2,h3);
    *(__nv_bfloat162*)(kp+base+256+64+2*p) = __nv_bfloat162(l2,l3);
  }
  // vT rows: [(b*4+kh)*128 + d] x 3072 in [hi|hi|lo], column = s
  {
    int kh = t>>6, d = t&63;
    ll rowl = ((ll)(b*4+kh))*128 + d;
    ll rowg = rowl + 64;
    __nv_bfloat16 hi, lo;
    bsplit(rl[1280+t], hi, lo);
    vp[rowl*3072 + s] = hi; vp[rowl*3072 + 1024 + s] = hi; vp[rowl*3072 + 2048 + s] = lo;
    bsplit(rg[1280+t], hi, lo);
    vp[rowg*3072 + s] = hi; vp[rowg*3072 + 1024 + s] = hi; vp[rowg*3072 + 2048 + s] = lo;
  }
}

// ---------------- final RMSNorm -> d_out ----------------
__global__ __launch_bounds__(256)
void rmsnorm_out(const float* __restrict__ y, const float* __restrict__ glc,
                 const float* __restrict__ ggc, float* __restrict__ out)
{
  const int row = blockIdx.x;
  const float* g = (row < 2048) ? glc : ggc;
  const float* r = y + (ll)row*1024;
  float* o = out + (ll)row*1024;
  const int t = threadIdx.x;
  float4 v = ((const float4*)r)[t];
  float ss = v.x*v.x + v.y*v.y + v.z*v.z + v.w*v.w;
  __shared__ float sm[8];
#pragma unroll
  for (int o2=16;o2;o2>>=1) ss += __shfl_xor_sync(0xffffffffu,ss,o2);
  const int w=t>>5, l=t&31;
  if (!l) sm[w]=ss;
  __syncthreads();
  ss = sm[0]+sm[1]+sm[2]+sm[3]+sm[4]+sm[5]+sm[6]+sm[7];
  const float rsq = rsqrtf(ss*(1.f/1024.f)+1e-5f);
  float4 gv = ((const float4*)g)[t];
  float4 ov = make_float4(v.x*rsq*gv.x, v.y*rsq*gv.y, v.z*rsq*gv.z, v.w*rsq*gv.w);
  ((float4*)o)[t]=ov;
}

// ---------------- launch ----------------
extern "C" void kernel_launch(void* const* d_in, const int* in_sizes, int n_in,
                              void* d_out, int out_size)
{
  (void)in_sizes; (void)n_in; (void)out_size;
  const float* local_c  = (const float*)d_in[0];
  const float* global_c = (const float*)d_in[1];
  const float* fcos     = (const float*)d_in[2];
  const float* fsin     = (const float*)d_in[3];
  const float* W_lc     = (const float*)d_in[4];
  const float* W_gc     = (const float*)d_in[5];
  const float* g_q_lc   = (const float*)d_in[6];
  const float* g_k_lc   = (const float*)d_in[7];
  const float* g_q_gc   = (const float*)d_in[8];
  const float* g_k_gc   = (const float*)d_in[9];
  const float* W_local  = (const float*)d_in[10];
  const float* b_local  = (const float*)d_in[11];
  const float* g_lc_out = (const float*)d_in[12];
  const float* W_global = (const float*)d_in[13];
  const float* b_global = (const float*)d_in[14];
  const float* g_gc_out = (const float*)d_in[15];

  __nv_bfloat16 *xp,*wq,*wp,*qp,*kp,*vtp,*aop;
  float *comb,*yy;
  cudaGetSymbolAddress((void**)&xp,  g_x_pack);
  cudaGetSymbolAddress((void**)&wq,  g_wqkv_pack);
  cudaGetSymbolAddress((void**)&wp,  g_wpr_pack);
  cudaGetSymbolAddress((void**)&comb, g_comb);
  cudaGetSymbolAddress((void**)&qp,  g_q_pack);
  cudaGetSymbolAddress((void**)&kp,  g_k_pack);
  cudaGetSymbolAddress((void**)&vtp, g_vT_pack);
  cudaGetSymbolAddress((void**)&aop, g_ao_pack);
  cudaGetSymbolAddress((void**)&yy,  g_yy);

  const int SMEMSZ = 2*STG;  // 73728
  static int attr_done = 0;
  if (!attr_done){
    cudaFuncSetAttribute(gemm_mma<false>, cudaFuncAttributeMaxDynamicSharedMemorySize, SMEMSZ);
    cudaFuncSetAttribute(gemm_mma<true>,  cudaFuncAttributeMaxDynamicSharedMemorySize, SMEMSZ);
    cudaFuncSetAttribute(flash_attn, cudaFuncAttributeMaxDynamicSharedMemorySize, FSMEM);
    attr_done = 1;
  }

  // 0) operand packs (8 elems/thread, vector stores)
  packK<true ><<<1024,256>>>(local_c,  xp,                 1024, 2048*1024);
  packK<true ><<<1024,256>>>(global_c, xp + 2048u*3072u,   1024, 2048*1024);
  packK<false><<< 768,256>>>(W_lc,     wq,                 1024, 1536*1024);
  packK<false><<< 768,256>>>(W_gc,     wq + 1536u*3072u,   1024, 1536*1024);
  packK<false><<<1024,256>>>(W_local,  wp,                 2048, 1024*2048);
  packK<false><<<1024,256>>>(W_global, wp + 1024u*6144u,   2048, 1024*2048);

  // 1) QKV projections, batched z=2: comb[z] = x[z] @ W[z]^T  (M=2048,N=1536,K'=3072)
  gemm_mma<false><<<dim3(12,16,2),256,SMEMSZ>>>(xp, wq, comb, nullptr, nullptr,
     3072, 3072,3072,1536, 2048LL*3072, 1536LL*3072, 2048LL*1536, 1.f);

  // 2) rmsnorm + rope + split-pack (q scaled by 1/8)
  norm_rope_pack<<<2048,256>>>(comb, comb + 2048u*1536u, fcos, fsin,
                               g_q_lc, g_k_lc, g_q_gc, g_k_gc, qp, kp, vtp);

  // 3) fused attention -> aop [hi|lo|hi]
  flash_attn<<<dim3(8,32),256,FSMEM>>>(qp, kp, vtp, aop);

  // 4) merged output projections + bias  (M=2048,N=2048,K'=6144, split-N epilogue)
  gemm_mma<true><<<dim3(16,16,1),256,SMEMSZ>>>(aop, wp, yy, b_local, b_global,
     6144, 6144,6144,1024, 0,0,0, 1.f);

  // 5) final rmsnorm -> d_out
  rmsnorm_out<<<4096,256>>>(yy, g_lc_out, g_gc_out, (float*)d_out);
}

// round 8
// speedup vs baseline: 2.6045x; 1.0962x over previous
#include <cuda_runtime.h>
#include <cuda_bf16.h>
#include <cstdint>

// B=2, S=1024, D=1024, H=16, KVH=4, HD=64, TOT=1536
// GEMMs on mma.sync bf16 tensor cores; fp32-level accuracy via 2-term split:
//   A packed [hi|lo|hi], B packed [hi|hi|lo]  => hi*hi + lo*hi + hi*lo, K' = 3K.
// 3-stage cp.async pipelines; flash attention with V interleaved into K groups
// and cross-chunk K prefetch.

typedef unsigned long long ull;
typedef long long ll;
#define DEVFN static __device__ __forceinline__

// ---------------- PTX helpers ----------------
DEVFN uint32_t smem_u32(const void* p){
  uint32_t a; asm("{ .reg .u64 t; cvta.to.shared.u64 t, %1; cvt.u32.u64 %0, t; }":"=r"(a):"l"(p)); return a;
}
DEVFN void ldsm_x4(uint32_t* r, uint32_t addr){
  asm volatile("ldmatrix.sync.aligned.m8n8.x4.shared.b16 {%0,%1,%2,%3}, [%4];"
    : "=r"(r[0]),"=r"(r[1]),"=r"(r[2]),"=r"(r[3]) : "r"(addr));
}
DEVFN void mma16816(float* c, const uint32_t* a, const uint32_t* b){
  asm volatile("mma.sync.aligned.m16n8k16.row.col.f32.bf16.bf16.f32 "
    "{%0,%1,%2,%3}, {%4,%5,%6,%7}, {%8,%9}, {%0,%1,%2,%3};"
    : "+f"(c[0]),"+f"(c[1]),"+f"(c[2]),"+f"(c[3])
    : "r"(a[0]),"r"(a[1]),"r"(a[2]),"r"(a[3]), "r"(b[0]),"r"(b[1]));
}
DEVFN void cp_async16(uint32_t dst, const void* src){
  asm volatile("cp.async.cg.shared.global [%0], [%1], 16;" :: "r"(dst), "l"(src));
}
#define CP_COMMIT() asm volatile("cp.async.commit_group;" ::: "memory")
template<int N> DEVFN void cp_waitg(){ asm volatile("cp.async.wait_group %0;"::"n"(N):"memory"); }

DEVFN void bsplit(float x, __nv_bfloat16 &hi, __nv_bfloat16 &lo){
  hi = __float2bfloat16(x);
  lo = __float2bfloat16(x - __bfloat162float(hi));
}
DEVFN uint32_t packb2(__nv_bfloat16 a, __nv_bfloat16 b){
  __nv_bfloat162 t(a, b); return *(uint32_t*)&t;
}

// ---------------- scratch (device globals) ----------------
__device__ __align__(128) __nv_bfloat16 g_x_pack   [2u*2048u*3072u];  // [lc|gc]
__device__ __align__(128) __nv_bfloat16 g_wqkv_pack[2u*1536u*3072u];  // [W_lc|W_gc]
__device__ __align__(128) __nv_bfloat16 g_wpr_pack [2u*1024u*6144u];  // [W_local|W_global]
__device__ __align__(128) float g_comb[2u*2048u*1536u];               // [lc|gc]
__device__ __align__(128) __nv_bfloat16 g_q_pack [32u*1024u*384u];    // q/8, [hi|lo|hi]
__device__ __align__(128) __nv_bfloat16 g_k_pack [8u*1024u*384u];     // [hi|hi|lo]
__device__ __align__(128) __nv_bfloat16 g_vT_pack[8u*128u*3072u];     // V^T [hi|hi|lo]
__device__ __align__(128) __nv_bfloat16 g_ao_pack[2048u*6144u];       // attn-out [hi|lo|hi]
__device__ __align__(128) float g_yy[4096u*1024u];

// ---------------- one merged pack launch: f32 [R x K] -> bf16 [R x 3K] ----------------
// blocks: [0,1024) xl | [1024,2048) xg | [2048,2816) wlc | [2816,3584) wgc
//         [3584,4608) wlo | [4608,5632) wgo
__global__ __launch_bounds__(256)
void packAll(const float* __restrict__ xl, const float* __restrict__ xg,
             const float* __restrict__ wlc, const float* __restrict__ wgc,
             const float* __restrict__ wlo, const float* __restrict__ wgo,
             __nv_bfloat16* __restrict__ xp, __nv_bfloat16* __restrict__ wq,
             __nv_bfloat16* __restrict__ wp)
{
  int bx = blockIdx.x;
  const float* src; __nv_bfloat16* dst; int K; bool af;
  if (bx < 2048){
    af = true; K = 1024;
    if (bx < 1024){ src = xl; dst = xp; }
    else { src = xg; dst = xp + 2048u*3072u; bx -= 1024; }
  } else if (bx < 3584){
    af = false; K = 1024; bx -= 2048;
    if (bx < 768){ src = wlc; dst = wq; }
    else { src = wgc; dst = wq + 1536u*3072u; bx -= 768; }
  } else {
    af = false; K = 2048; bx -= 3584;
    if (bx < 1024){ src = wlo; dst = wp; }
    else { src = wgo; dst = wp + 1024u*6144u; bx -= 1024; }
  }
  int idx = (bx*256 + threadIdx.x)*8;
  float4 v0 = *(const float4*)(src + idx);
  float4 v1 = *(const float4*)(src + idx + 4);
  int r = idx / K, k = idx - r*K;
  __nv_bfloat16* d = dst + (ll)r*3*K + k;
  float vv[8] = {v0.x,v0.y,v0.z,v0.w,v1.x,v1.y,v1.z,v1.w};
  uint32_t hw[4], lw[4];
#pragma unroll
  for (int i=0;i<4;i++){
    __nv_bfloat16 h0,l0,h1,l1;
    bsplit(vv[2*i],h0,l0); bsplit(vv[2*i+1],h1,l1);
    hw[i] = packb2(h0,h1); lw[i] = packb2(l0,l1);
  }
  uint4 hv = make_uint4(hw[0],hw[1],hw[2],hw[3]);
  uint4 lv = make_uint4(lw[0],lw[1],lw[2],lw[3]);
  *(uint4*)(d)       = hv;
  *(uint4*)(d + K)   = af ? lv : hv;
  *(uint4*)(d + 2*K) = af ? hv : lv;
}

// ---------------- mma.sync GEMM, K-chunk 64, 3-stage pipeline ----------------
#define ROWB2 144     // 128B data + 16B pad
#define STG 36864     // (128+128)*144 per stage

template<bool SPLIT_N>
__global__ __launch_bounds__(256, 2)
void gemm_mma(const __nv_bfloat16* __restrict__ A, const __nv_bfloat16* __restrict__ B,
              float* __restrict__ Cf,
              const float* __restrict__ bias0, const float* __restrict__ bias1,
              int Kp, int lda, int ldb, int ldc,
              ll sA, ll sB, ll sC, float cscale)
{
  extern __shared__ char smem[];
  const uint32_t sb = smem_u32(smem);
  const int tid = threadIdx.x, wid = tid>>5, lane = tid&31;
  const int z = blockIdx.z;
  const int m0 = blockIdx.y*128, n0 = blockIdx.x*128;
  A += z*sA + (ll)m0*lda;
  B += z*sB + (ll)n0*ldb;
  Cf += z*sC;

  const int wm = wid>>1, wn = wid&1;  // 4(M) x 2(N) warps: 32x64 per warp

  float acc[2][8][4];
#pragma unroll
  for (int i=0;i<2;i++)
#pragma unroll
    for (int j=0;j<8;j++)
#pragma unroll
      for (int q=0;q<4;q++) acc[i][j][q]=0.f;

  const int nch = Kp >> 6;

  auto loadStage = [&](int c, int s){
    const __nv_bfloat16* Ak = A + c*64;
    const __nv_bfloat16* Bk = B + c*64;
    uint32_t abase = sb + s*STG;
    uint32_t bbase = abase + 18432;
#pragma unroll
    for (int i=0;i<4;i++){
      int f = tid + i*256;
      int r = f>>3, q = f&7;
      cp_async16(abase + r*ROWB2 + q*16, (const char*)(Ak + (ll)r*lda) + q*16);
      cp_async16(bbase + r*ROWB2 + q*16, (const char*)(Bk + (ll)r*ldb) + q*16);
    }
  };

  loadStage(0, 0); CP_COMMIT();
  if (nch > 1) loadStage(1, 1);
  CP_COMMIT();

  for (int c=0; c<nch; c++){
    cp_waitg<1>();
    __syncthreads();
    if (c+2 < nch) loadStage(c+2, (c+2)%3);
    CP_COMMIT();

    const uint32_t abase = sb + (c%3)*STG;
    const uint32_t bbase = abase + 18432;
#pragma unroll
    for (int kk=0; kk<64; kk+=16){
      uint32_t a[2][4], b[4][4];
#pragma unroll
      for (int h=0; h<2; h++)
        ldsm_x4(a[h], abase + (wm*32 + h*16 + (lane&15))*ROWB2
                             + (kk + ((lane>>4)<<3))*2);
#pragma unroll
      for (int p=0; p<4; p++)
        ldsm_x4(b[p], bbase + (wn*64 + p*16 + ((lane>>4)&1)*8 + (lane&7))*ROWB2
                             + (kk + (((lane>>3)&1)<<3))*2);
#pragma unroll
      for (int mi=0; mi<2; mi++)
#pragma unroll
        for (int p=0; p<4; p++){
          mma16816(acc[mi][2*p+0], a[mi], &b[p][0]);
          mma16816(acc[mi][2*p+1], a[mi], &b[p][2]);
        }
    }
  }

#pragma unroll
  for (int mi=0; mi<2; mi++){
#pragma unroll
    for (int ni=0; ni<8; ni++){
      int mrow = m0 + wm*32 + mi*16 + (lane>>2);
      int ncol = n0 + wn*64 + ni*8 + (lane&3)*2;
#pragma unroll
      for (int hh=0; hh<2; hh++){
        int m = mrow + hh*8;
        float v0 = acc[mi][ni][2*hh+0]*cscale;
        float v1 = acc[mi][ni][2*hh+1]*cscale;
        if (SPLIT_N){
          int nl = ncol & 1023;
          const float* bs = (ncol >= 1024) ? bias1 : bias0;
          v0 += bs[nl]; v1 += bs[nl+1];
          float* dst = Cf + ((ncol >= 1024) ? 2097152LL : 0LL) + (ll)m*1024 + nl;
          *(float2*)dst = make_float2(v0,v1);
        } else {
          *(float2*)(Cf + (ll)m*ldc + ncol) = make_float2(v0,v1);
        }
      }
    }
  }
}

// ---------------- fused flash attention ----------------
// 3 K slots (prefetch dist 2), V spread over the K-chunk groups, next-chunk
// K0/K1 prefetched before the PV phase. Occ 1 (register-bound).
#define QROWB 784     // 768B + 16 pad
#define KROWB 144     // 128B + 16 pad
#define KSLOT 18432   // 128*144
#define VROWB 272     // 256B + 16 pad
#define OFF_K  100352                 // Q = 128*784
#define OFF_V  155648                 // OFF_K + 3*KSLOT
#define OFF_VL 190464                 // OFF_V + 128*VROWB
#define FSMEM  225280                 // OFF_VL + 128*VROWB

DEVFN void flash_issueK(uint32_t sb, const __nv_bfloat16* Kc, int kcol, int slot, int tid){
  uint32_t kb = sb + OFF_K + slot*KSLOT;
#pragma unroll
  for (int i=0;i<4;i++){
    int f = tid + i*256;
    int r = f>>3, q = f&7;
    cp_async16(kb + r*KROWB + q*16, (const char*)(Kc + (ll)r*384 + kcol) + q*16);
  }
}
// part in 0..4: rows [part*26, min(128, part*26+26)) of both hi and lo tiles
DEVFN void flash_issueV(uint32_t sb, const __nv_bfloat16* Vc, int part, int tid){
  int r0 = part*26;
  int nr = 128 - r0; if (nr > 26) nr = 26;
  for (int f = tid; f < nr*32; f += 256){
    int r = r0 + (f>>5), c = f&31;
    const char* base = (const char*)(Vc + (ll)r*3072);
    if (c < 16) cp_async16(sb + OFF_V  + r*VROWB + c*16, base + c*16);
    else        cp_async16(sb + OFF_VL + r*VROWB + (c-16)*16, base + 4096 + (c-16)*16);
  }
}

__global__ __launch_bounds__(256, 1)
void flash_attn(const __nv_bfloat16* __restrict__ qp,
                const __nv_bfloat16* __restrict__ kp,
                const __nv_bfloat16* __restrict__ vtp,
                __nv_bfloat16* __restrict__ aop)
{
  extern __shared__ char smem[];
  const uint32_t sb = smem_u32(smem);
  const int tid = threadIdx.x, wid = tid>>5, lane = tid&31;
  const int z = blockIdx.y, b = z>>4, h = z&15;
  const int s0 = blockIdx.x*128;
  const __nv_bfloat16* Qb = qp + ((ll)z*1024 + s0)*384;
  const __nv_bfloat16* Kb = kp + (ll)(z>>2)*1024*384;
  const __nv_bfloat16* Vb = vtp + (ll)(z>>2)*128*3072;

  // Q tile (128 x 384 bf16)
#pragma unroll
  for (int i=0;i<24;i++){
    int f = tid + i*256;
    int r = f/48, c = f - r*48;
    cp_async16(sb + r*QROWB + c*16, (const char*)(Qb + (ll)r*384) + c*16);
  }
  CP_COMMIT();
  // chunk 0: K0, K1
  flash_issueK(sb, Kb, 0,  0, tid); CP_COMMIT();
  flash_issueK(sb, Kb, 64, 1, tid); CP_COMMIT();

  float m0=-1e30f, m1=-1e30f, l0=0.f, l1=0.f;
  float o[16][4];
#pragma unroll
  for (int ni=0;ni<16;ni++){ o[ni][0]=0.f;o[ni][1]=0.f;o[ni][2]=0.f;o[ni][3]=0.f; }

#pragma unroll 1
  for (int nc=0; nc<8; nc++){
    const __nv_bfloat16* Kc = Kb + (ll)(nc*128)*384;
    const __nv_bfloat16* Vc = Vb + nc*128;

    float acc[16][4];
#pragma unroll
    for (int ni=0;ni<16;ni++){ acc[ni][0]=0.f;acc[ni][1]=0.f;acc[ni][2]=0.f;acc[ni][3]=0.f; }

#pragma unroll
    for (int kc=0; kc<6; kc++){
      cp_waitg<1>();            // drains group carrying K(kc)
      __syncthreads();
      if (kc < 4){
        flash_issueK(sb, Kc, (kc+2)*64, (kc+2)%3, tid);
        flash_issueV(sb, Vc, kc, tid);
        CP_COMMIT();
      } else if (kc == 4){
        flash_issueV(sb, Vc, 4, tid);
        CP_COMMIT();
      }
      const uint32_t kb = sb + OFF_K + (kc%3)*KSLOT;
#pragma unroll
      for (int kk=0; kk<64; kk+=16){
        uint32_t a[4];
        ldsm_x4(a, sb + (wid*16 + (lane&15))*QROWB + (kc*64 + kk + ((lane>>4)<<3))*2);
        uint32_t bf[8][4];
#pragma unroll
        for (int p=0;p<8;p++)
          ldsm_x4(bf[p], kb + (p*16 + ((lane>>4)&1)*8 + (lane&7))*KROWB
                            + (kk + (((lane>>3)&1)<<3))*2);
#pragma unroll
        for (int p=0;p<8;p++){
          mma16816(acc[2*p+0], a, &bf[p][0]);
          mma16816(acc[2*p+1], a, &bf[p][2]);
        }
      }
    }

    __syncthreads();            // all warps done with K smem
    if (nc < 7){                // prefetch next chunk's K0/K1 behind softmax+PV
      const __nv_bfloat16* Kn = Kb + (ll)((nc+1)*128)*384;
      flash_issueK(sb, Kn, 0,  0, tid); CP_COMMIT();
      flash_issueK(sb, Kn, 64, 1, tid); CP_COMMIT();
      cp_waitg<2>();            // drains trailing V group; next-chunk K may pend
    } else {
      cp_waitg<0>();
    }
    __syncthreads();            // V visible to all

    // ---- online softmax (registers + quad shuffles) ----
    float cm0=-1e30f, cm1=-1e30f;
#pragma unroll
    for (int ni=0;ni<16;ni++){
      cm0 = fmaxf(cm0, fmaxf(acc[ni][0], acc[ni][1]));
      cm1 = fmaxf(cm1, fmaxf(acc[ni][2], acc[ni][3]));
    }
    cm0 = fmaxf(cm0, __shfl_xor_sync(0xffffffffu, cm0, 1));
    cm0 = fmaxf(cm0, __shfl_xor_sync(0xffffffffu, cm0, 2));
    cm1 = fmaxf(cm1, __shfl_xor_sync(0xffffffffu, cm1, 1));
    cm1 = fmaxf(cm1, __shfl_xor_sync(0xffffffffu, cm1, 2));
    float mn0 = fmaxf(m0, cm0), mn1 = fmaxf(m1, cm1);
    float sc0 = __expf(m0 - mn0), sc1 = __expf(m1 - mn1);
    m0 = mn0; m1 = mn1;
    float rs0=0.f, rs1=0.f;
#pragma unroll
    for (int ni=0;ni<16;ni++){
      acc[ni][0]=__expf(acc[ni][0]-m0); acc[ni][1]=__expf(acc[ni][1]-m0);
      acc[ni][2]=__expf(acc[ni][2]-m1); acc[ni][3]=__expf(acc[ni][3]-m1);
      rs0 += acc[ni][0]+acc[ni][1];
      rs1 += acc[ni][2]+acc[ni][3];
    }
    rs0 += __shfl_xor_sync(0xffffffffu, rs0, 1);
    rs0 += __shfl_xor_sync(0xffffffffu, rs0, 2);
    rs1 += __shfl_xor_sync(0xffffffffu, rs1, 1);
    rs1 += __shfl_xor_sync(0xffffffffu, rs1, 2);
    l0 = l0*sc0 + rs0;
    l1 = l1*sc1 + rs1;
#pragma unroll
    for (int ni=0;ni<16;ni++){
      o[ni][0]*=sc0; o[ni][1]*=sc0; o[ni][2]*=sc1; o[ni][3]*=sc1;
    }

    // ---- PV: Phi*Vhi + Plo*Vhi + Phi*Vlo ----
#pragma unroll
    for (int kg=0; kg<8; kg++){
      uint32_t ahi[4], alo[4];
      {
        __nv_bfloat16 x0,y0,x1,y1;
        bsplit(acc[2*kg][0],x0,y0);   bsplit(acc[2*kg][1],x1,y1);
        ahi[0]=packb2(x0,x1); alo[0]=packb2(y0,y1);
        bsplit(acc[2*kg][2],x0,y0);   bsplit(acc[2*kg][3],x1,y1);
        ahi[1]=packb2(x0,x1); alo[1]=packb2(y0,y1);
        bsplit(acc[2*kg+1][0],x0,y0); bsplit(acc[2*kg+1][1],x1,y1);
        ahi[2]=packb2(x0,x1); alo[2]=packb2(y0,y1);
        bsplit(acc[2*kg+1][2],x0,y0); bsplit(acc[2*kg+1][3],x1,y1);
        ahi[3]=packb2(x0,x1); alo[3]=packb2(y0,y1);
      }
#pragma unroll
      for (int p=0;p<8;p++){
        uint32_t rowoff = (p*16 + ((lane>>4)&1)*8 + (lane&7))*VROWB
                        + (kg*16 + (((lane>>3)&1)<<3))*2;
        uint32_t bh[4], bl[4];
        ldsm_x4(bh, sb + OFF_V  + rowoff);
        ldsm_x4(bl, sb + OFF_VL + rowoff);
        mma16816(o[2*p+0], ahi, &bh[0]);
        mma16816(o[2*p+0], alo, &bh[0]);
        mma16816(o[2*p+0], ahi, &bl[0]);
        mma16816(o[2*p+1], ahi, &bh[2]);
        mma16816(o[2*p+1], alo, &bh[2]);
        mma16816(o[2*p+1], ahi, &bl[2]);
      }
    }
    // next iteration's kc=0 wait+sync protects V smem before overwrite
  }

  // ---- epilogue: normalize + [hi|lo|hi] pack ----
  const float inv0 = 1.f/l0, inv1 = 1.f/l1;
  const int qrow0 = s0 + wid*16 + (lane>>2);
  const ll rb0 = ((ll)(b*1024 + qrow0))*6144 + h*128;
  const ll rb1 = rb0 + 8LL*6144;
#pragma unroll
  for (int ni=0;ni<16;ni++){
    int col = ni*8 + (lane&3)*2;
    {
      float v0 = o[ni][0]*inv0, v1 = o[ni][1]*inv0;
      __nv_bfloat16 h0,l0b,h1,l1b; bsplit(v0,h0,l0b); bsplit(v1,h1,l1b);
      __nv_bfloat16* d = aop + rb0 + col;
      *(__nv_bfloat162*)(d)      = __nv_bfloat162(h0,h1);
      *(__nv_bfloat162*)(d+2048) = __nv_bfloat162(l0b,l1b);
      *(__nv_bfloat162*)(d+4096) = __nv_bfloat162(h0,h1);
    }
    {
      float v0 = o[ni][2]*inv1, v1 = o[ni][3]*inv1;
      __nv_bfloat16 h0,l0b,h1,l1b; bsplit(v0,h0,l0b); bsplit(v1,h1,l1b);
      __nv_bfloat16* d = aop + rb1 + col;
      *(__nv_bfloat162*)(d)      = __nv_bfloat162(h0,h1);
      *(__nv_bfloat162*)(d+2048) = __nv_bfloat162(l0b,l1b);
      *(__nv_bfloat162*)(d+4096) = __nv_bfloat162(h0,h1);
    }
  }
}

// ---------------- RMSNorm + RoPE + split-pack q/k (v handled separately) ----------------
__global__ __launch_bounds__(256)
void norm_rope_pack(const float* __restrict__ cl, const float* __restrict__ cg,
                    const float* __restrict__ cosT, const float* __restrict__ sinT,
                    const float* __restrict__ gql, const float* __restrict__ gkl,
                    const float* __restrict__ gqg, const float* __restrict__ gkg,
                    __nv_bfloat16* __restrict__ qp, __nv_bfloat16* __restrict__ kp)
{
  const int bs = blockIdx.x;
  const int b = bs >> 10, s = bs & 1023;
  const int t = threadIdx.x;
  const float* rl = cl + (ll)bs*1536;
  const float* rg = cg + (ll)bs*1536;

  float sql=0.f, sqg=0.f;
#pragma unroll
  for (int i=t;i<1024;i+=256){ float x=rl[i]; sql+=x*x; float y=rg[i]; sqg+=y*y; }
  float xk=rl[1024+t], yk=rg[1024+t];
  float skl = xk*xk, skg = yk*yk;

  __shared__ float4 red[8];
  float4 v4 = make_float4(sql,sqg,skl,skg);
#pragma unroll
  for (int off=16;off;off>>=1){
    v4.x += __shfl_xor_sync(0xffffffffu, v4.x, off);
    v4.y += __shfl_xor_sync(0xffffffffu, v4.y, off);
    v4.z += __shfl_xor_sync(0xffffffffu, v4.z, off);
    v4.w += __shfl_xor_sync(0xffffffffu, v4.w, off);
  }
  const int w = t>>5, l = t&31;
  if (!l) red[w]=v4;
  __syncthreads();
  if (t==0){
    float4 a = red[0];
    for (int i=1;i<8;i++){ a.x+=red[i].x; a.y+=red[i].y; a.z+=red[i].z; a.w+=red[i].w; }
    red[0]=a;
  }
  __syncthreads();
  float4 tot = red[0];
  const float rql = rsqrtf(tot.x*(1.f/1024.f)+1e-5f) * 0.125f;  // fold /8 into q
  const float rqg = rsqrtf(tot.y*(1.f/1024.f)+1e-5f) * 0.125f;
  const float rkl = rsqrtf(tot.z*(1.f/256.f)+1e-5f);
  const float rkg = rsqrtf(tot.w*(1.f/256.f)+1e-5f);

  // q rows: [(b*16+h)*1024+s] x 384 in [hi|lo|hi]
#pragma unroll
  for (int pp=t; pp<512; pp+=256){
    int h = pp>>5, p = pp&31;
    float c = cosT[s*32+p], sn = sinT[s*32+p];
    int d0 = h*64 + 2*p;
    ll base = (((ll)(b*16+h))*1024 + s)*384;
    float x0 = rl[d0]*rql*gql[d0];
    float x1 = rl[d0+1]*rql*gql[d0+1];
    float y0 = rg[d0]*rqg*gqg[d0];
    float y1 = rg[d0+1]*rqg*gqg[d0+1];
    float o0 = x0*c - x1*sn, o1 = x0*sn + x1*c;
    float o2 = y0*c - y1*sn, o3 = y0*sn + y1*c;
    __nv_bfloat16 h0,l0,h1,l1,h2,l2,h3,l3;
    bsplit(o0,h0,l0); bsplit(o1,h1,l1); bsplit(o2,h2,l2); bsplit(o3,h3,l3);
    *(__nv_bfloat162*)(qp+base+2*p)        = __nv_bfloat162(h0,h1);
    *(__nv_bfloat162*)(qp+base+128+2*p)    = __nv_bfloat162(l0,l1);
    *(__nv_bfloat162*)(qp+base+256+2*p)    = __nv_bfloat162(h0,h1);
    *(__nv_bfloat162*)(qp+base+64+2*p)     = __nv_bfloat162(h2,h3);
    *(__nv_bfloat162*)(qp+base+128+64+2*p) = __nv_bfloat162(l2,l3);
    *(__nv_bfloat162*)(qp+base+256+64+2*p) = __nv_bfloat162(h2,h3);
  }
  // k rows: [(b*4+kh)*1024+s] x 384 in [hi|hi|lo]
  if (t < 128){
    int kh = t>>5, p = t&31;
    float c = cosT[s*32+p], sn = sinT[s*32+p];
    int gd = kh*64 + 2*p;
    ll base = (((ll)(b*4+kh))*1024 + s)*384;
    float x0 = rl[1024+gd]*rkl*gkl[gd];
    float x1 = rl[1024+gd+1]*rkl*gkl[gd+1];
    float y0 = rg[1024+gd]*rkg*gkg[gd];
    float y1 = rg[1024+gd+1]*rkg*gkg[gd+1];
    float o0 = x0*c - x1*sn, o1 = x0*sn + x1*c;
    float o2 = y0*c - y1*sn, o3 = y0*sn + y1*c;
    __nv_bfloat16 h0,l0,h1,l1,h2,l2,h3,l3;
    bsplit(o0,h0,l0); bsplit(o1,h1,l1); bsplit(o2,h2,l2); bsplit(o3,h3,l3);
    *(__nv_bfloat162*)(kp+base+2*p)        = __nv_bfloat162(h0,h1);
    *(__nv_bfloat162*)(kp+base+128+2*p)    = __nv_bfloat162(h0,h1);
    *(__nv_bfloat162*)(kp+base+256+2*p)    = __nv_bfloat162(l0,l1);
    *(__nv_bfloat162*)(kp+base+64+2*p)     = __nv_bfloat162(h2,h3);
    *(__nv_bfloat162*)(kp+base+128+64+2*p) = __nv_bfloat162(h2,h3);
    *(__nv_bfloat162*)(kp+base+256+64+2*p) = __nv_bfloat162(l2,l3);
  }
}

// ---------------- V transpose: comb v-section -> vT pack, coalesced both sides ----------------
// grid (32 s-tiles, 8 vcol-tiles, 4 = b*2+strm), block 256 (8 rows x 32)
__global__ __launch_bounds__(256)
void v_transpose(const float* __restrict__ comb, __nv_bfloat16* __restrict__ vp)
{
  const int s0 = blockIdx.x*32;
  const int c0 = blockIdx.y*32;
  const int b  = blockIdx.z>>1, strm = blockIdx.z&1;
  __shared__ float t[32][33];
  const int tx = threadIdx.x&31, ty = threadIdx.x>>5;
  const float* base = comb + (ll)strm*2048*1536;
#pragma unroll
  for (int r=0;r<32;r+=8)
    t[ty+r][tx] = base[(ll)(b*1024 + s0+ty+r)*1536 + 1280 + c0 + tx];
  __syncthreads();
#pragma unroll
  for (int r=0;r<32;r+=8){
    int v = c0 + ty + r;
    int kh = v>>6, d = v&63;
    ll row = (ll)(b*4+kh)*128 + strm*64 + d;
    float val = t[tx][ty+r];
    __nv_bfloat16 hi,lo; bsplit(val,hi,lo);
    __nv_bfloat16* o = vp + row*3072 + s0;
    o[tx] = hi; o[1024+tx] = hi; o[2048+tx] = lo;
  }
}

// ---------------- final RMSNorm -> d_out ----------------
__global__ __launch_bounds__(256)
void rmsnorm_out(const float* __restrict__ y, const float* __restrict__ glc,
                 const float* __restrict__ ggc, float* __restrict__ out)
{
  const int row = blockIdx.x;
  const float* g = (row < 2048) ? glc : ggc;
  const float* r = y + (ll)row*1024;
  float* o = out + (ll)row*1024;
  const int t = threadIdx.x;
  float4 v = ((const float4*)r)[t];
  float ss = v.x*v.x + v.y*v.y + v.z*v.z + v.w*v.w;
  __shared__ float sm[8];
#pragma unroll
  for (int o2=16;o2;o2>>=1) ss += __shfl_xor_sync(0xffffffffu,ss,o2);
  const int w=t>>5, l=t&31;
  if (!l) sm[w]=ss;
  __syncthreads();
  ss = sm[0]+sm[1]+sm[2]+sm[3]+sm[4]+sm[5]+sm[6]+sm[7];
  const float rsq = rsqrtf(ss*(1.f/1024.f)+1e-5f);
  float4 gv = ((const float4*)g)[t];
  float4 ov = make_float4(v.x*rsq*gv.x, v.y*rsq*gv.y, v.z*rsq*gv.z, v.w*rsq*gv.w);
  ((float4*)o)[t]=ov;
}

// ---------------- launch ----------------
extern "C" void kernel_launch(void* const* d_in, const int* in_sizes, int n_in,
                              void* d_out, int out_size)
{
  (void)in_sizes; (void)n_in; (void)out_size;
  const float* local_c  = (const float*)d_in[0];
  const float* global_c = (const float*)d_in[1];
  const float* fcos     = (const float*)d_in[2];
  const float* fsin     = (const float*)d_in[3];
  const float* W_lc     = (const float*)d_in[4];
  const float* W_gc     = (const float*)d_in[5];
  const float* g_q_lc   = (const float*)d_in[6];
  const float* g_k_lc   = (const float*)d_in[7];
  const float* g_q_gc   = (const float*)d_in[8];
  const float* g_k_gc   = (const float*)d_in[9];
  const float* W_local  = (const float*)d_in[10];
  const float* b_local  = (const float*)d_in[11];
  const float* g_lc_out = (const float*)d_in[12];
  const float* W_global = (const float*)d_in[13];
  const float* b_global = (const float*)d_in[14];
  const float* g_gc_out = (const float*)d_in[15];

  __nv_bfloat16 *xp,*wq,*wp,*qp,*kp,*vtp,*aop;
  float *comb,*yy;
  cudaGetSymbolAddress((void**)&xp,  g_x_pack);
  cudaGetSymbolAddress((void**)&wq,  g_wqkv_pack);
  cudaGetSymbolAddress((void**)&wp,  g_wpr_pack);
  cudaGetSymbolAddress((void**)&comb, g_comb);
  cudaGetSymbolAddress((void**)&qp,  g_q_pack);
  cudaGetSymbolAddress((void**)&kp,  g_k_pack);
  cudaGetSymbolAddress((void**)&vtp, g_vT_pack);
  cudaGetSymbolAddress((void**)&aop, g_ao_pack);
  cudaGetSymbolAddress((void**)&yy,  g_yy);

  const int SMEMSZ = 3*STG;  // 110592
  static int attr_done = 0;
  if (!attr_done){
    cudaFuncSetAttribute(gemm_mma<false>, cudaFuncAttributeMaxDynamicSharedMemorySize, SMEMSZ);
    cudaFuncSetAttribute(gemm_mma<true>,  cudaFuncAttributeMaxDynamicSharedMemorySize, SMEMSZ);
    cudaFuncSetAttribute(flash_attn, cudaFuncAttributeMaxDynamicSharedMemorySize, FSMEM);
    attr_done = 1;
  }

  // 0) all operand packs in one launch
  packAll<<<5632,256>>>(local_c, global_c, W_lc, W_gc, W_local, W_global, xp, wq, wp);

  // 1) QKV projections, batched z=2  (M=2048,N=1536,K'=3072)
  gemm_mma<false><<<dim3(12,16,2),256,SMEMSZ>>>(xp, wq, comb, nullptr, nullptr,
     3072, 3072,3072,1536, 2048LL*3072, 1536LL*3072, 2048LL*1536, 1.f);

  // 2) rmsnorm + rope + split-pack q/k;  V via coalesced transpose
  norm_rope_pack<<<2048,256>>>(comb, comb + 2048u*1536u, fcos, fsin,
                               g_q_lc, g_k_lc, g_q_gc, g_k_gc, qp, kp);
  v_transpose<<<dim3(32,8,4),256>>>(comb, vtp);

  // 3) fused attention -> aop [hi|lo|hi]
  flash_attn<<<dim3(8,32),256,FSMEM>>>(qp, kp, vtp, aop);

  // 4) merged output projections + bias  (M=2048,N=2048,K'=6144, split-N epilogue)
  gemm_mma<true><<<dim3(16,16,1),256,SMEMSZ>>>(aop, wp, yy, b_local, b_global,
     6144, 6144,6144,1024, 0,0,0, 1.f);

  // 5) final rmsnorm -> d_out
  rmsnorm_out<<<4096,256>>>(yy, g_lc_out, g_gc_out, (float*)d_out);
}

// round 10
// speedup vs baseline: 2.6481x; 1.0167x over previous
#include <cuda_runtime.h>
#include <cuda_bf16.h>
#include <cstdint>

// B=2, S=1024, D=1024, H=16, KVH=4, HD=64, TOT=1536
// GEMMs on mma.sync bf16; fp32-level accuracy via 2-term split with a 3-term
// virtual-K loop: physical operands stored [hi|lo] (2K); GEMM iterates
// term t=0,1,2 with A cols {hi,lo,hi} x B cols {hi,hi,lo}.
// Flash-fused attention; 3-stage cp.async pipelines; base-2 softmax.

typedef unsigned long long ull;
typedef long long ll;
#define DEVFN static __device__ __forceinline__

// ---------------- PTX helpers ----------------
DEVFN uint32_t smem_u32(const void* p){
  uint32_t a; asm("{ .reg .u64 t; cvta.to.shared.u64 t, %1; cvt.u32.u64 %0, t; }":"=r"(a):"l"(p)); return a;
}
DEVFN void ldsm_x4(uint32_t* r, uint32_t addr){
  asm volatile("ldmatrix.sync.aligned.m8n8.x4.shared.b16 {%0,%1,%2,%3}, [%4];"
    : "=r"(r[0]),"=r"(r[1]),"=r"(r[2]),"=r"(r[3]) : "r"(addr));
}
DEVFN void mma16816(float* c, const uint32_t* a, const uint32_t* b){
  asm volatile("mma.sync.aligned.m16n8k16.row.col.f32.bf16.bf16.f32 "
    "{%0,%1,%2,%3}, {%4,%5,%6,%7}, {%8,%9}, {%0,%1,%2,%3};"
    : "+f"(c[0]),"+f"(c[1]),"+f"(c[2]),"+f"(c[3])
    : "r"(a[0]),"r"(a[1]),"r"(a[2]),"r"(a[3]), "r"(b[0]),"r"(b[1]));
}
DEVFN void cp_async16(uint32_t dst, const void* src){
  asm volatile("cp.async.cg.shared.global [%0], [%1], 16;" :: "r"(dst), "l"(src));
}
#define CP_COMMIT() asm volatile("cp.async.commit_group;" ::: "memory")
template<int N> DEVFN void cp_waitg(){ asm volatile("cp.async.wait_group %0;"::"n"(N):"memory"); }

DEVFN void bsplit(float x, __nv_bfloat16 &hi, __nv_bfloat16 &lo){
  hi = __float2bfloat16(x);
  lo = __float2bfloat16(x - __bfloat162float(hi));
}
DEVFN uint32_t packb2(__nv_bfloat16 a, __nv_bfloat16 b){
  __nv_bfloat162 t(a, b); return *(uint32_t*)&t;
}

// ---------------- scratch (device globals) ----------------
__device__ __align__(128) __nv_bfloat16 g_x_pack   [2u*2048u*2048u];  // [lc|gc], rows [hi|lo]
__device__ __align__(128) __nv_bfloat16 g_wqkv_pack[2u*1536u*2048u];
__device__ __align__(128) __nv_bfloat16 g_wpr_pack [2u*1024u*4096u];
__device__ __align__(128) float g_comb[2u*2048u*1536u];
__device__ __align__(128) __nv_bfloat16 g_q_pack [32u*1024u*256u];    // q*log2e/8
__device__ __align__(128) __nv_bfloat16 g_k_pack [8u*1024u*256u];
__device__ __align__(128) __nv_bfloat16 g_vT_pack[8u*128u*2048u];     // V^T rows [hi(1024)|lo(1024)]
__device__ __align__(128) __nv_bfloat16 g_ao_pack[2048u*4096u];       // attn-out rows [hi|lo]
__device__ __align__(128) float g_yy[4096u*1024u];

// ---------------- merged pack: f32 [R x K] -> bf16 [R x 2K] [hi|lo] ----------------
// blocks: [0,1024) xl | [1024,2048) xg | [2048,2816) wlc | [2816,3584) wgc
//         [3584,4608) wlo | [4608,5632) wgo
__global__ __launch_bounds__(256)
void packAll(const float* __restrict__ xl, const float* __restrict__ xg,
             const float* __restrict__ wlc, const float* __restrict__ wgc,
             const float* __restrict__ wlo, const float* __restrict__ wgo,
             __nv_bfloat16* __restrict__ xp, __nv_bfloat16* __restrict__ wq,
             __nv_bfloat16* __restrict__ wp)
{
  int bx = blockIdx.x;
  const float* src; __nv_bfloat16* dst; int K;
  if (bx < 2048){
    K = 1024;
    if (bx < 1024){ src = xl; dst = xp; }
    else { src = xg; dst = xp + 2048u*2048u; bx -= 1024; }
  } else if (bx < 3584){
    K = 1024; bx -= 2048;
    if (bx < 768){ src = wlc; dst = wq; }
    else { src = wgc; dst = wq + 1536u*2048u; bx -= 768; }
  } else {
    K = 2048; bx -= 3584;
    if (bx < 1024){ src = wlo; dst = wp; }
    else { src = wgo; dst = wp + 1024u*4096u; bx -= 1024; }
  }
  int idx = (bx*256 + threadIdx.x)*8;
  float4 v0 = *(const float4*)(src + idx);
  float4 v1 = *(const float4*)(src + idx + 4);
  int r = idx / K, k = idx - r*K;
  __nv_bfloat16* d = dst + (ll)r*2*K + k;
  float vv[8] = {v0.x,v0.y,v0.z,v0.w,v1.x,v1.y,v1.z,v1.w};
  uint32_t hw[4], lw[4];
#pragma unroll
  for (int i=0;i<4;i++){
    __nv_bfloat16 h0,l0,h1,l1;
    bsplit(vv[2*i],h0,l0); bsplit(vv[2*i+1],h1,l1);
    hw[i] = packb2(h0,h1); lw[i] = packb2(l0,l1);
  }
  *(uint4*)(d)     = make_uint4(hw[0],hw[1],hw[2],hw[3]);
  *(uint4*)(d + K) = make_uint4(lw[0],lw[1],lw[2],lw[3]);
}

// ---------------- mma.sync GEMM: 3-term virtual K over [hi|lo] operands ----------------
#define ROWB2 144     // 128B data + 16B pad
#define STG 36864     // (128+128)*144 per stage

template<bool SPLIT_N>
__global__ __launch_bounds__(256, 2)
void gemm_mma(const __nv_bfloat16* __restrict__ A, const __nv_bfloat16* __restrict__ B,
              float* __restrict__ Cf,
              const float* __restrict__ bias0, const float* __restrict__ bias1,
              int Kreal, int lgn1, int lda, int ldb, int ldc,
              ll sA, ll sB, ll sC, float cscale)
{
  extern __shared__ char smem[];
  const uint32_t sb = smem_u32(smem);
  const int tid = threadIdx.x, wid = tid>>5, lane = tid&31;
  const int z = blockIdx.z;
  const int m0 = blockIdx.y*128, n0 = blockIdx.x*128;
  A += z*sA + (ll)m0*lda;
  B += z*sB + (ll)n0*ldb;
  Cf += z*sC;

  const int wm = wid>>1, wn = wid&1;  // 4(M) x 2(N) warps: 32x64 per warp
  const int n1m = (1<<lgn1) - 1;

  float acc[2][8][4];
#pragma unroll
  for (int i=0;i<2;i++)
#pragma unroll
    for (int j=0;j<8;j++)
#pragma unroll
      for (int q=0;q<4;q++) acc[i][j][q]=0.f;

  const int nch = 3 << lgn1;

  auto loadStage = [&](int c, int s){
    int t = c >> lgn1, r = c & n1m;
    int acol = ((t==1) ? Kreal : 0) + r*64;
    int bcol = ((t==2) ? Kreal : 0) + r*64;
    const __nv_bfloat16* Ak = A + acol;
    const __nv_bfloat16* Bk = B + bcol;
    uint32_t abase = sb + s*STG;
    uint32_t bbase = abase + 18432;
#pragma unroll
    for (int i=0;i<4;i++){
      int f = tid + i*256;
      int rr = f>>3, q = f&7;
      cp_async16(abase + rr*ROWB2 + q*16, (const char*)(Ak + (ll)rr*lda) + q*16);
      cp_async16(bbase + rr*ROWB2 + q*16, (const char*)(Bk + (ll)rr*ldb) + q*16);
    }
  };

  loadStage(0, 0); CP_COMMIT();
  loadStage(1, 1); CP_COMMIT();

  for (int c=0; c<nch; c++){
    cp_waitg<1>();
    __syncthreads();
    if (c+2 < nch) loadStage(c+2, (c+2)%3);
    CP_COMMIT();

    const uint32_t abase = sb + (c%3)*STG;
    const uint32_t bbase = abase + 18432;
#pragma unroll
    for (int kk=0; kk<64; kk+=16){
      uint32_t a[2][4], b[4][4];
#pragma unroll
      for (int h=0; h<2; h++)
        ldsm_x4(a[h], abase + (wm*32 + h*16 + (lane&15))*ROWB2
                             + (kk + ((lane>>4)<<3))*2);
#pragma unroll
      for (int p=0; p<4; p++)
        ldsm_x4(b[p], bbase + (wn*64 + p*16 + ((lane>>4)&1)*8 + (lane&7))*ROWB2
                             + (kk + (((lane>>3)&1)<<3))*2);
#pragma unroll
      for (int mi=0; mi<2; mi++)
#pragma unroll
        for (int p=0; p<4; p++){
          mma16816(acc[mi][2*p+0], a[mi], &b[p][0]);
          mma16816(acc[mi][2*p+1], a[mi], &b[p][2]);
        }
    }
  }

#pragma unroll
  for (int mi=0; mi<2; mi++){
#pragma unroll
    for (int ni=0; ni<8; ni++){
      int mrow = m0 + wm*32 + mi*16 + (lane>>2);
      int ncol = n0 + wn*64 + ni*8 + (lane&3)*2;
#pragma unroll
      for (int hh=0; hh<2; hh++){
        int m = mrow + hh*8;
        float v0 = acc[mi][ni][2*hh+0]*cscale;
        float v1 = acc[mi][ni][2*hh+1]*cscale;
        if (SPLIT_N){
          int nl = ncol & 1023;
          const float* bs = (ncol >= 1024) ? bias1 : bias0;
          v0 += bs[nl]; v1 += bs[nl+1];
          float* dst = Cf + ((ncol >= 1024) ? 2097152LL : 0LL) + (ll)m*1024 + nl;
          *(float2*)dst = make_float2(v0,v1);
        } else {
          *(float2*)(Cf + (ll)m*ldc + ncol) = make_float2(v0,v1);
        }
      }
    }
  }
}

// ---------------- fused flash attention ----------------
// Q/K stored [hi|lo] (256 cols). Virtual 6 k-chunks of 64:
//   Q cols {0,64,128,192,0,64} (hi,lo,hi), K cols {0,64,0,64,128,192} (hi,hi,lo).
#define QROWB 528     // 512B + 16 pad
#define KROWB 144     // 128B + 16 pad
#define KSLOT 18432   // 128*144
#define VROWB 272     // 256B + 16 pad
#define OFF_K  67584                  // Q = 128*528
#define OFF_V  122880                 // OFF_K + 3*KSLOT
#define OFF_VL 157696                 // OFF_V + 128*VROWB
#define FSMEM  192512                 // OFF_VL + 128*VROWB

DEVFN void flash_issueK(uint32_t sb, const __nv_bfloat16* Kc, int kcol, int slot, int tid){
  uint32_t kb = sb + OFF_K + slot*KSLOT;
#pragma unroll
  for (int i=0;i<4;i++){
    int f = tid + i*256;
    int r = f>>3, q = f&7;
    cp_async16(kb + r*KROWB + q*16, (const char*)(Kc + (ll)r*256 + kcol) + q*16);
  }
}
// part in 0..4: rows [part*26, min(128, part*26+26)) of hi and lo tiles
DEVFN void flash_issueV(uint32_t sb, const __nv_bfloat16* Vc, int part, int tid){
  int r0 = part*26;
  int nr = 128 - r0; if (nr > 26) nr = 26;
  for (int f = tid; f < nr*32; f += 256){
    int r = r0 + (f>>5), c = f&31;
    const char* base = (const char*)(Vc + (ll)r*2048);
    if (c < 16) cp_async16(sb + OFF_V  + r*VROWB + c*16, base + c*16);
    else        cp_async16(sb + OFF_VL + r*VROWB + (c-16)*16, base + 2048 + (c-16)*16);
  }
}

__global__ __launch_bounds__(256, 1)
void flash_attn(const __nv_bfloat16* __restrict__ qp,
                const __nv_bfloat16* __restrict__ kp,
                const __nv_bfloat16* __restrict__ vtp,
                __nv_bfloat16* __restrict__ aop)
{
  extern __shared__ char smem[];
  const uint32_t sb = smem_u32(smem);
  const int tid = threadIdx.x, wid = tid>>5, lane = tid&31;
  const int z = blockIdx.y, b = z>>4, h = z&15;
  const int s0 = blockIdx.x*128;
  const __nv_bfloat16* Qb = qp + ((ll)z*1024 + s0)*256;
  const __nv_bfloat16* Kb = kp + (ll)(z>>2)*1024*256;
  const __nv_bfloat16* Vb = vtp + (ll)(z>>2)*128*2048;

  // Q tile (128 x 256 bf16 = 64KB)
#pragma unroll
  for (int i=0;i<16;i++){
    int f = tid + i*256;
    int r = f>>5, c = f&31;
    cp_async16(sb + r*QROWB + c*16, (const char*)(Qb + (ll)r*256) + c*16);
  }
  CP_COMMIT();
  // chunk 0: K chunks 0,1 (hi cols 0,64)
  flash_issueK(sb, Kb, 0,  0, tid); CP_COMMIT();
  flash_issueK(sb, Kb, 64, 1, tid); CP_COMMIT();

  float m0=-1e30f, m1=-1e30f, l0=0.f, l1=0.f;
  float o[16][4];
#pragma unroll
  for (int ni=0;ni<16;ni++){ o[ni][0]=0.f;o[ni][1]=0.f;o[ni][2]=0.f;o[ni][3]=0.f; }

  const int QCOL[6] = {0,64,128,192,0,64};
  const int KCOL[6] = {0,64,0,64,128,192};

#pragma unroll 1
  for (int nc=0; nc<8; nc++){
    const __nv_bfloat16* Kc = Kb + (ll)(nc*128)*256;
    const __nv_bfloat16* Vc = Vb + nc*128;

    float acc[16][4];
#pragma unroll
    for (int ni=0;ni<16;ni++){ acc[ni][0]=0.f;acc[ni][1]=0.f;acc[ni][2]=0.f;acc[ni][3]=0.f; }

#pragma unroll
    for (int kc=0; kc<6; kc++){
      cp_waitg<1>();            // drains group carrying K(kc)
      __syncthreads();
      if (kc < 4){
        flash_issueK(sb, Kc, KCOL[kc+2], (kc+2)%3, tid);
        flash_issueV(sb, Vc, kc, tid);
        CP_COMMIT();
      } else if (kc == 4){
        flash_issueV(sb, Vc, 4, tid);
        CP_COMMIT();
      }
      const uint32_t kb = sb + OFF_K + (kc%3)*KSLOT;
      const int qc = QCOL[kc];
#pragma unroll
      for (int kk=0; kk<64; kk+=16){
        uint32_t a[4];
        ldsm_x4(a, sb + (wid*16 + (lane&15))*QROWB + (qc + kk + ((lane>>4)<<3))*2);
        uint32_t bf[8][4];
#pragma unroll
        for (int p=0;p<8;p++)
          ldsm_x4(bf[p], kb + (p*16 + ((lane>>4)&1)*8 + (lane&7))*KROWB
                            + (kk + (((lane>>3)&1)<<3))*2);
#pragma unroll
        for (int p=0;p<8;p++){
          mma16816(acc[2*p+0], a, &bf[p][0]);
          mma16816(acc[2*p+1], a, &bf[p][2]);
        }
      }
    }

    __syncthreads();            // all warps done with K smem
    if (nc < 7){                // prefetch next chunk's K0/K1 behind softmax+PV
      const __nv_bfloat16* Kn = Kb + (ll)((nc+1)*128)*256;
      flash_issueK(sb, Kn, 0,  0, tid); CP_COMMIT();
      flash_issueK(sb, Kn, 64, 1, tid); CP_COMMIT();
      cp_waitg<2>();            // drains trailing V group
    } else {
      cp_waitg<0>();
    }
    __syncthreads();            // V visible to all

    // ---- online softmax (base-2; log2e folded into q scale) ----
    float cm0=-1e30f, cm1=-1e30f;
#pragma unroll
    for (int ni=0;ni<16;ni++){
      cm0 = fmaxf(cm0, fmaxf(acc[ni][0], acc[ni][1]));
      cm1 = fmaxf(cm1, fmaxf(acc[ni][2], acc[ni][3]));
    }
    cm0 = fmaxf(cm0, __shfl_xor_sync(0xffffffffu, cm0, 1));
    cm0 = fmaxf(cm0, __shfl_xor_sync(0xffffffffu, cm0, 2));
    cm1 = fmaxf(cm1, __shfl_xor_sync(0xffffffffu, cm1, 1));
    cm1 = fmaxf(cm1, __shfl_xor_sync(0xffffffffu, cm1, 2));
    float mn0 = fmaxf(m0, cm0), mn1 = fmaxf(m1, cm1);
    float sc0 = exp2f(m0 - mn0), sc1 = exp2f(m1 - mn1);
    m0 = mn0; m1 = mn1;
    float rs0=0.f, rs1=0.f;
#pragma unroll
    for (int ni=0;ni<16;ni++){
      acc[ni][0]=exp2f(acc[ni][0]-m0); acc[ni][1]=exp2f(acc[ni][1]-m0);
      acc[ni][2]=exp2f(acc[ni][2]-m1); acc[ni][3]=exp2f(acc[ni][3]-m1);
      rs0 += acc[ni][0]+acc[ni][1];
      rs1 += acc[ni][2]+acc[ni][3];
    }
    rs0 += __shfl_xor_sync(0xffffffffu, rs0, 1);
    rs0 += __shfl_xor_sync(0xffffffffu, rs0, 2);
    rs1 += __shfl_xor_sync(0xffffffffu, rs1, 1);
    rs1 += __shfl_xor_sync(0xffffffffu, rs1, 2);
    l0 = l0*sc0 + rs0;
    l1 = l1*sc1 + rs1;
#pragma unroll
    for (int ni=0;ni<16;ni++){
      o[ni][0]*=sc0; o[ni][1]*=sc0; o[ni][2]*=sc1; o[ni][3]*=sc1;
    }

    // ---- PV: Phi*Vhi + Plo*Vhi + Phi*Vlo ----
#pragma unroll
    for (int kg=0; kg<8; kg++){
      uint32_t ahi[4], alo[4];
      {
        __nv_bfloat16 x0,y0,x1,y1;
        bsplit(acc[2*kg][0],x0,y0);   bsplit(acc[2*kg][1],x1,y1);
        ahi[0]=packb2(x0,x1); alo[0]=packb2(y0,y1);
        bsplit(acc[2*kg][2],x0,y0);   bsplit(acc[2*kg][3],x1,y1);
        ahi[1]=packb2(x0,x1); alo[1]=packb2(y0,y1);
        bsplit(acc[2*kg+1][0],x0,y0); bsplit(acc[2*kg+1][1],x1,y1);
        ahi[2]=packb2(x0,x1); alo[2]=packb2(y0,y1);
        bsplit(acc[2*kg+1][2],x0,y0); bsplit(acc[2*kg+1][3],x1,y1);
        ahi[3]=packb2(x0,x1); alo[3]=packb2(y0,y1);
      }
#pragma unroll
      for (int p=0;p<8;p++){
        uint32_t rowoff = (p*16 + ((lane>>4)&1)*8 + (lane&7))*VROWB
                        + (kg*16 + (((lane>>3)&1)<<3))*2;
        uint32_t bh[4], bl[4];
        ldsm_x4(bh, sb + OFF_V  + rowoff);
        ldsm_x4(bl, sb + OFF_VL + rowoff);
        mma16816(o[2*p+0], ahi, &bh[0]);
        mma16816(o[2*p+0], alo, &bh[0]);
        mma16816(o[2*p+0], ahi, &bl[0]);
        mma16816(o[2*p+1], ahi, &bh[2]);
        mma16816(o[2*p+1], alo, &bh[2]);
        mma16816(o[2*p+1], ahi, &bl[2]);
      }
    }
    // next iteration's kc=0 wait+sync protects V smem before overwrite
  }

  // ---- epilogue: normalize + [hi|lo] pack ----
  const float inv0 = 1.f/l0, inv1 = 1.f/l1;
  const int qrow0 = s0 + wid*16 + (lane>>2);
  const ll rb0 = ((ll)(b*1024 + qrow0))*4096 + h*128;
  const ll rb1 = rb0 + 8LL*4096;
#pragma unroll
  for (int ni=0;ni<16;ni++){
    int col = ni*8 + (lane&3)*2;
    {
      float v0 = o[ni][0]*inv0, v1 = o[ni][1]*inv0;
      __nv_bfloat16 h0,l0b,h1,l1b; bsplit(v0,h0,l0b); bsplit(v1,h1,l1b);
      __nv_bfloat16* d = aop + rb0 + col;
      *(__nv_bfloat162*)(d)      = __nv_bfloat162(h0,h1);
      *(__nv_bfloat162*)(d+2048) = __nv_bfloat162(l0b,l1b);
    }
    {
      float v0 = o[ni][2]*inv1, v1 = o[ni][3]*inv1;
      __nv_bfloat16 h0,l0b,h1,l1b; bsplit(v0,h0,l0b); bsplit(v1,h1,l1b);
      __nv_bfloat16* d = aop + rb1 + col;
      *(__nv_bfloat162*)(d)      = __nv_bfloat162(h0,h1);
      *(__nv_bfloat162*)(d+2048) = __nv_bfloat162(l0b,l1b);
    }
  }
}

// ---------------- merged prep: RMSNorm+RoPE pack (blocks<2048) | V transpose ----------------
__global__ __launch_bounds__(256)
void prep_qkv(const float* __restrict__ comb,
              const float* __restrict__ cosT, const float* __restrict__ sinT,
              const float* __restrict__ gql, const float* __restrict__ gkl,
              const float* __restrict__ gqg, const float* __restrict__ gkg,
              __nv_bfloat16* __restrict__ qp, __nv_bfloat16* __restrict__ kp,
              __nv_bfloat16* __restrict__ vp)
{
  __shared__ float shbuf[32*33];
  const int t = threadIdx.x;

  if (blockIdx.x >= 2048){
    // ---- V transpose part: 1024 blocks -> (32 s-tiles, 8 ctile, 4 z) ----
    int b2 = blockIdx.x - 2048;
    const int s0 = (b2 & 31)*32;
    const int c0 = ((b2>>5)&7)*32;
    const int zz = b2>>8;
    const int b = zz>>1, strm = zz&1;
    float (*tt)[33] = (float(*)[33])shbuf;
    const int tx = t&31, ty = t>>5;
    const float* base = comb + (ll)strm*2048*1536;
#pragma unroll
    for (int r=0;r<32;r+=8)
      tt[ty+r][tx] = base[(ll)(b*1024 + s0+ty+r)*1536 + 1280 + c0 + tx];
    __syncthreads();
#pragma unroll
    for (int r=0;r<32;r+=8){
      int v = c0 + ty + r;
      int kh = v>>6, d = v&63;
      ll row = (ll)(b*4+kh)*128 + strm*64 + d;
      float val = tt[tx][ty+r];
      __nv_bfloat16 hi,lo; bsplit(val,hi,lo);
      __nv_bfloat16* o = vp + row*2048 + s0;
      o[tx] = hi; o[1024+tx] = lo;
    }
    return;
  }

  // ---- norm+rope part ----
  const int bs = blockIdx.x;
  const int b = bs >> 10, s = bs & 1023;
  const float* rl = comb + (ll)bs*1536;
  const float* rg = rl + (ll)2048*1536;

  float sql=0.f, sqg=0.f;
#pragma unroll
  for (int i=t;i<1024;i+=256){ float x=rl[i]; sql+=x*x; float y=rg[i]; sqg+=y*y; }
  float xk=rl[1024+t], yk=rg[1024+t];
  float skl = xk*xk, skg = yk*yk;

  float4* red = (float4*)shbuf;
  float4 v4 = make_float4(sql,sqg,skl,skg);
#pragma unroll
  for (int off=16;off;off>>=1){
    v4.x += __shfl_xor_sync(0xffffffffu, v4.x, off);
    v4.y += __shfl_xor_sync(0xffffffffu, v4.y, off);
    v4.z += __shfl_xor_sync(0xffffffffu, v4.z, off);
    v4.w += __shfl_xor_sync(0xffffffffu, v4.w, off);
  }
  const int w = t>>5, l = t&31;
  if (!l) red[w]=v4;
  __syncthreads();
  if (t==0){
    float4 a = red[0];
    for (int i=1;i<8;i++){ a.x+=red[i].x; a.y+=red[i].y; a.z+=red[i].z; a.w+=red[i].w; }
    red[0]=a;
  }
  __syncthreads();
  float4 tot = red[0];
  const float QF = 0.125f * 1.4426950408889634f;   // /8 and log2e folded into q
  const float rql = rsqrtf(tot.x*(1.f/1024.f)+1e-5f) * QF;
  const float rqg = rsqrtf(tot.y*(1.f/1024.f)+1e-5f) * QF;
  const float rkl = rsqrtf(tot.z*(1.f/256.f)+1e-5f);
  const float rkg = rsqrtf(tot.w*(1.f/256.f)+1e-5f);

  // q rows: [(b*16+h)*1024+s] x 256 [hi(128)|lo(128)]
#pragma unroll
  for (int pp=t; pp<512; pp+=256){
    int h = pp>>5, p = pp&31;
    float c = cosT[s*32+p], sn = sinT[s*32+p];
    int d0 = h*64 + 2*p;
    ll base = (((ll)(b*16+h))*1024 + s)*256;
    float x0 = rl[d0]*rql*gql[d0];
    float x1 = rl[d0+1]*rql*gql[d0+1];
    float y0 = rg[d0]*rqg*gqg[d0];
    float y1 = rg[d0+1]*rqg*gqg[d0+1];
    float o0 = x0*c - x1*sn, o1 = x0*sn + x1*c;
    float o2 = y0*c - y1*sn, o3 = y0*sn + y1*c;
    __nv_bfloat16 h0,l0,h1,l1,h2,l2,h3,l3;
    bsplit(o0,h0,l0); bsplit(o1,h1,l1); bsplit(o2,h2,l2); bsplit(o3,h3,l3);
    *(__nv_bfloat162*)(qp+base+2*p)        = __nv_bfloat162(h0,h1);
    *(__nv_bfloat162*)(qp+base+64+2*p)     = __nv_bfloat162(h2,h3);
    *(__nv_bfloat162*)(qp+base+128+2*p)    = __nv_bfloat162(l0,l1);
    *(__nv_bfloat162*)(qp+base+128+64+2*p) = __nv_bfloat162(l2,l3);
  }
  // k rows: [(b*4+kh)*1024+s] x 256 [hi|lo]
  if (t < 128){
    int kh = t>>5, p = t&31;
    float c = cosT[s*32+p], sn = sinT[s*32+p];
    int gd = kh*64 + 2*p;
    ll base = (((ll)(b*4+kh))*1024 + s)*256;
    float x0 = rl[1024+gd]*rkl*gkl[gd];
    float x1 = rl[1024+gd+1]*rkl*gkl[gd+1];
    float y0 = rg[1024+gd]*rkg*gkg[gd];
    float y1 = rg[1024+gd+1]*rkg*gkg[gd+1];
    float o0 = x0*c - x1*sn, o1 = x0*sn + x1*c;
    float o2 = y0*c - y1*sn, o3 = y0*sn + y1*c;
    __nv_bfloat16 h0,l0,h1,l1,h2,l2,h3,l3;
    bsplit(o0,h0,l0); bsplit(o1,h1,l1); bsplit(o2,h2,l2); bsplit(o3,h3,l3);
    *(__nv_bfloat162*)(kp+base+2*p)        = __nv_bfloat162(h0,h1);
    *(__nv_bfloat162*)(kp+base+64+2*p)     = __nv_bfloat162(h2,h3);
    *(__nv_bfloat162*)(kp+base+128+2*p)    = __nv_bfloat162(l0,l1);
    *(__nv_bfloat162*)(kp+base+128+64+2*p) = __nv_bfloat162(l2,l3);
  }
}

// ---------------- final RMSNorm -> d_out ----------------
__global__ __launch_bounds__(256)
void rmsnorm_out(const float* __restrict__ y, const float* __restrict__ glc,
                 const float* __restrict__ ggc, float* __restrict__ out)
{
  const int row = blockIdx.x;
  const float* g = (row < 2048) ? glc : ggc;
  const float* r = y + (ll)row*1024;
  float* o = out + (ll)row*1024;
  const int t = threadIdx.x;
  float4 v = ((const float4*)r)[t];
  float ss = v.x*v.x + v.y*v.y + v.z*v.z + v.w*v.w;
  __shared__ float sm[8];
#pragma unroll
  for (int o2=16;o2;o2>>=1) ss += __shfl_xor_sync(0xffffffffu,ss,o2);
  const int w=t>>5, l=t&31;
  if (!l) sm[w]=ss;
  __syncthreads();
  ss = sm[0]+sm[1]+sm[2]+sm[3]+sm[4]+sm[5]+sm[6]+sm[7];
  const float rsq = rsqrtf(ss*(1.f/1024.f)+1e-5f);
  float4 gv = ((const float4*)g)[t];
  float4 ov = make_float4(v.x*rsq*gv.x, v.y*rsq*gv.y, v.z*rsq*gv.z, v.w*rsq*gv.w);
  ((float4*)o)[t]=ov;
}

// ---------------- launch ----------------
extern "C" void kernel_launch(void* const* d_in, const int* in_sizes, int n_in,
                              void* d_out, int out_size)
{
  (void)in_sizes; (void)n_in; (void)out_size;
  const float* local_c  = (const float*)d_in[0];
  const float* global_c = (const float*)d_in[1];
  const float* fcos     = (const float*)d_in[2];
  const float* fsin     = (const float*)d_in[3];
  const float* W_lc     = (const float*)d_in[4];
  const float* W_gc     = (const float*)d_in[5];
  const float* g_q_lc   = (const float*)d_in[6];
  const float* g_k_lc   = (const float*)d_in[7];
  const float* g_q_gc   = (const float*)d_in[8];
  const float* g_k_gc   = (const float*)d_in[9];
  const float* W_local  = (const float*)d_in[10];
  const float* b_local  = (const float*)d_in[11];
  const float* g_lc_out = (const float*)d_in[12];
  const float* W_global = (const float*)d_in[13];
  const float* b_global = (const float*)d_in[14];
  const float* g_gc_out = (const float*)d_in[15];

  __nv_bfloat16 *xp,*wq,*wp,*qp,*kp,*vtp,*aop;
  float *comb,*yy;
  cudaGetSymbolAddress((void**)&xp,  g_x_pack);
  cudaGetSymbolAddress((void**)&wq,  g_wqkv_pack);
  cudaGetSymbolAddress((void**)&wp,  g_wpr_pack);
  cudaGetSymbolAddress((void**)&comb, g_comb);
  cudaGetSymbolAddress((void**)&qp,  g_q_pack);
  cudaGetSymbolAddress((void**)&kp,  g_k_pack);
  cudaGetSymbolAddress((void**)&vtp, g_vT_pack);
  cudaGetSymbolAddress((void**)&aop, g_ao_pack);
  cudaGetSymbolAddress((void**)&yy,  g_yy);

  const int SMEMSZ = 3*STG;  // 110592
  static int attr_done = 0;
  if (!attr_done){
    cudaFuncSetAttribute(gemm_mma<false>, cudaFuncAttributeMaxDynamicSharedMemorySize, SMEMSZ);
    cudaFuncSetAttribute(gemm_mma<true>,  cudaFuncAttributeMaxDynamicSharedMemorySize, SMEMSZ);
    cudaFuncSetAttribute(flash_attn, cudaFuncAttributeMaxDynamicSharedMemorySize, FSMEM);
    attr_done = 1;
  }

  // 0) all operand packs, [hi|lo] layout
  packAll<<<5632,256>>>(local_c, global_c, W_lc, W_gc, W_local, W_global, xp, wq, wp);

  // 1) QKV projections, batched z=2  (M=2048,N=1536, K=1024, lgn1=4)
  gemm_mma<false><<<dim3(12,16,2),256,SMEMSZ>>>(xp, wq, comb, nullptr, nullptr,
     1024, 4, 2048, 2048, 1536, 2048LL*2048, 1536LL*2048, 2048LL*1536, 1.f);

  // 2) merged rmsnorm+rope pack + V transpose
  prep_qkv<<<3072,256>>>(comb, fcos, fsin, g_q_lc, g_k_lc, g_q_gc, g_k_gc, qp, kp, vtp);

  // 3) fused attention -> aop [hi|lo]
  flash_attn<<<dim3(8,32),256,FSMEM>>>(qp, kp, vtp, aop);

  // 4) merged output projections + bias  (M=2048,N=2048, K=2048, lgn1=5, split-N)
  gemm_mma<true><<<dim3(16,16,1),256,SMEMSZ>>>(aop, wp, yy, b_local, b_global,
     2048, 5, 4096, 4096, 1024, 0,0,0, 1.f);

  // 5) final rmsnorm -> d_out
  rmsnorm_out<<<4096,256>>>(yy, g_lc_out, g_gc_out, (float*)d_out);
}

// round 11
// speedup vs baseline: 3.3648x; 1.2706x over previous
#include <cuda_runtime.h>
#include <cuda_bf16.h>
#include <cuda_fp16.h>
#include <cstdint>

// B=2, S=1024, D=1024, H=16, KVH=4, HD=64, TOT=1536
// QKV proj + attention: bf16 mma with 2-term split ([hi|lo] storage, 3-term
// virtual-K loop).  Output projection: single-term fp16 mma (rel_err ~4e-4).
// Flash-fused attention; 3-stage cp.async pipelines; base-2 softmax.

typedef unsigned long long ull;
typedef long long ll;
#define DEVFN static __device__ __forceinline__

// ---------------- PTX helpers ----------------
DEVFN uint32_t smem_u32(const void* p){
  uint32_t a; asm("{ .reg .u64 t; cvta.to.shared.u64 t, %1; cvt.u32.u64 %0, t; }":"=r"(a):"l"(p)); return a;
}
DEVFN void ldsm_x4(uint32_t* r, uint32_t addr){
  asm volatile("ldmatrix.sync.aligned.m8n8.x4.shared.b16 {%0,%1,%2,%3}, [%4];"
    : "=r"(r[0]),"=r"(r[1]),"=r"(r[2]),"=r"(r[3]) : "r"(addr));
}
DEVFN void mma16816(float* c, const uint32_t* a, const uint32_t* b){
  asm volatile("mma.sync.aligned.m16n8k16.row.col.f32.bf16.bf16.f32 "
    "{%0,%1,%2,%3}, {%4,%5,%6,%7}, {%8,%9}, {%0,%1,%2,%3};"
    : "+f"(c[0]),"+f"(c[1]),"+f"(c[2]),"+f"(c[3])
    : "r"(a[0]),"r"(a[1]),"r"(a[2]),"r"(a[3]), "r"(b[0]),"r"(b[1]));
}
DEVFN void mma16816h(float* c, const uint32_t* a, const uint32_t* b){
  asm volatile("mma.sync.aligned.m16n8k16.row.col.f32.f16.f16.f32 "
    "{%0,%1,%2,%3}, {%4,%5,%6,%7}, {%8,%9}, {%0,%1,%2,%3};"
    : "+f"(c[0]),"+f"(c[1]),"+f"(c[2]),"+f"(c[3])
    : "r"(a[0]),"r"(a[1]),"r"(a[2]),"r"(a[3]), "r"(b[0]),"r"(b[1]));
}
DEVFN void cp_async16(uint32_t dst, const void* src){
  asm volatile("cp.async.cg.shared.global [%0], [%1], 16;" :: "r"(dst), "l"(src));
}
#define CP_COMMIT() asm volatile("cp.async.commit_group;" ::: "memory")
template<int N> DEVFN void cp_waitg(){ asm volatile("cp.async.wait_group %0;"::"n"(N):"memory"); }

DEVFN void bsplit(float x, __nv_bfloat16 &hi, __nv_bfloat16 &lo){
  hi = __float2bfloat16(x);
  lo = __float2bfloat16(x - __bfloat162float(hi));
}
DEVFN uint32_t packb2(__nv_bfloat16 a, __nv_bfloat16 b){
  __nv_bfloat162 t(a, b); return *(uint32_t*)&t;
}
DEVFN uint32_t packh2(float a, float b){
  __half2 t = __floats2half2_rn(a, b); return *(uint32_t*)&t;
}

// ---------------- scratch (device globals) ----------------
__device__ __align__(128) __nv_bfloat16 g_x_pack   [2u*2048u*2048u];  // [lc|gc], rows [hi|lo]
__device__ __align__(128) __nv_bfloat16 g_wqkv_pack[2u*1536u*2048u];
__device__ __align__(128) __half        g_wpr_pack [2u*1024u*2048u];  // fp16 single plane
__device__ __align__(128) float g_comb[2u*2048u*1536u];
__device__ __align__(128) __nv_bfloat16 g_q_pack [32u*1024u*256u];    // q*log2e/8
__device__ __align__(128) __nv_bfloat16 g_k_pack [8u*1024u*256u];
__device__ __align__(128) __nv_bfloat16 g_vT_pack[8u*128u*2048u];     // V^T rows [hi|lo]
__device__ __align__(128) __half        g_ao     [2048u*2048u];       // attn-out fp16
__device__ __align__(128) float g_yy[4096u*1024u];

// ---------------- merged pack ----------------
// blocks: [0,1024) xl | [1024,2048) xg | [2048,2816) wlc | [2816,3584) wgc
//         [3584,4608) wlo | [4608,5632) wgo   (wpr sections -> fp16 single)
__global__ __launch_bounds__(256)
void packAll(const float* __restrict__ xl, const float* __restrict__ xg,
             const float* __restrict__ wlc, const float* __restrict__ wgc,
             const float* __restrict__ wlo, const float* __restrict__ wgo,
             __nv_bfloat16* __restrict__ xp, __nv_bfloat16* __restrict__ wq,
             __half* __restrict__ wp)
{
  int bx = blockIdx.x;
  if (bx >= 3584){
    // fp16 single-plane pack for W_local/W_global
    const float* src; __half* dst;
    bx -= 3584;
    if (bx < 1024){ src = wlo; dst = wp; }
    else { src = wgo; dst = wp + 1024u*2048u; bx -= 1024; }
    int idx = (bx*256 + threadIdx.x)*8;
    float4 v0 = *(const float4*)(src + idx);
    float4 v1 = *(const float4*)(src + idx + 4);
    uint4 hv = make_uint4(packh2(v0.x,v0.y), packh2(v0.z,v0.w),
                          packh2(v1.x,v1.y), packh2(v1.z,v1.w));
    *(uint4*)(dst + idx) = hv;   // layout identical to src (row-major 2048)
    return;
  }
  const float* src; __nv_bfloat16* dst; int K;
  if (bx < 2048){
    K = 1024;
    if (bx < 1024){ src = xl; dst = xp; }
    else { src = xg; dst = xp + 2048u*2048u; bx -= 1024; }
  } else {
    K = 1024; bx -= 2048;
    if (bx < 768){ src = wlc; dst = wq; }
    else { src = wgc; dst = wq + 1536u*2048u; bx -= 768; }
  }
  int idx = (bx*256 + threadIdx.x)*8;
  float4 v0 = *(const float4*)(src + idx);
  float4 v1 = *(const float4*)(src + idx + 4);
  int r = idx / K, k = idx - r*K;
  __nv_bfloat16* d = dst + (ll)r*2*K + k;
  float vv[8] = {v0.x,v0.y,v0.z,v0.w,v1.x,v1.y,v1.z,v1.w};
  uint32_t hw[4], lw[4];
#pragma unroll
  for (int i=0;i<4;i++){
    __nv_bfloat16 h0,l0,h1,l1;
    bsplit(vv[2*i],h0,l0); bsplit(vv[2*i+1],h1,l1);
    hw[i] = packb2(h0,h1); lw[i] = packb2(l0,l1);
  }
  *(uint4*)(d)     = make_uint4(hw[0],hw[1],hw[2],hw[3]);
  *(uint4*)(d + K) = make_uint4(lw[0],lw[1],lw[2],lw[3]);
}

// ---------------- mma.sync GEMM template ----------------
// NT8: n8-tiles per warp (warp n-width NT8*8, block N = 2*NT8*8).
// TERMS: 1 (plain) or 3 (split: A cols {hi,lo,hi}, B cols {hi,hi,lo}).
// FP16: use f16 mma (operands raw 16-bit, pointers reinterpret).
#define ROWB2 144

template<bool SPLIT_N, int NT8, bool FP16, int TERMS>
__global__ __launch_bounds__(256, 2)
void gemm_mma(const __nv_bfloat16* __restrict__ A, const __nv_bfloat16* __restrict__ B,
              float* __restrict__ Cf,
              const float* __restrict__ bias0, const float* __restrict__ bias1,
              int Kreal, int lgn1, int lda, int ldb, int ldc,
              ll sA, ll sB, ll sC, float cscale)
{
  constexpr int NP    = NT8/2;          // b-frag ldsm count per warp
  constexpr int BROWS = NT8*16;         // B tile rows
  constexpr int BIT   = NT8/2;          // B loader iterations (BROWS*8/256)
  constexpr int STGT  = (128 + BROWS)*ROWB2;

  extern __shared__ char smem[];
  const uint32_t sb = smem_u32(smem);
  const int tid = threadIdx.x, wid = tid>>5, lane = tid&31;
  const int z = blockIdx.z;
  const int m0 = blockIdx.y*128, n0 = blockIdx.x*(NT8*16);
  A += z*sA + (ll)m0*lda;
  B += z*sB + (ll)n0*ldb;
  Cf += z*sC;

  const int wm = wid>>1, wn = wid&1;  // 4(M) x 2(N) warps
  const int n1m = (1<<lgn1) - 1;

  float acc[2][NT8][4];
#pragma unroll
  for (int i=0;i<2;i++)
#pragma unroll
    for (int j=0;j<NT8;j++)
#pragma unroll
      for (int q=0;q<4;q++) acc[i][j][q]=0.f;

  const int nch = TERMS << lgn1;

  auto loadStage = [&](int c, int s){
    int t = c >> lgn1, r = c & n1m;
    int acol = ((t==1) ? Kreal : 0) + r*64;
    int bcol = ((t==2) ? Kreal : 0) + r*64;
    const __nv_bfloat16* Ak = A + acol;
    const __nv_bfloat16* Bk = B + bcol;
    uint32_t abase = sb + s*STGT;
    uint32_t bbase = abase + 128*ROWB2;
#pragma unroll
    for (int i=0;i<4;i++){
      int f = tid + i*256;
      int rr = f>>3, q = f&7;
      cp_async16(abase + rr*ROWB2 + q*16, (const char*)(Ak + (ll)rr*lda) + q*16);
    }
#pragma unroll
    for (int i=0;i<BIT;i++){
      int f = tid + i*256;
      int rr = f>>3, q = f&7;
      cp_async16(bbase + rr*ROWB2 + q*16, (const char*)(Bk + (ll)rr*ldb) + q*16);
    }
  };

  loadStage(0, 0); CP_COMMIT();
  loadStage(1, 1); CP_COMMIT();

  for (int c=0; c<nch; c++){
    cp_waitg<1>();
    __syncthreads();
    if (c+2 < nch) loadStage(c+2, (c+2)%3);
    CP_COMMIT();

    const uint32_t abase = sb + (c%3)*STGT;
    const uint32_t bbase = abase + 128*ROWB2;
#pragma unroll
    for (int kk=0; kk<64; kk+=16){
      uint32_t a[2][4], b[NP][4];
#pragma unroll
      for (int h=0; h<2; h++)
        ldsm_x4(a[h], abase + (wm*32 + h*16 + (lane&15))*ROWB2
                             + (kk + ((lane>>4)<<3))*2);
#pragma unroll
      for (int p=0; p<NP; p++)
        ldsm_x4(b[p], bbase + (wn*(NT8*8) + p*16 + ((lane>>4)&1)*8 + (lane&7))*ROWB2
                             + (kk + (((lane>>3)&1)<<3))*2);
#pragma unroll
      for (int mi=0; mi<2; mi++)
#pragma unroll
        for (int p=0; p<NP; p++){
          if (FP16){
            mma16816h(acc[mi][2*p+0], a[mi], &b[p][0]);
            mma16816h(acc[mi][2*p+1], a[mi], &b[p][2]);
          } else {
            mma16816(acc[mi][2*p+0], a[mi], &b[p][0]);
            mma16816(acc[mi][2*p+1], a[mi], &b[p][2]);
          }
        }
    }
  }

#pragma unroll
  for (int mi=0; mi<2; mi++){
#pragma unroll
    for (int ni=0; ni<NT8; ni++){
      int mrow = m0 + wm*32 + mi*16 + (lane>>2);
      int ncol = n0 + wn*(NT8*8) + ni*8 + (lane&3)*2;
#pragma unroll
      for (int hh=0; hh<2; hh++){
        int m = mrow + hh*8;
        float v0 = acc[mi][ni][2*hh+0]*cscale;
        float v1 = acc[mi][ni][2*hh+1]*cscale;
        if (SPLIT_N){
          int nl = ncol & 1023;
          const float* bs = (ncol >= 1024) ? bias1 : bias0;
          v0 += bs[nl]; v1 += bs[nl+1];
          float* dst = Cf + ((ncol >= 1024) ? 2097152LL : 0LL) + (ll)m*1024 + nl;
          *(float2*)dst = make_float2(v0,v1);
        } else {
          *(float2*)(Cf + (ll)m*ldc + ncol) = make_float2(v0,v1);
        }
      }
    }
  }
}

// ---------------- fused flash attention (bf16 3-term; unchanged core) ----------------
#define QROWB 528
#define KROWB 144
#define KSLOT 18432
#define VROWB 272
#define OFF_K  67584
#define OFF_V  122880
#define OFF_VL 157696
#define FSMEM  192512

DEVFN void flash_issueK(uint32_t sb, const __nv_bfloat16* Kc, int kcol, int slot, int tid){
  uint32_t kb = sb + OFF_K + slot*KSLOT;
#pragma unroll
  for (int i=0;i<4;i++){
    int f = tid + i*256;
    int r = f>>3, q = f&7;
    cp_async16(kb + r*KROWB + q*16, (const char*)(Kc + (ll)r*256 + kcol) + q*16);
  }
}
DEVFN void flash_issueV(uint32_t sb, const __nv_bfloat16* Vc, int part, int tid){
  int r0 = part*26;
  int nr = 128 - r0; if (nr > 26) nr = 26;
  for (int f = tid; f < nr*32; f += 256){
    int r = r0 + (f>>5), c = f&31;
    const char* base = (const char*)(Vc + (ll)r*2048);
    if (c < 16) cp_async16(sb + OFF_V  + r*VROWB + c*16, base + c*16);
    else        cp_async16(sb + OFF_VL + r*VROWB + (c-16)*16, base + 2048 + (c-16)*16);
  }
}

__global__ __launch_bounds__(256, 1)
void flash_attn(const __nv_bfloat16* __restrict__ qp,
                const __nv_bfloat16* __restrict__ kp,
                const __nv_bfloat16* __restrict__ vtp,
                __half* __restrict__ aop)
{
  extern __shared__ char smem[];
  const uint32_t sb = smem_u32(smem);
  const int tid = threadIdx.x, wid = tid>>5, lane = tid&31;
  const int z = blockIdx.y, b = z>>4, h = z&15;
  const int s0 = blockIdx.x*128;
  const __nv_bfloat16* Qb = qp + ((ll)z*1024 + s0)*256;
  const __nv_bfloat16* Kb = kp + (ll)(z>>2)*1024*256;
  const __nv_bfloat16* Vb = vtp + (ll)(z>>2)*128*2048;

#pragma unroll
  for (int i=0;i<16;i++){
    int f = tid + i*256;
    int r = f>>5, c = f&31;
    cp_async16(sb + r*QROWB + c*16, (const char*)(Qb + (ll)r*256) + c*16);
  }
  CP_COMMIT();
  flash_issueK(sb, Kb, 0,  0, tid); CP_COMMIT();
  flash_issueK(sb, Kb, 64, 1, tid); CP_COMMIT();

  float m0=-1e30f, m1=-1e30f, l0=0.f, l1=0.f;
  float o[16][4];
#pragma unroll
  for (int ni=0;ni<16;ni++){ o[ni][0]=0.f;o[ni][1]=0.f;o[ni][2]=0.f;o[ni][3]=0.f; }

  const int QCOL[6] = {0,64,128,192,0,64};
  const int KCOL[6] = {0,64,0,64,128,192};

#pragma unroll 1
  for (int nc=0; nc<8; nc++){
    const __nv_bfloat16* Kc = Kb + (ll)(nc*128)*256;
    const __nv_bfloat16* Vc = Vb + nc*128;

    float acc[16][4];
#pragma unroll
    for (int ni=0;ni<16;ni++){ acc[ni][0]=0.f;acc[ni][1]=0.f;acc[ni][2]=0.f;acc[ni][3]=0.f; }

#pragma unroll
    for (int kc=0; kc<6; kc++){
      cp_waitg<1>();
      __syncthreads();
      if (kc < 4){
        flash_issueK(sb, Kc, KCOL[kc+2], (kc+2)%3, tid);
        flash_issueV(sb, Vc, kc, tid);
        CP_COMMIT();
      } else if (kc == 4){
        flash_issueV(sb, Vc, 4, tid);
        CP_COMMIT();
      }
      const uint32_t kb = sb + OFF_K + (kc%3)*KSLOT;
      const int qc = QCOL[kc];
#pragma unroll
      for (int kk=0; kk<64; kk+=16){
        uint32_t a[4];
        ldsm_x4(a, sb + (wid*16 + (lane&15))*QROWB + (qc + kk + ((lane>>4)<<3))*2);
        uint32_t bf[8][4];
#pragma unroll
        for (int p=0;p<8;p++)
          ldsm_x4(bf[p], kb + (p*16 + ((lane>>4)&1)*8 + (lane&7))*KROWB
                            + (kk + (((lane>>3)&1)<<3))*2);
#pragma unroll
        for (int p=0;p<8;p++){
          mma16816(acc[2*p+0], a, &bf[p][0]);
          mma16816(acc[2*p+1], a, &bf[p][2]);
        }
      }
    }

    __syncthreads();
    if (nc < 7){
      const __nv_bfloat16* Kn = Kb + (ll)((nc+1)*128)*256;
      flash_issueK(sb, Kn, 0,  0, tid); CP_COMMIT();
      flash_issueK(sb, Kn, 64, 1, tid); CP_COMMIT();
      cp_waitg<2>();
    } else {
      cp_waitg<0>();
    }
    __syncthreads();

    // ---- online softmax (base-2) ----
    float cm0=-1e30f, cm1=-1e30f;
#pragma unroll
    for (int ni=0;ni<16;ni++){
      cm0 = fmaxf(cm0, fmaxf(acc[ni][0], acc[ni][1]));
      cm1 = fmaxf(cm1, fmaxf(acc[ni][2], acc[ni][3]));
    }
    cm0 = fmaxf(cm0, __shfl_xor_sync(0xffffffffu, cm0, 1));
    cm0 = fmaxf(cm0, __shfl_xor_sync(0xffffffffu, cm0, 2));
    cm1 = fmaxf(cm1, __shfl_xor_sync(0xffffffffu, cm1, 1));
    cm1 = fmaxf(cm1, __shfl_xor_sync(0xffffffffu, cm1, 2));
    float mn0 = fmaxf(m0, cm0), mn1 = fmaxf(m1, cm1);
    float sc0 = exp2f(m0 - mn0), sc1 = exp2f(m1 - mn1);
    m0 = mn0; m1 = mn1;
    float rs0=0.f, rs1=0.f;
#pragma unroll
    for (int ni=0;ni<16;ni++){
      acc[ni][0]=exp2f(acc[ni][0]-m0); acc[ni][1]=exp2f(acc[ni][1]-m0);
      acc[ni][2]=exp2f(acc[ni][2]-m1); acc[ni][3]=exp2f(acc[ni][3]-m1);
      rs0 += acc[ni][0]+acc[ni][1];
      rs1 += acc[ni][2]+acc[ni][3];
    }
    rs0 += __shfl_xor_sync(0xffffffffu, rs0, 1);
    rs0 += __shfl_xor_sync(0xffffffffu, rs0, 2);
    rs1 += __shfl_xor_sync(0xffffffffu, rs1, 1);
    rs1 += __shfl_xor_sync(0xffffffffu, rs1, 2);
    l0 = l0*sc0 + rs0;
    l1 = l1*sc1 + rs1;
#pragma unroll
    for (int ni=0;ni<16;ni++){
      o[ni][0]*=sc0; o[ni][1]*=sc0; o[ni][2]*=sc1; o[ni][3]*=sc1;
    }

    // ---- PV: Phi*Vhi + Plo*Vhi + Phi*Vlo ----
#pragma unroll
    for (int kg=0; kg<8; kg++){
      uint32_t ahi[4], alo[4];
      {
        __nv_bfloat16 x0,y0,x1,y1;
        bsplit(acc[2*kg][0],x0,y0);   bsplit(acc[2*kg][1],x1,y1);
        ahi[0]=packb2(x0,x1); alo[0]=packb2(y0,y1);
        bsplit(acc[2*kg][2],x0,y0);   bsplit(acc[2*kg][3],x1,y1);
        ahi[1]=packb2(x0,x1); alo[1]=packb2(y0,y1);
        bsplit(acc[2*kg+1][0],x0,y0); bsplit(acc[2*kg+1][1],x1,y1);
        ahi[2]=packb2(x0,x1); alo[2]=packb2(y0,y1);
        bsplit(acc[2*kg+1][2],x0,y0); bsplit(acc[2*kg+1][3],x1,y1);
        ahi[3]=packb2(x0,x1); alo[3]=packb2(y0,y1);
      }
#pragma unroll
      for (int p=0;p<8;p++){
        uint32_t rowoff = (p*16 + ((lane>>4)&1)*8 + (lane&7))*VROWB
                        + (kg*16 + (((lane>>3)&1)<<3))*2;
        uint32_t bh[4], bl[4];
        ldsm_x4(bh, sb + OFF_V  + rowoff);
        ldsm_x4(bl, sb + OFF_VL + rowoff);
        mma16816(o[2*p+0], ahi, &bh[0]);
        mma16816(o[2*p+0], alo, &bh[0]);
        mma16816(o[2*p+0], ahi, &bl[0]);
        mma16816(o[2*p+1], ahi, &bh[2]);
        mma16816(o[2*p+1], alo, &bh[2]);
        mma16816(o[2*p+1], ahi, &bl[2]);
      }
    }
  }

  // ---- epilogue: normalize -> fp16 aop ----
  const float inv0 = 1.f/l0, inv1 = 1.f/l1;
  const int qrow0 = s0 + wid*16 + (lane>>2);
  const ll rb0 = ((ll)(b*1024 + qrow0))*2048 + h*128;
  const ll rb1 = rb0 + 8LL*2048;
#pragma unroll
  for (int ni=0;ni<16;ni++){
    int col = ni*8 + (lane&3)*2;
    *(uint32_t*)(aop + rb0 + col) = packh2(o[ni][0]*inv0, o[ni][1]*inv0);
    *(uint32_t*)(aop + rb1 + col) = packh2(o[ni][2]*inv1, o[ni][3]*inv1);
  }
}

// ---------------- merged prep: RMSNorm+RoPE pack | V transpose ----------------
__global__ __launch_bounds__(256)
void prep_qkv(const float* __restrict__ comb,
              const float* __restrict__ cosT, const float* __restrict__ sinT,
              const float* __restrict__ gql, const float* __restrict__ gkl,
              const float* __restrict__ gqg, const float* __restrict__ gkg,
              __nv_bfloat16* __restrict__ qp, __nv_bfloat16* __restrict__ kp,
              __nv_bfloat16* __restrict__ vp)
{
  __shared__ float shbuf[32*33];
  const int t = threadIdx.x;

  if (blockIdx.x >= 2048){
    int b2 = blockIdx.x - 2048;
    const int s0 = (b2 & 31)*32;
    const int c0 = ((b2>>5)&7)*32;
    const int zz = b2>>8;
    const int b = zz>>1, strm = zz&1;
    float (*tt)[33] = (float(*)[33])shbuf;
    const int tx = t&31, ty = t>>5;
    const float* base = comb + (ll)strm*2048*1536;
#pragma unroll
    for (int r=0;r<32;r+=8)
      tt[ty+r][tx] = base[(ll)(b*1024 + s0+ty+r)*1536 + 1280 + c0 + tx];
    __syncthreads();
#pragma unroll
    for (int r=0;r<32;r+=8){
      int v = c0 + ty + r;
      int kh = v>>6, d = v&63;
      ll row = (ll)(b*4+kh)*128 + strm*64 + d;
      float val = tt[tx][ty+r];
      __nv_bfloat16 hi,lo; bsplit(val,hi,lo);
      __nv_bfloat16* o = vp + row*2048 + s0;
      o[tx] = hi; o[1024+tx] = lo;
    }
    return;
  }

  const int bs = blockIdx.x;
  const int b = bs >> 10, s = bs & 1023;
  const float* rl = comb + (ll)bs*1536;
  const float* rg = rl + (ll)2048*1536;

  float sql=0.f, sqg=0.f;
#pragma unroll
  for (int i=t;i<1024;i+=256){ float x=rl[i]; sql+=x*x; float y=rg[i]; sqg+=y*y; }
  float xk=rl[1024+t], yk=rg[1024+t];
  float skl = xk*xk, skg = yk*yk;

  float4* red = (float4*)shbuf;
  float4 v4 = make_float4(sql,sqg,skl,skg);
#pragma unroll
  for (int off=16;off;off>>=1){
    v4.x += __shfl_xor_sync(0xffffffffu, v4.x, off);
    v4.y += __shfl_xor_sync(0xffffffffu, v4.y, off);
    v4.z += __shfl_xor_sync(0xffffffffu, v4.z, off);
    v4.w += __shfl_xor_sync(0xffffffffu, v4.w, off);
  }
  const int w = t>>5, l = t&31;
  if (!l) red[w]=v4;
  __syncthreads();
  if (t==0){
    float4 a = red[0];
    for (int i=1;i<8;i++){ a.x+=red[i].x; a.y+=red[i].y; a.z+=red[i].z; a.w+=red[i].w; }
    red[0]=a;
  }
  __syncthreads();
  float4 tot = red[0];
  const float QF = 0.125f * 1.4426950408889634f;
  const float rql = rsqrtf(tot.x*(1.f/1024.f)+1e-5f) * QF;
  const float rqg = rsqrtf(tot.y*(1.f/1024.f)+1e-5f) * QF;
  const float rkl = rsqrtf(tot.z*(1.f/256.f)+1e-5f);
  const float rkg = rsqrtf(tot.w*(1.f/256.f)+1e-5f);

#pragma unroll
  for (int pp=t; pp<512; pp+=256){
    int h = pp>>5, p = pp&31;
    float c = cosT[s*32+p], sn = sinT[s*32+p];
    int d0 = h*64 + 2*p;
    ll base = (((ll)(b*16+h))*1024 + s)*256;
    float x0 = rl[d0]*rql*gql[d0];
    float x1 = rl[d0+1]*rql*gql[d0+1];
    float y0 = rg[d0]*rqg*gqg[d0];
    float y1 = rg[d0+1]*rqg*gqg[d0+1];
    float o0 = x0*c - x1*sn, o1 = x0*sn + x1*c;
    float o2 = y0*c - y1*sn, o3 = y0*sn + y1*c;
    __nv_bfloat16 h0,l0,h1,l1,h2,l2,h3,l3;
    bsplit(o0,h0,l0); bsplit(o1,h1,l1); bsplit(o2,h2,l2); bsplit(o3,h3,l3);
    *(__nv_bfloat162*)(qp+base+2*p)        = __nv_bfloat162(h0,h1);
    *(__nv_bfloat162*)(qp+base+64+2*p)     = __nv_bfloat162(h2,h3);
    *(__nv_bfloat162*)(qp+base+128+2*p)    = __nv_bfloat162(l0,l1);
    *(__nv_bfloat162*)(qp+base+128+64+2*p) = __nv_bfloat162(l2,l3);
  }
  if (t < 128){
    int kh = t>>5, p = t&31;
    float c = cosT[s*32+p], sn = sinT[s*32+p];
    int gd = kh*64 + 2*p;
    ll base = (((ll)(b*4+kh))*1024 + s)*256;
    float x0 = rl[1024+gd]*rkl*gkl[gd];
    float x1 = rl[1024+gd+1]*rkl*gkl[gd+1];
    float y0 = rg[1024+gd]*rkg*gkg[gd];
    float y1 = rg[1024+gd+1]*rkg*gkg[gd+1];
    float o0 = x0*c - x1*sn, o1 = x0*sn + x1*c;
    float o2 = y0*c - y1*sn, o3 = y0*sn + y1*c;
    __nv_bfloat16 h0,l0,h1,l1,h2,l2,h3,l3;
    bsplit(o0,h0,l0); bsplit(o1,h1,l1); bsplit(o2,h2,l2); bsplit(o3,h3,l3);
    *(__nv_bfloat162*)(kp+base+2*p)        = __nv_bfloat162(h0,h1);
    *(__nv_bfloat162*)(kp+base+64+2*p)     = __nv_bfloat162(h2,h3);
    *(__nv_bfloat162*)(kp+base+128+2*p)    = __nv_bfloat162(l0,l1);
    *(__nv_bfloat162*)(kp+base+128+64+2*p) = __nv_bfloat162(l2,l3);
  }
}

// ---------------- final RMSNorm -> d_out ----------------
__global__ __launch_bounds__(256)
void rmsnorm_out(const float* __restrict__ y, const float* __restrict__ glc,
                 const float* __restrict__ ggc, float* __restrict__ out)
{
  const int row = blockIdx.x;
  const float* g = (row < 2048) ? glc : ggc;
  const float* r = y + (ll)row*1024;
  float* o = out + (ll)row*1024;
  const int t = threadIdx.x;
  float4 v = ((const float4*)r)[t];
  float ss = v.x*v.x + v.y*v.y + v.z*v.z + v.w*v.w;
  __shared__ float sm[8];
#pragma unroll
  for (int o2=16;o2;o2>>=1) ss += __shfl_xor_sync(0xffffffffu,ss,o2);
  const int w=t>>5, l=t&31;
  if (!l) sm[w]=ss;
  __syncthreads();
  ss = sm[0]+sm[1]+sm[2]+sm[3]+sm[4]+sm[5]+sm[6]+sm[7];
  const float rsq = rsqrtf(ss*(1.f/1024.f)+1e-5f);
  float4 gv = ((const float4*)g)[t];
  float4 ov = make_float4(v.x*rsq*gv.x, v.y*rsq*gv.y, v.z*rsq*gv.z, v.w*rsq*gv.w);
  ((float4*)o)[t]=ov;
}

// ---------------- launch ----------------
extern "C" void kernel_launch(void* const* d_in, const int* in_sizes, int n_in,
                              void* d_out, int out_size)
{
  (void)in_sizes; (void)n_in; (void)out_size;
  const float* local_c  = (const float*)d_in[0];
  const float* global_c = (const float*)d_in[1];
  const float* fcos     = (const float*)d_in[2];
  const float* fsin     = (const float*)d_in[3];
  const float* W_lc     = (const float*)d_in[4];
  const float* W_gc     = (const float*)d_in[5];
  const float* g_q_lc   = (const float*)d_in[6];
  const float* g_k_lc   = (const float*)d_in[7];
  const float* g_q_gc   = (const float*)d_in[8];
  const float* g_k_gc   = (const float*)d_in[9];
  const float* W_local  = (const float*)d_in[10];
  const float* b_local  = (const float*)d_in[11];
  const float* g_lc_out = (const float*)d_in[12];
  const float* W_global = (const float*)d_in[13];
  const float* b_global = (const float*)d_in[14];
  const float* g_gc_out = (const float*)d_in[15];

  __nv_bfloat16 *xp,*wq,*qp,*kp,*vtp;
  __half *wp,*aop;
  float *comb,*yy;
  cudaGetSymbolAddress((void**)&xp,  g_x_pack);
  cudaGetSymbolAddress((void**)&wq,  g_wqkv_pack);
  cudaGetSymbolAddress((void**)&wp,  g_wpr_pack);
  cudaGetSymbolAddress((void**)&comb, g_comb);
  cudaGetSymbolAddress((void**)&qp,  g_q_pack);
  cudaGetSymbolAddress((void**)&kp,  g_k_pack);
  cudaGetSymbolAddress((void**)&vtp, g_vT_pack);
  cudaGetSymbolAddress((void**)&aop, g_ao);
  cudaGetSymbolAddress((void**)&yy,  g_yy);

  const int SM_QKV = 3*((128+96)*144);   // 96768
  const int SM_OUT = 3*((128+128)*144);  // 110592
  static int attr_done = 0;
  if (!attr_done){
    cudaFuncSetAttribute((const void*)gemm_mma<false,6,false,3>,
                         cudaFuncAttributeMaxDynamicSharedMemorySize, SM_QKV);
    cudaFuncSetAttribute((const void*)gemm_mma<true,8,true,1>,
                         cudaFuncAttributeMaxDynamicSharedMemorySize, SM_OUT);
    cudaFuncSetAttribute((const void*)flash_attn,
                         cudaFuncAttributeMaxDynamicSharedMemorySize, FSMEM);
    attr_done = 1;
  }

  // 0) operand packs
  packAll<<<5632,256>>>(local_c, global_c, W_lc, W_gc, W_local, W_global, xp, wq, wp);

  // 1) QKV projections, bf16 3-term, N-tile 96  (M=2048,N=1536,K=1024,lgn1=4)
  gemm_mma<false,6,false,3><<<dim3(16,16,2),256,SM_QKV>>>(xp, wq, comb, nullptr, nullptr,
     1024, 4, 2048, 2048, 1536, 2048LL*2048, 1536LL*2048, 2048LL*1536, 1.f);

  // 2) merged rmsnorm+rope pack + V transpose
  prep_qkv<<<3072,256>>>(comb, fcos, fsin, g_q_lc, g_k_lc, g_q_gc, g_k_gc, qp, kp, vtp);

  // 3) fused attention -> aop (fp16)
  flash_attn<<<dim3(8,32),256,FSMEM>>>(qp, kp, vtp, aop);

  // 4) merged output projections, fp16 1-term + bias  (M=2048,N=2048,K=2048,lgn1=5)
  gemm_mma<true,8,true,1><<<dim3(16,16,1),256,SM_OUT>>>(
     (const __nv_bfloat16*)aop, (const __nv_bfloat16*)wp, yy, b_local, b_global,
     2048, 5, 2048, 2048, 1024, 0,0,0, 1.f);

  // 5) final rmsnorm -> d_out
  rmsnorm_out<<<4096,256>>>(yy, g_lc_out, g_gc_out, (float*)d_out);
}

// round 14
// speedup vs baseline: 3.7523x; 1.1152x over previous
#include <cuda_runtime.h>
#include <cuda_bf16.h>
#include <cuda_fp16.h>
#include <cstdint>

// B=2, S=1024, D=1024, H=16, KVH=4, HD=64, TOT=1536
// QKV proj + QK^T: bf16 mma, 2-term split ([hi|lo] storage, 3-term virtual-K).
// PV and output projection: single-term fp16 mma (combined rel_err ~5e-4).
// Flash-fused attention; 3-stage cp.async pipelines; base-2 softmax.

typedef unsigned long long ull;
typedef long long ll;
#define DEVFN static __device__ __forceinline__

// ---------------- PTX helpers ----------------
DEVFN uint32_t smem_u32(const void* p){
  uint32_t a; asm("{ .reg .u64 t; cvta.to.shared.u64 t, %1; cvt.u32.u64 %0, t; }":"=r"(a):"l"(p)); return a;
}
DEVFN void ldsm_x4(uint32_t* r, uint32_t addr){
  asm volatile("ldmatrix.sync.aligned.m8n8.x4.shared.b16 {%0,%1,%2,%3}, [%4];"
    : "=r"(r[0]),"=r"(r[1]),"=r"(r[2]),"=r"(r[3]) : "r"(addr));
}
DEVFN void mma16816(float* c, const uint32_t* a, const uint32_t* b){
  asm volatile("mma.sync.aligned.m16n8k16.row.col.f32.bf16.bf16.f32 "
    "{%0,%1,%2,%3}, {%4,%5,%6,%7}, {%8,%9}, {%0,%1,%2,%3};"
    : "+f"(c[0]),"+f"(c[1]),"+f"(c[2]),"+f"(c[3])
    : "r"(a[0]),"r"(a[1]),"r"(a[2]),"r"(a[3]), "r"(b[0]),"r"(b[1]));
}
DEVFN void mma16816h(float* c, const uint32_t* a, const uint32_t* b){
  asm volatile("mma.sync.aligned.m16n8k16.row.col.f32.f16.f16.f32 "
    "{%0,%1,%2,%3}, {%4,%5,%6,%7}, {%8,%9}, {%0,%1,%2,%3};"
    : "+f"(c[0]),"+f"(c[1]),"+f"(c[2]),"+f"(c[3])
    : "r"(a[0]),"r"(a[1]),"r"(a[2]),"r"(a[3]), "r"(b[0]),"r"(b[1]));
}
DEVFN void cp_async16(uint32_t dst, const void* src){
  asm volatile("cp.async.cg.shared.global [%0], [%1], 16;" :: "r"(dst), "l"(src));
}
#define CP_COMMIT() asm volatile("cp.async.commit_group;" ::: "memory")
template<int N> DEVFN void cp_waitg(){ asm volatile("cp.async.wait_group %0;"::"n"(N):"memory"); }

DEVFN void bsplit(float x, __nv_bfloat16 &hi, __nv_bfloat16 &lo){
  hi = __float2bfloat16(x);
  lo = __float2bfloat16(x - __bfloat162float(hi));
}
DEVFN uint32_t packb2(__nv_bfloat16 a, __nv_bfloat16 b){
  __nv_bfloat162 t(a, b); return *(uint32_t*)&t;
}
DEVFN uint32_t packh2(float a, float b){
  __half2 t = __floats2half2_rn(a, b); return *(uint32_t*)&t;
}

// ---------------- scratch (device globals) ----------------
__device__ __align__(128) __nv_bfloat16 g_x_pack   [2u*2048u*2048u];  // [lc|gc], rows [hi|lo]
__device__ __align__(128) __nv_bfloat16 g_wqkv_pack[2u*1536u*2048u];
__device__ __align__(128) __half        g_wpr_pack [2u*1024u*2048u];  // fp16 single plane
__device__ __align__(128) float g_comb[2u*2048u*1536u];
__device__ __align__(128) __nv_bfloat16 g_q_pack [32u*1024u*256u];    // q*log2e/8, [hi|lo]
__device__ __align__(128) __nv_bfloat16 g_k_pack [8u*1024u*256u];     // [hi|lo]
__device__ __align__(128) __half        g_vT     [8u*128u*1024u];     // V^T fp16 single plane
__device__ __align__(128) __half        g_ao     [2048u*2048u];       // attn-out fp16
__device__ __align__(128) float g_yy[4096u*1024u];

// ---------------- merged pack ----------------
// blocks: [0,1024) xl | [1024,2048) xg | [2048,2816) wlc | [2816,3584) wgc
//         [3584,4608) wlo | [4608,5632) wgo  (wpr -> fp16 single plane)
__global__ __launch_bounds__(256)
void packAll(const float* __restrict__ xl, const float* __restrict__ xg,
             const float* __restrict__ wlc, const float* __restrict__ wgc,
             const float* __restrict__ wlo, const float* __restrict__ wgo,
             __nv_bfloat16* __restrict__ xp, __nv_bfloat16* __restrict__ wq,
             __half* __restrict__ wp)
{
  int bx = blockIdx.x;
  if (bx >= 3584){
    const float* src; __half* dst;
    bx -= 3584;
    if (bx < 1024){ src = wlo; dst = wp; }
    else { src = wgo; dst = wp + 1024u*2048u; bx -= 1024; }
    int idx = (bx*256 + threadIdx.x)*8;
    float4 v0 = *(const float4*)(src + idx);
    float4 v1 = *(const float4*)(src + idx + 4);
    uint4 hv = make_uint4(packh2(v0.x,v0.y), packh2(v0.z,v0.w),
                          packh2(v1.x,v1.y), packh2(v1.z,v1.w));
    *(uint4*)(dst + idx) = hv;
    return;
  }
  const float* src; __nv_bfloat16* dst; int K;
  if (bx < 2048){
    K = 1024;
    if (bx < 1024){ src = xl; dst = xp; }
    else { src = xg; dst = xp + 2048u*2048u; bx -= 1024; }
  } else {
    K = 1024; bx -= 2048;
    if (bx < 768){ src = wlc; dst = wq; }
    else { src = wgc; dst = wq + 1536u*2048u; bx -= 768; }
  }
  int idx = (bx*256 + threadIdx.x)*8;
  float4 v0 = *(const float4*)(src + idx);
  float4 v1 = *(const float4*)(src + idx + 4);
  int r = idx / K, k = idx - r*K;
  __nv_bfloat16* d = dst + (ll)r*2*K + k;
  float vv[8] = {v0.x,v0.y,v0.z,v0.w,v1.x,v1.y,v1.z,v1.w};
  uint32_t hw[4], lw[4];
#pragma unroll
  for (int i=0;i<4;i++){
    __nv_bfloat16 h0,l0,h1,l1;
    bsplit(vv[2*i],h0,l0); bsplit(vv[2*i+1],h1,l1);
    hw[i] = packb2(h0,h1); lw[i] = packb2(l0,l1);
  }
  *(uint4*)(d)     = make_uint4(hw[0],hw[1],hw[2],hw[3]);
  *(uint4*)(d + K) = make_uint4(lw[0],lw[1],lw[2],lw[3]);
}

// ---------------- mma.sync GEMM template ----------------
#define ROWB2 144

template<bool SPLIT_N, int NT8, bool FP16, int TERMS>
__global__ __launch_bounds__(256, 2)
void gemm_mma(const __nv_bfloat16* __restrict__ A, const __nv_bfloat16* __restrict__ B,
              float* __restrict__ Cf,
              const float* __restrict__ bias0, const float* __restrict__ bias1,
              int Kreal, int lgn1, int lda, int ldb, int ldc,
              ll sA, ll sB, ll sC, float cscale)
{
  constexpr int NP    = NT8/2;
  constexpr int BROWS = NT8*16;
  constexpr int BIT   = NT8/2;
  constexpr int STGT  = (128 + BROWS)*ROWB2;

  extern __shared__ char smem[];
  const uint32_t sb = smem_u32(smem);
  const int tid = threadIdx.x, wid = tid>>5, lane = tid&31;
  const int z = blockIdx.z;
  const int m0 = blockIdx.y*128, n0 = blockIdx.x*(NT8*16);
  A += z*sA + (ll)m0*lda;
  B += z*sB + (ll)n0*ldb;
  Cf += z*sC;

  const int wm = wid>>1, wn = wid&1;
  const int n1m = (1<<lgn1) - 1;

  float acc[2][NT8][4];
#pragma unroll
  for (int i=0;i<2;i++)
#pragma unroll
    for (int j=0;j<NT8;j++)
#pragma unroll
      for (int q=0;q<4;q++) acc[i][j][q]=0.f;

  const int nch = TERMS << lgn1;

  auto loadStage = [&](int c, int s){
    int t = c >> lgn1, r = c & n1m;
    int acol = ((t==1) ? Kreal : 0) + r*64;
    int bcol = ((t==2) ? Kreal : 0) + r*64;
    const __nv_bfloat16* Ak = A + acol;
    const __nv_bfloat16* Bk = B + bcol;
    uint32_t abase = sb + s*STGT;
    uint32_t bbase = abase + 128*ROWB2;
#pragma unroll
    for (int i=0;i<4;i++){
      int f = tid + i*256;
      int rr = f>>3, q = f&7;
      cp_async16(abase + rr*ROWB2 + q*16, (const char*)(Ak + (ll)rr*lda) + q*16);
    }
#pragma unroll
    for (int i=0;i<BIT;i++){
      int f = tid + i*256;
      int rr = f>>3, q = f&7;
      cp_async16(bbase + rr*ROWB2 + q*16, (const char*)(Bk + (ll)rr*ldb) + q*16);
    }
  };

  loadStage(0, 0); CP_COMMIT();
  loadStage(1, 1); CP_COMMIT();

  for (int c=0; c<nch; c++){
    cp_waitg<1>();
    __syncthreads();
    if (c+2 < nch) loadStage(c+2, (c+2)%3);
    CP_COMMIT();

    const uint32_t abase = sb + (c%3)*STGT;
    const uint32_t bbase = abase + 128*ROWB2;
#pragma unroll
    for (int kk=0; kk<64; kk+=16){
      uint32_t a[2][4], b[NP][4];
#pragma unroll
      for (int h=0; h<2; h++)
        ldsm_x4(a[h], abase + (wm*32 + h*16 + (lane&15))*ROWB2
                             + (kk + ((lane>>4)<<3))*2);
#pragma unroll
      for (int p=0; p<NP; p++)
        ldsm_x4(b[p], bbase + (wn*(NT8*8) + p*16 + ((lane>>4)&1)*8 + (lane&7))*ROWB2
                             + (kk + (((lane>>3)&1)<<3))*2);
#pragma unroll
      for (int mi=0; mi<2; mi++)
#pragma unroll
        for (int p=0; p<NP; p++){
          if (FP16){
            mma16816h(acc[mi][2*p+0], a[mi], &b[p][0]);
            mma16816h(acc[mi][2*p+1], a[mi], &b[p][2]);
          } else {
            mma16816(acc[mi][2*p+0], a[mi], &b[p][0]);
            mma16816(acc[mi][2*p+1], a[mi], &b[p][2]);
          }
        }
    }
  }

#pragma unroll
  for (int mi=0; mi<2; mi++){
#pragma unroll
    for (int ni=0; ni<NT8; ni++){
      int mrow = m0 + wm*32 + mi*16 + (lane>>2);
      int ncol = n0 + wn*(NT8*8) + ni*8 + (lane&3)*2;
#pragma unroll
      for (int hh=0; hh<2; hh++){
        int m = mrow + hh*8;
        float v0 = acc[mi][ni][2*hh+0]*cscale;
        float v1 = acc[mi][ni][2*hh+1]*cscale;
        if (SPLIT_N){
          int nl = ncol & 1023;
          const float* bs = (ncol >= 1024) ? bias1 : bias0;
          v0 += bs[nl]; v1 += bs[nl+1];
          float* dst = Cf + ((ncol >= 1024) ? 2097152LL : 0LL) + (ll)m*1024 + nl;
          *(float2*)dst = make_float2(v0,v1);
        } else {
          *(float2*)(Cf + (ll)m*ldc + ncol) = make_float2(v0,v1);
        }
      }
    }
  }
}

// ---------------- fused flash attention ----------------
// QK: bf16 3-term over [hi|lo] Q/K.  PV: fp16 single-term (P rounded, V fp16).
#define QROWB 528
#define KROWB 144
#define KSLOT 18432
#define VROWB 272     // 256B data (128 seq fp16) + 16 pad
#define OFF_K  67584                  // Q = 128*528
#define OFF_V  122880                 // OFF_K + 3*KSLOT
#define FSMEM  157696                 // OFF_V + 128*VROWB

DEVFN void flash_issueK(uint32_t sb, const __nv_bfloat16* Kc, int kcol, int slot, int tid){
  uint32_t kb = sb + OFF_K + slot*KSLOT;
#pragma unroll
  for (int i=0;i<4;i++){
    int f = tid + i*256;
    int r = f>>3, q = f&7;
    cp_async16(kb + r*KROWB + q*16, (const char*)(Kc + (ll)r*256 + kcol) + q*16);
  }
}
// part in 0..4: rows [part*26, min(128, part*26+26)) of the fp16 V tile
DEVFN void flash_issueV(uint32_t sb, const __half* Vc, int part, int tid){
  int r0 = part*26;
  int nr = 128 - r0; if (nr > 26) nr = 26;
  for (int f = tid; f < nr*16; f += 256){
    int r = r0 + (f>>4), c = f&15;
    cp_async16(sb + OFF_V + r*VROWB + c*16, (const char*)(Vc + (ll)r*1024) + c*16);
  }
}

__global__ __launch_bounds__(256, 1)
void flash_attn(const __nv_bfloat16* __restrict__ qp,
                const __nv_bfloat16* __restrict__ kp,
                const __half* __restrict__ vtp,
                __half* __restrict__ aop)
{
  extern __shared__ char smem[];
  const uint32_t sb = smem_u32(smem);
  const int tid = threadIdx.x, wid = tid>>5, lane = tid&31;
  const int z = blockIdx.y, b = z>>4, h = z&15;
  const int s0 = blockIdx.x*128;
  const __nv_bfloat16* Qb = qp + ((ll)z*1024 + s0)*256;
  const __nv_bfloat16* Kb = kp + (ll)(z>>2)*1024*256;
  const __half* Vb = vtp + (ll)(z>>2)*128*1024;

#pragma unroll
  for (int i=0;i<16;i++){
    int f = tid + i*256;
    int r = f>>5, c = f&31;
    cp_async16(sb + r*QROWB + c*16, (const char*)(Qb + (ll)r*256) + c*16);
  }
  CP_COMMIT();
  flash_issueK(sb, Kb, 0,  0, tid); CP_COMMIT();
  flash_issueK(sb, Kb, 64, 1, tid); CP_COMMIT();

  float m0=-1e30f, m1=-1e30f, l0=0.f, l1=0.f;
  float o[16][4];
#pragma unroll
  for (int ni=0;ni<16;ni++){ o[ni][0]=0.f;o[ni][1]=0.f;o[ni][2]=0.f;o[ni][3]=0.f; }

  const int QCOL[6] = {0,64,128,192,0,64};
  const int KCOL[6] = {0,64,0,64,128,192};

#pragma unroll 1
  for (int nc=0; nc<8; nc++){
    const __nv_bfloat16* Kc = Kb + (ll)(nc*128)*256;
    const __half* Vc = Vb + nc*128;

    float acc[16][4];
#pragma unroll
    for (int ni=0;ni<16;ni++){ acc[ni][0]=0.f;acc[ni][1]=0.f;acc[ni][2]=0.f;acc[ni][3]=0.f; }

#pragma unroll
    for (int kc=0; kc<6; kc++){
      cp_waitg<1>();
      __syncthreads();
      if (kc < 4){
        flash_issueK(sb, Kc, KCOL[kc+2], (kc+2)%3, tid);
        flash_issueV(sb, Vc, kc, tid);
        CP_COMMIT();
      } else if (kc == 4){
        flash_issueV(sb, Vc, 4, tid);
        CP_COMMIT();
      }
      const uint32_t kb = sb + OFF_K + (kc%3)*KSLOT;
      const int qc = QCOL[kc];
#pragma unroll
      for (int kk=0; kk<64; kk+=16){
        uint32_t a[4];
        ldsm_x4(a, sb + (wid*16 + (lane&15))*QROWB + (qc + kk + ((lane>>4)<<3))*2);
        uint32_t bf[8][4];
#pragma unroll
        for (int p=0;p<8;p++)
          ldsm_x4(bf[p], kb + (p*16 + ((lane>>4)&1)*8 + (lane&7))*KROWB
                            + (kk + (((lane>>3)&1)<<3))*2);
#pragma unroll
        for (int p=0;p<8;p++){
          mma16816(acc[2*p+0], a, &bf[p][0]);
          mma16816(acc[2*p+1], a, &bf[p][2]);
        }
      }
    }

    __syncthreads();
    if (nc < 7){
      const __nv_bfloat16* Kn = Kb + (ll)((nc+1)*128)*256;
      flash_issueK(sb, Kn, 0,  0, tid); CP_COMMIT();
      flash_issueK(sb, Kn, 64, 1, tid); CP_COMMIT();
      cp_waitg<2>();
    } else {
      cp_waitg<0>();
    }
    __syncthreads();

    // ---- online softmax (base-2) ----
    float cm0=-1e30f, cm1=-1e30f;
#pragma unroll
    for (int ni=0;ni<16;ni++){
      cm0 = fmaxf(cm0, fmaxf(acc[ni][0], acc[ni][1]));
      cm1 = fmaxf(cm1, fmaxf(acc[ni][2], acc[ni][3]));
    }
    cm0 = fmaxf(cm0, __shfl_xor_sync(0xffffffffu, cm0, 1));
    cm0 = fmaxf(cm0, __shfl_xor_sync(0xffffffffu, cm0, 2));
    cm1 = fmaxf(cm1, __shfl_xor_sync(0xffffffffu, cm1, 1));
    cm1 = fmaxf(cm1, __shfl_xor_sync(0xffffffffu, cm1, 2));
    float mn0 = fmaxf(m0, cm0), mn1 = fmaxf(m1, cm1);
    float sc0 = exp2f(m0 - mn0), sc1 = exp2f(m1 - mn1);
    m0 = mn0; m1 = mn1;
    float rs0=0.f, rs1=0.f;
#pragma unroll
    for (int ni=0;ni<16;ni++){
      acc[ni][0]=exp2f(acc[ni][0]-m0); acc[ni][1]=exp2f(acc[ni][1]-m0);
      acc[ni][2]=exp2f(acc[ni][2]-m1); acc[ni][3]=exp2f(acc[ni][3]-m1);
      rs0 += acc[ni][0]+acc[ni][1];
      rs1 += acc[ni][2]+acc[ni][3];
    }
    rs0 += __shfl_xor_sync(0xffffffffu, rs0, 1);
    rs0 += __shfl_xor_sync(0xffffffffu, rs0, 2);
    rs1 += __shfl_xor_sync(0xffffffffu, rs1, 1);
    rs1 += __shfl_xor_sync(0xffffffffu, rs1, 2);
    l0 = l0*sc0 + rs0;
    l1 = l1*sc1 + rs1;
#pragma unroll
    for (int ni=0;ni<16;ni++){
      o[ni][0]*=sc0; o[ni][1]*=sc0; o[ni][2]*=sc1; o[ni][3]*=sc1;
    }

    // ---- PV: single-term fp16 (P rounded to fp16, V fp16) ----
#pragma unroll
    for (int kg=0; kg<8; kg++){
      uint32_t ap[4];
      ap[0] = packh2(acc[2*kg][0],   acc[2*kg][1]);
      ap[1] = packh2(acc[2*kg][2],   acc[2*kg][3]);
      ap[2] = packh2(acc[2*kg+1][0], acc[2*kg+1][1]);
      ap[3] = packh2(acc[2*kg+1][2], acc[2*kg+1][3]);
#pragma unroll
      for (int p=0;p<8;p++){
        uint32_t bh[4];
        ldsm_x4(bh, sb + OFF_V + (p*16 + ((lane>>4)&1)*8 + (lane&7))*VROWB
                               + (kg*16 + (((lane>>3)&1)<<3))*2);
        mma16816h(o[2*p+0], ap, &bh[0]);
        mma16816h(o[2*p+1], ap, &bh[2]);
      }
    }
  }

  // ---- epilogue: normalize -> fp16 aop ----
  const float inv0 = 1.f/l0, inv1 = 1.f/l1;
  const int qrow0 = s0 + wid*16 + (lane>>2);
  const ll rb0 = ((ll)(b*1024 + qrow0))*2048 + h*128;
  const ll rb1 = rb0 + 8LL*2048;
#pragma unroll
  for (int ni=0;ni<16;ni++){
    int col = ni*8 + (lane&3)*2;
    *(uint32_t*)(aop + rb0 + col) = packh2(o[ni][0]*inv0, o[ni][1]*inv0);
    *(uint32_t*)(aop + rb1 + col) = packh2(o[ni][2]*inv1, o[ni][3]*inv1);
  }
}

// ---------------- merged prep: RMSNorm+RoPE pack | V transpose ----------------
__global__ __launch_bounds__(256)
void prep_qkv(const float* __restrict__ comb,
              const float* __restrict__ cosT, const float* __restrict__ sinT,
              const float* __restrict__ gql, const float* __restrict__ gkl,
              const float* __restrict__ gqg, const float* __restrict__ gkg,
              __nv_bfloat16* __restrict__ qp, __nv_bfloat16* __restrict__ kp,
              __half* __restrict__ vp)
{
  __shared__ float shbuf[32*33];
  const int t = threadIdx.x;

  if (blockIdx.x >= 2048){
    int b2 = blockIdx.x - 2048;
    const int s0 = (b2 & 31)*32;
    const int c0 = ((b2>>5)&7)*32;
    const int zz = b2>>8;
    const int b = zz>>1, strm = zz&1;
    float (*tt)[33] = (float(*)[33])shbuf;
    const int tx = t&31, ty = t>>5;
    const float* base = comb + (ll)strm*2048*1536;
#pragma unroll
    for (int r=0;r<32;r+=8)
      tt[ty+r][tx] = base[(ll)(b*1024 + s0+ty+r)*1536 + 1280 + c0 + tx];
    __syncthreads();
#pragma unroll
    for (int r=0;r<32;r+=8){
      int v = c0 + ty + r;
      int kh = v>>6, d = v&63;
      ll row = (ll)(b*4+kh)*128 + strm*64 + d;
      vp[row*1024 + s0 + tx] = __float2half_rn(tt[tx][ty+r]);
    }
    return;
  }

  const int bs = blockIdx.x;
  const int b = bs >> 10, s = bs & 1023;
  const float* rl = comb + (ll)bs*1536;
  const float* rg = rl + (ll)2048*1536;

  float sql=0.f, sqg=0.f;
#pragma unroll
  for (int i=t;i<1024;i+=256){ float x=rl[i]; sql+=x*x; float y=rg[i]; sqg+=y*y; }
  float xk=rl[1024+t], yk=rg[1024+t];
  float skl = xk*xk, skg = yk*yk;

  float4* red = (float4*)shbuf;
  float4 v4 = make_float4(sql,sqg,skl,skg);
#pragma unroll
  for (int off=16;off;off>>=1){
    v4.x += __shfl_xor_sync(0xffffffffu, v4.x, off);
    v4.y += __shfl_xor_sync(0xffffffffu, v4.y, off);
    v4.z += __shfl_xor_sync(0xffffffffu, v4.z, off);
    v4.w += __shfl_xor_sync(0xffffffffu, v4.w, off);
  }
  const int w = t>>5, l = t&31;
  if (!l) red[w]=v4;
  __syncthreads();
  if (t==0){
    float4 a = red[0];
    for (int i=1;i<8;i++){ a.x+=red[i].x; a.y+=red[i].y; a.z+=red[i].z; a.w+=red[i].w; }
    red[0]=a;
  }
  __syncthreads();
  float4 tot = red[0];
  const float QF = 0.125f * 1.4426950408889634f;
  const float rql = rsqrtf(tot.x*(1.f/1024.f)+1e-5f) * QF;
  const float rqg = rsqrtf(tot.y*(1.f/1024.f)+1e-5f) * QF;
  const float rkl = rsqrtf(tot.z*(1.f/256.f)+1e-5f);
  const float rkg = rsqrtf(tot.w*(1.f/256.f)+1e-5f);

#pragma unroll
  for (int pp=t; pp<512; pp+=256){
    int h = pp>>5, p = pp&31;
    float c = cosT[s*32+p], sn = sinT[s*32+p];
    int d0 = h*64 + 2*p;
    ll base = (((ll)(b*16+h))*1024 + s)*256;
    float x0 = rl[d0]*rql*gql[d0];
    float x1 = rl[d0+1]*rql*gql[d0+1];
    float y0 = rg[d0]*rqg*gqg[d0];
    float y1 = rg[d0+1]*rqg*gqg[d0+1];
    float o0 = x0*c - x1*sn, o1 = x0*sn + x1*c;
    float o2 = y0*c - y1*sn, o3 = y0*sn + y1*c;
    __nv_bfloat16 h0,l0,h1,l1,h2,l2,h3,l3;
    bsplit(o0,h0,l0); bsplit(o1,h1,l1); bsplit(o2,h2,l2); bsplit(o3,h3,l3);
    *(__nv_bfloat162*)(qp+base+2*p)        = __nv_bfloat162(h0,h1);
    *(__nv_bfloat162*)(qp+base+64+2*p)     = __nv_bfloat162(h2,h3);
    *(__nv_bfloat162*)(qp+base+128+2*p)    = __nv_bfloat162(l0,l1);
    *(__nv_bfloat162*)(qp+base+128+64+2*p) = __nv_bfloat162(l2,l3);
  }
  if (t < 128){
    int kh = t>>5, p = t&31;
    float c = cosT[s*32+p], sn = sinT[s*32+p];
    int gd = kh*64 + 2*p;
    ll base = (((ll)(b*4+kh))*1024 + s)*256;
    float x0 = rl[1024+gd]*rkl*gkl[gd];
    float x1 = rl[1024+gd+1]*rkl*gkl[gd+1];
    float y0 = rg[1024+gd]*rkg*gkg[gd];
    float y1 = rg[1024+gd+1]*rkg*gkg[gd+1];
    float o0 = x0*c - x1*sn, o1 = x0*sn + x1*c;
    float o2 = y0*c - y1*sn, o3 = y0*sn + y1*c;
    __nv_bfloat16 h0,l0,h1,l1,h2,l2,h3,l3;
    bsplit(o0,h0,l0); bsplit(o1,h1,l1); bsplit(o2,h2,l2); bsplit(o3,h3,l3);
    *(__nv_bfloat162*)(kp+base+2*p)        = __nv_bfloat162(h0,h1);
    *(__nv_bfloat162*)(kp+base+64+2*p)     = __nv_bfloat162(h2,h3);
    *(__nv_bfloat162*)(kp+base+128+2*p)    = __nv_bfloat162(l0,l1);
    *(__nv_bfloat162*)(kp+base+128+64+2*p) = __nv_bfloat162(l2,l3);
  }
}

// ---------------- final RMSNorm -> d_out ----------------
__global__ __launch_bounds__(256)
void rmsnorm_out(const float* __restrict__ y, const float* __restrict__ glc,
                 const float* __restrict__ ggc, float* __restrict__ out)
{
  const int row = blockIdx.x;
  const float* g = (row < 2048) ? glc : ggc;
  const float* r = y + (ll)row*1024;
  float* o = out + (ll)row*1024;
  const int t = threadIdx.x;
  float4 v = ((const float4*)r)[t];
  float ss = v.x*v.x + v.y*v.y + v.z*v.z + v.w*v.w;
  __shared__ float sm[8];
#pragma unroll
  for (int o2=16;o2;o2>>=1) ss += __shfl_xor_sync(0xffffffffu,ss,o2);
  const int w=t>>5, l=t&31;
  if (!l) sm[w]=ss;
  __syncthreads();
  ss = sm[0]+sm[1]+sm[2]+sm[3]+sm[4]+sm[5]+sm[6]+sm[7];
  const float rsq = rsqrtf(ss*(1.f/1024.f)+1e-5f);
  float4 gv = ((const float4*)g)[t];
  float4 ov = make_float4(v.x*rsq*gv.x, v.y*rsq*gv.y, v.z*rsq*gv.z, v.w*rsq*gv.w);
  ((float4*)o)[t]=ov;
}

// ---------------- launch ----------------
extern "C" void kernel_launch(void* const* d_in, const int* in_sizes, int n_in,
                              void* d_out, int out_size)
{
  (void)in_sizes; (void)n_in; (void)out_size;
  const float* local_c  = (const float*)d_in[0];
  const float* global_c = (const float*)d_in[1];
  const float* fcos     = (const float*)d_in[2];
  const float* fsin     = (const float*)d_in[3];
  const float* W_lc     = (const float*)d_in[4];
  const float* W_gc     = (const float*)d_in[5];
  const float* g_q_lc   = (const float*)d_in[6];
  const float* g_k_lc   = (const float*)d_in[7];
  const float* g_q_gc   = (const float*)d_in[8];
  const float* g_k_gc   = (const float*)d_in[9];
  const float* W_local  = (const float*)d_in[10];
  const float* b_local  = (const float*)d_in[11];
  const float* g_lc_out = (const float*)d_in[12];
  const float* W_global = (const float*)d_in[13];
  const float* b_global = (const float*)d_in[14];
  const float* g_gc_out = (const float*)d_in[15];

  __nv_bfloat16 *xp,*wq,*qp,*kp;
  __half *wp,*vtp,*aop;
  float *comb,*yy;
  cudaGetSymbolAddress((void**)&xp,  g_x_pack);
  cudaGetSymbolAddress((void**)&wq,  g_wqkv_pack);
  cudaGetSymbolAddress((void**)&wp,  g_wpr_pack);
  cudaGetSymbolAddress((void**)&comb, g_comb);
  cudaGetSymbolAddress((void**)&qp,  g_q_pack);
  cudaGetSymbolAddress((void**)&kp,  g_k_pack);
  cudaGetSymbolAddress((void**)&vtp, g_vT);
  cudaGetSymbolAddress((void**)&aop, g_ao);
  cudaGetSymbolAddress((void**)&yy,  g_yy);

  const int SM_QKV = 3*((128+96)*144);   // 96768
  const int SM_OUT = 3*((128+128)*144);  // 110592
  static int attr_done = 0;
  if (!attr_done){
    cudaFuncSetAttribute((const void*)gemm_mma<false,6,false,3>,
                         cudaFuncAttributeMaxDynamicSharedMemorySize, SM_QKV);
    cudaFuncSetAttribute((const void*)gemm_mma<true,8,true,1>,
                         cudaFuncAttributeMaxDynamicSharedMemorySize, SM_OUT);
    cudaFuncSetAttribute((const void*)flash_attn,
                         cudaFuncAttributeMaxDynamicSharedMemorySize, FSMEM);
    attr_done = 1;
  }

  // 0) operand packs
  packAll<<<5632,256>>>(local_c, global_c, W_lc, W_gc, W_local, W_global, xp, wq, wp);

  // 1) QKV projections, bf16 3-term, N-tile 96  (M=2048,N=1536,K=1024,lgn1=4)
  gemm_mma<false,6,false,3><<<dim3(16,16,2),256,SM_QKV>>>(xp, wq, comb, nullptr, nullptr,
     1024, 4, 2048, 2048, 1536, 2048LL*2048, 1536LL*2048, 2048LL*1536, 1.f);

  // 2) merged rmsnorm+rope pack + V transpose (V -> fp16 single plane)
  prep_qkv<<<3072,256>>>(comb, fcos, fsin, g_q_lc, g_k_lc, g_q_gc, g_k_gc, qp, kp, vtp);

  // 3) fused attention -> aop (fp16); PV single-term fp16
  flash_attn<<<dim3(8,32),256,FSMEM>>>(qp, kp, vtp, aop);

  // 4) merged output projections, fp16 1-term + bias  (M=2048,N=2048,K=2048,lgn1=5)
  gemm_mma<true,8,true,1><<<dim3(16,16,1),256,SM_OUT>>>(
     (const __nv_bfloat16*)aop, (const __nv_bfloat16*)wp, yy, b_local, b_global,
     2048, 5, 2048, 2048, 1024, 0,0,0, 1.f);

  // 5) final rmsnorm -> d_out
  rmsnorm_out<<<4096,256>>>(yy, g_lc_out, g_gc_out, (float*)d_out);
}

// round 15
// speedup vs baseline: 4.4126x; 1.1760x over previous
#include <cuda_runtime.h>
#include <cuda_bf16.h>
#include <cuda_fp16.h>
#include <cstdint>

// B=2, S=1024, D=1024, H=16, KVH=4, HD=64, TOT=1536
// QKV projection: bf16 mma, 2-term split ([hi|lo] storage, 3-term virtual-K).
// Attention (QK and PV) + output projection: single-term fp16 mma.
// Flash-fused attention with flat 16-chunk cp.async pipeline; base-2 softmax.

typedef unsigned long long ull;
typedef long long ll;
#define DEVFN static __device__ __forceinline__

// ---------------- PTX helpers ----------------
DEVFN uint32_t smem_u32(const void* p){
  uint32_t a; asm("{ .reg .u64 t; cvta.to.shared.u64 t, %1; cvt.u32.u64 %0, t; }":"=r"(a):"l"(p)); return a;
}
DEVFN void ldsm_x4(uint32_t* r, uint32_t addr){
  asm volatile("ldmatrix.sync.aligned.m8n8.x4.shared.b16 {%0,%1,%2,%3}, [%4];"
    : "=r"(r[0]),"=r"(r[1]),"=r"(r[2]),"=r"(r[3]) : "r"(addr));
}
DEVFN void mma16816(float* c, const uint32_t* a, const uint32_t* b){
  asm volatile("mma.sync.aligned.m16n8k16.row.col.f32.bf16.bf16.f32 "
    "{%0,%1,%2,%3}, {%4,%5,%6,%7}, {%8,%9}, {%0,%1,%2,%3};"
    : "+f"(c[0]),"+f"(c[1]),"+f"(c[2]),"+f"(c[3])
    : "r"(a[0]),"r"(a[1]),"r"(a[2]),"r"(a[3]), "r"(b[0]),"r"(b[1]));
}
DEVFN void mma16816h(float* c, const uint32_t* a, const uint32_t* b){
  asm volatile("mma.sync.aligned.m16n8k16.row.col.f32.f16.f16.f32 "
    "{%0,%1,%2,%3}, {%4,%5,%6,%7}, {%8,%9}, {%0,%1,%2,%3};"
    : "+f"(c[0]),"+f"(c[1]),"+f"(c[2]),"+f"(c[3])
    : "r"(a[0]),"r"(a[1]),"r"(a[2]),"r"(a[3]), "r"(b[0]),"r"(b[1]));
}
DEVFN void cp_async16(uint32_t dst, const void* src){
  asm volatile("cp.async.cg.shared.global [%0], [%1], 16;" :: "r"(dst), "l"(src));
}
#define CP_COMMIT() asm volatile("cp.async.commit_group;" ::: "memory")
template<int N> DEVFN void cp_waitg(){ asm volatile("cp.async.wait_group %0;"::"n"(N):"memory"); }

DEVFN void bsplit(float x, __nv_bfloat16 &hi, __nv_bfloat16 &lo){
  hi = __float2bfloat16(x);
  lo = __float2bfloat16(x - __bfloat162float(hi));
}
DEVFN uint32_t packb2(__nv_bfloat16 a, __nv_bfloat16 b){
  __nv_bfloat162 t(a, b); return *(uint32_t*)&t;
}
DEVFN uint32_t packh2(float a, float b){
  __half2 t = __floats2half2_rn(a, b); return *(uint32_t*)&t;
}

// ---------------- scratch (device globals) ----------------
__device__ __align__(128) __nv_bfloat16 g_x_pack   [2u*2048u*2048u];  // [lc|gc], rows [hi|lo]
__device__ __align__(128) __nv_bfloat16 g_wqkv_pack[2u*1536u*2048u];
__device__ __align__(128) __half        g_wpr_pack [2u*1024u*2048u];  // fp16 single plane
__device__ __align__(128) float g_comb[2u*2048u*1536u];
__device__ __align__(128) __half        g_q  [32u*1024u*128u];        // q*log2e/8, fp16
__device__ __align__(128) __half        g_k  [8u*1024u*128u];         // fp16
__device__ __align__(128) __half        g_vT [8u*128u*1024u];         // V^T fp16
__device__ __align__(128) __half        g_ao [2048u*2048u];           // attn-out fp16
__device__ __align__(128) float g_yy[4096u*1024u];

// ---------------- merged pack ----------------
// blocks: [0,1024) xl | [1024,2048) xg | [2048,2816) wlc | [2816,3584) wgc
//         [3584,4608) wlo | [4608,5632) wgo  (wpr -> fp16 single plane)
__global__ __launch_bounds__(256)
void packAll(const float* __restrict__ xl, const float* __restrict__ xg,
             const float* __restrict__ wlc, const float* __restrict__ wgc,
             const float* __restrict__ wlo, const float* __restrict__ wgo,
             __nv_bfloat16* __restrict__ xp, __nv_bfloat16* __restrict__ wq,
             __half* __restrict__ wp)
{
  int bx = blockIdx.x;
  if (bx >= 3584){
    const float* src; __half* dst;
    bx -= 3584;
    if (bx < 1024){ src = wlo; dst = wp; }
    else { src = wgo; dst = wp + 1024u*2048u; bx -= 1024; }
    int idx = (bx*256 + threadIdx.x)*8;
    float4 v0 = *(const float4*)(src + idx);
    float4 v1 = *(const float4*)(src + idx + 4);
    uint4 hv = make_uint4(packh2(v0.x,v0.y), packh2(v0.z,v0.w),
                          packh2(v1.x,v1.y), packh2(v1.z,v1.w));
    *(uint4*)(dst + idx) = hv;
    return;
  }
  const float* src; __nv_bfloat16* dst; int K;
  if (bx < 2048){
    K = 1024;
    if (bx < 1024){ src = xl; dst = xp; }
    else { src = xg; dst = xp + 2048u*2048u; bx -= 1024; }
  } else {
    K = 1024; bx -= 2048;
    if (bx < 768){ src = wlc; dst = wq; }
    else { src = wgc; dst = wq + 1536u*2048u; bx -= 768; }
  }
  int idx = (bx*256 + threadIdx.x)*8;
  float4 v0 = *(const float4*)(src + idx);
  float4 v1 = *(const float4*)(src + idx + 4);
  int r = idx / K, k = idx - r*K;
  __nv_bfloat16* d = dst + (ll)r*2*K + k;
  float vv[8] = {v0.x,v0.y,v0.z,v0.w,v1.x,v1.y,v1.z,v1.w};
  uint32_t hw[4], lw[4];
#pragma unroll
  for (int i=0;i<4;i++){
    __nv_bfloat16 h0,l0,h1,l1;
    bsplit(vv[2*i],h0,l0); bsplit(vv[2*i+1],h1,l1);
    hw[i] = packb2(h0,h1); lw[i] = packb2(l0,l1);
  }
  *(uint4*)(d)     = make_uint4(hw[0],hw[1],hw[2],hw[3]);
  *(uint4*)(d + K) = make_uint4(lw[0],lw[1],lw[2],lw[3]);
}

// ---------------- mma.sync GEMM template ----------------
#define ROWB2 144

template<bool SPLIT_N, int NT8, bool FP16, int TERMS>
__global__ __launch_bounds__(256, 2)
void gemm_mma(const __nv_bfloat16* __restrict__ A, const __nv_bfloat16* __restrict__ B,
              float* __restrict__ Cf,
              const float* __restrict__ bias0, const float* __restrict__ bias1,
              int Kreal, int lgn1, int lda, int ldb, int ldc,
              ll sA, ll sB, ll sC, float cscale)
{
  constexpr int NP    = NT8/2;
  constexpr int BROWS = NT8*16;
  constexpr int BIT   = NT8/2;
  constexpr int STGT  = (128 + BROWS)*ROWB2;

  extern __shared__ char smem[];
  const uint32_t sb = smem_u32(smem);
  const int tid = threadIdx.x, wid = tid>>5, lane = tid&31;
  const int z = blockIdx.z;
  const int m0 = blockIdx.y*128, n0 = blockIdx.x*(NT8*16);
  A += z*sA + (ll)m0*lda;
  B += z*sB + (ll)n0*ldb;
  Cf += z*sC;

  const int wm = wid>>1, wn = wid&1;
  const int n1m = (1<<lgn1) - 1;

  float acc[2][NT8][4];
#pragma unroll
  for (int i=0;i<2;i++)
#pragma unroll
    for (int j=0;j<NT8;j++)
#pragma unroll
      for (int q=0;q<4;q++) acc[i][j][q]=0.f;

  const int nch = TERMS << lgn1;

  auto loadStage = [&](int c, int s){
    int t = c >> lgn1, r = c & n1m;
    int acol = ((t==1) ? Kreal : 0) + r*64;
    int bcol = ((t==2) ? Kreal : 0) + r*64;
    const __nv_bfloat16* Ak = A + acol;
    const __nv_bfloat16* Bk = B + bcol;
    uint32_t abase = sb + s*STGT;
    uint32_t bbase = abase + 128*ROWB2;
#pragma unroll
    for (int i=0;i<4;i++){
      int f = tid + i*256;
      int rr = f>>3, q = f&7;
      cp_async16(abase + rr*ROWB2 + q*16, (const char*)(Ak + (ll)rr*lda) + q*16);
    }
#pragma unroll
    for (int i=0;i<BIT;i++){
      int f = tid + i*256;
      int rr = f>>3, q = f&7;
      cp_async16(bbase + rr*ROWB2 + q*16, (const char*)(Bk + (ll)rr*ldb) + q*16);
    }
  };

  loadStage(0, 0); CP_COMMIT();
  loadStage(1, 1); CP_COMMIT();

  for (int c=0; c<nch; c++){
    cp_waitg<1>();
    __syncthreads();
    if (c+2 < nch) loadStage(c+2, (c+2)%3);
    CP_COMMIT();

    const uint32_t abase = sb + (c%3)*STGT;
    const uint32_t bbase = abase + 128*ROWB2;
#pragma unroll
    for (int kk=0; kk<64; kk+=16){
      uint32_t a[2][4], b[NP][4];
#pragma unroll
      for (int h=0; h<2; h++)
        ldsm_x4(a[h], abase + (wm*32 + h*16 + (lane&15))*ROWB2
                             + (kk + ((lane>>4)<<3))*2);
#pragma unroll
      for (int p=0; p<NP; p++)
        ldsm_x4(b[p], bbase + (wn*(NT8*8) + p*16 + ((lane>>4)&1)*8 + (lane&7))*ROWB2
                             + (kk + (((lane>>3)&1)<<3))*2);
#pragma unroll
      for (int mi=0; mi<2; mi++)
#pragma unroll
        for (int p=0; p<NP; p++){
          if (FP16){
            mma16816h(acc[mi][2*p+0], a[mi], &b[p][0]);
            mma16816h(acc[mi][2*p+1], a[mi], &b[p][2]);
          } else {
            mma16816(acc[mi][2*p+0], a[mi], &b[p][0]);
            mma16816(acc[mi][2*p+1], a[mi], &b[p][2]);
          }
        }
    }
  }

#pragma unroll
  for (int mi=0; mi<2; mi++){
#pragma unroll
    for (int ni=0; ni<NT8; ni++){
      int mrow = m0 + wm*32 + mi*16 + (lane>>2);
      int ncol = n0 + wn*(NT8*8) + ni*8 + (lane&3)*2;
#pragma unroll
      for (int hh=0; hh<2; hh++){
        int m = mrow + hh*8;
        float v0 = acc[mi][ni][2*hh+0]*cscale;
        float v1 = acc[mi][ni][2*hh+1]*cscale;
        if (SPLIT_N){
          int nl = ncol & 1023;
          const float* bs = (ncol >= 1024) ? bias1 : bias0;
          v0 += bs[nl]; v1 += bs[nl+1];
          float* dst = Cf + ((ncol >= 1024) ? 2097152LL : 0LL) + (ll)m*1024 + nl;
          *(float2*)dst = make_float2(v0,v1);
        } else {
          *(float2*)(Cf + (ll)m*ldc + ncol) = make_float2(v0,v1);
        }
      }
    }
  }
}

// ---------------- fused flash attention (all fp16 single-term) ----------------
// Flat pipeline: 16 K chunks (8 nc x 2 halves of HD=128), slot = g%3.
// V(nc) halves ride in the same groups as K chunks 2nc / 2nc+1; V double-buffered.
#define QROWB 272     // 256B (128 fp16) + 16 pad
#define KROWB 144     // 128B (64 fp16) + 16 pad
#define KSLOT 18432   // 128*144
#define VROWB 272
#define VBUF  34816   // 128*272
#define OFF_K  34816                  // Q = 128*272
#define OFF_V  90112                  // OFF_K + 3*KSLOT
#define FSMEM  159744                 // OFF_V + 2*VBUF

DEVFN void flash_issueK(uint32_t sb, const __half* Kc, int kcol, int slot, int tid){
  uint32_t kb = sb + OFF_K + slot*KSLOT;
#pragma unroll
  for (int i=0;i<4;i++){
    int f = tid + i*256;
    int r = f>>3, q = f&7;
    cp_async16(kb + r*KROWB + q*16, (const char*)(Kc + (ll)r*128 + kcol) + q*16);
  }
}
// half in {0,1}: rows [half*64, half*64+64) of the 128-row fp16 V tile
DEVFN void flash_issueV(uint32_t sb, const __half* Vc, int vbuf, int half, int tid){
  uint32_t vb = sb + OFF_V + vbuf*VBUF;
#pragma unroll
  for (int i=0;i<4;i++){
    int f = tid + i*256;
    int r = half*64 + (f>>4), c = f&15;
    cp_async16(vb + r*VROWB + c*16, (const char*)(Vc + (ll)r*1024) + c*16);
  }
}

__global__ __launch_bounds__(256, 1)
void flash_attn(const __half* __restrict__ qp,
                const __half* __restrict__ kp,
                const __half* __restrict__ vtp,
                __half* __restrict__ aop)
{
  extern __shared__ char smem[];
  const uint32_t sb = smem_u32(smem);
  const int tid = threadIdx.x, wid = tid>>5, lane = tid&31;
  const int z = blockIdx.y, b = z>>4, h = z&15;
  const int s0 = blockIdx.x*128;
  const __half* Qb = qp + ((ll)z*1024 + s0)*128;
  const __half* Kb = kp + (ll)(z>>2)*1024*128;
  const __half* Vb = vtp + (ll)(z>>2)*128*1024;

  // Q tile (128 x 128 fp16)
#pragma unroll
  for (int i=0;i<8;i++){
    int f = tid + i*256;
    int r = f>>4, c = f&15;
    cp_async16(sb + r*QROWB + c*16, (const char*)(Qb + (ll)r*128) + c*16);
  }
  CP_COMMIT();

  auto issueG = [&](int g){
    if (g < 16){
      int nc2 = g>>1, half = g&1;
      flash_issueK(sb, Kb + (ll)(nc2*128)*128, half*64, g%3, tid);
      flash_issueV(sb, Vb + nc2*128, nc2&1, half, tid);
    }
    CP_COMMIT();
  };
  issueG(0); issueG(1);

  float m0=-1e30f, m1=-1e30f, l0=0.f, l1=0.f;
  float o[16][4];
#pragma unroll
  for (int ni=0;ni<16;ni++){ o[ni][0]=0.f;o[ni][1]=0.f;o[ni][2]=0.f;o[ni][3]=0.f; }

#pragma unroll 1
  for (int nc=0; nc<8; nc++){
    float acc[16][4];
#pragma unroll
    for (int ni=0;ni<16;ni++){ acc[ni][0]=0.f;acc[ni][1]=0.f;acc[ni][2]=0.f;acc[ni][3]=0.f; }

#pragma unroll
    for (int kc=0; kc<2; kc++){
      const int g = nc*2 + kc;
      cp_waitg<1>();            // K(g) + V(nc, half kc) complete
      __syncthreads();
      issueG(g+2);
      const uint32_t kb = sb + OFF_K + (g%3)*KSLOT;
      const int qc = kc*64;
#pragma unroll
      for (int kk=0; kk<64; kk+=16){
        uint32_t a[4];
        ldsm_x4(a, sb + (wid*16 + (lane&15))*QROWB + (qc + kk + ((lane>>4)<<3))*2);
        uint32_t bf[8][4];
#pragma unroll
        for (int p=0;p<8;p++)
          ldsm_x4(bf[p], kb + (p*16 + ((lane>>4)&1)*8 + (lane&7))*KROWB
                            + (kk + (((lane>>3)&1)<<3))*2);
#pragma unroll
        for (int p=0;p<8;p++){
          mma16816h(acc[2*p+0], a, &bf[p][0]);
          mma16816h(acc[2*p+1], a, &bf[p][2]);
        }
      }
    }

    // ---- online softmax (base-2; log2e folded into q scale) ----
    float cm0=-1e30f, cm1=-1e30f;
#pragma unroll
    for (int ni=0;ni<16;ni++){
      cm0 = fmaxf(cm0, fmaxf(acc[ni][0], acc[ni][1]));
      cm1 = fmaxf(cm1, fmaxf(acc[ni][2], acc[ni][3]));
    }
    cm0 = fmaxf(cm0, __shfl_xor_sync(0xffffffffu, cm0, 1));
    cm0 = fmaxf(cm0, __shfl_xor_sync(0xffffffffu, cm0, 2));
    cm1 = fmaxf(cm1, __shfl_xor_sync(0xffffffffu, cm1, 1));
    cm1 = fmaxf(cm1, __shfl_xor_sync(0xffffffffu, cm1, 2));
    float mn0 = fmaxf(m0, cm0), mn1 = fmaxf(m1, cm1);
    float sc0 = exp2f(m0 - mn0), sc1 = exp2f(m1 - mn1);
    m0 = mn0; m1 = mn1;
    float rs0=0.f, rs1=0.f;
#pragma unroll
    for (int ni=0;ni<16;ni++){
      acc[ni][0]=exp2f(acc[ni][0]-m0); acc[ni][1]=exp2f(acc[ni][1]-m0);
      acc[ni][2]=exp2f(acc[ni][2]-m1); acc[ni][3]=exp2f(acc[ni][3]-m1);
      rs0 += acc[ni][0]+acc[ni][1];
      rs1 += acc[ni][2]+acc[ni][3];
    }
    rs0 += __shfl_xor_sync(0xffffffffu, rs0, 1);
    rs0 += __shfl_xor_sync(0xffffffffu, rs0, 2);
    rs1 += __shfl_xor_sync(0xffffffffu, rs1, 1);
    rs1 += __shfl_xor_sync(0xffffffffu, rs1, 2);
    l0 = l0*sc0 + rs0;
    l1 = l1*sc1 + rs1;
#pragma unroll
    for (int ni=0;ni<16;ni++){
      o[ni][0]*=sc0; o[ni][1]*=sc0; o[ni][2]*=sc1; o[ni][3]*=sc1;
    }

    // ---- PV: single-term fp16 on V buffer nc&1 (already waited + synced) ----
    const uint32_t vb = sb + OFF_V + (nc&1)*VBUF;
#pragma unroll
    for (int kg=0; kg<8; kg++){
      uint32_t ap[4];
      ap[0] = packh2(acc[2*kg][0],   acc[2*kg][1]);
      ap[1] = packh2(acc[2*kg][2],   acc[2*kg][3]);
      ap[2] = packh2(acc[2*kg+1][0], acc[2*kg+1][1]);
      ap[3] = packh2(acc[2*kg+1][2], acc[2*kg+1][3]);
#pragma unroll
      for (int p=0;p<8;p++){
        uint32_t bh[4];
        ldsm_x4(bh, vb + (p*16 + ((lane>>4)&1)*8 + (lane&7))*VROWB
                       + (kg*16 + (((lane>>3)&1)<<3))*2);
        mma16816h(o[2*p+0], ap, &bh[0]);
        mma16816h(o[2*p+1], ap, &bh[2]);
      }
    }
    // next nc's kc=0 wait+sync orders V buffer reuse (overwrite is 2 nc away)
  }

  // ---- epilogue: normalize -> fp16 aop ----
  const float inv0 = 1.f/l0, inv1 = 1.f/l1;
  const int qrow0 = s0 + wid*16 + (lane>>2);
  const ll rb0 = ((ll)(b*1024 + qrow0))*2048 + h*128;
  const ll rb1 = rb0 + 8LL*2048;
#pragma unroll
  for (int ni=0;ni<16;ni++){
    int col = ni*8 + (lane&3)*2;
    *(uint32_t*)(aop + rb0 + col) = packh2(o[ni][0]*inv0, o[ni][1]*inv0);
    *(uint32_t*)(aop + rb1 + col) = packh2(o[ni][2]*inv1, o[ni][3]*inv1);
  }
}

// ---------------- merged prep: RMSNorm+RoPE (fp16 q/k) | V transpose ----------------
__global__ __launch_bounds__(256)
void prep_qkv(const float* __restrict__ comb,
              const float* __restrict__ cosT, const float* __restrict__ sinT,
              const float* __restrict__ gql, const float* __restrict__ gkl,
              const float* __restrict__ gqg, const float* __restrict__ gkg,
              __half* __restrict__ qp, __half* __restrict__ kp,
              __half* __restrict__ vp)
{
  __shared__ float shbuf[32*33];
  const int t = threadIdx.x;

  if (blockIdx.x >= 2048){
    int b2 = blockIdx.x - 2048;
    const int s0 = (b2 & 31)*32;
    const int c0 = ((b2>>5)&7)*32;
    const int zz = b2>>8;
    const int b = zz>>1, strm = zz&1;
    float (*tt)[33] = (float(*)[33])shbuf;
    const int tx = t&31, ty = t>>5;
    const float* base = comb + (ll)strm*2048*1536;
#pragma unroll
    for (int r=0;r<32;r+=8)
      tt[ty+r][tx] = base[(ll)(b*1024 + s0+ty+r)*1536 + 1280 + c0 + tx];
    __syncthreads();
#pragma unroll
    for (int r=0;r<32;r+=8){
      int v = c0 + ty + r;
      int kh = v>>6, d = v&63;
      ll row = (ll)(b*4+kh)*128 + strm*64 + d;
      vp[row*1024 + s0 + tx] = __float2half_rn(tt[tx][ty+r]);
    }
    return;
  }

  const int bs = blockIdx.x;
  const int b = bs >> 10, s = bs & 1023;
  const float* rl = comb + (ll)bs*1536;
  const float* rg = rl + (ll)2048*1536;

  float sql=0.f, sqg=0.f;
#pragma unroll
  for (int i=t;i<1024;i+=256){ float x=rl[i]; sql+=x*x; float y=rg[i]; sqg+=y*y; }
  float xk=rl[1024+t], yk=rg[1024+t];
  float skl = xk*xk, skg = yk*yk;

  float4* red = (float4*)shbuf;
  float4 v4 = make_float4(sql,sqg,skl,skg);
#pragma unroll
  for (int off=16;off;off>>=1){
    v4.x += __shfl_xor_sync(0xffffffffu, v4.x, off);
    v4.y += __shfl_xor_sync(0xffffffffu, v4.y, off);
    v4.z += __shfl_xor_sync(0xffffffffu, v4.z, off);
    v4.w += __shfl_xor_sync(0xffffffffu, v4.w, off);
  }
  const int w = t>>5, l = t&31;
  if (!l) red[w]=v4;
  __syncthreads();
  if (t==0){
    float4 a = red[0];
    for (int i=1;i<8;i++){ a.x+=red[i].x; a.y+=red[i].y; a.z+=red[i].z; a.w+=red[i].w; }
    red[0]=a;
  }
  __syncthreads();
  float4 tot = red[0];
  const float QF = 0.125f * 1.4426950408889634f;   // /8 and log2e folded into q
  const float rql = rsqrtf(tot.x*(1.f/1024.f)+1e-5f) * QF;
  const float rqg = rsqrtf(tot.y*(1.f/1024.f)+1e-5f) * QF;
  const float rkl = rsqrtf(tot.z*(1.f/256.f)+1e-5f);
  const float rkg = rsqrtf(tot.w*(1.f/256.f)+1e-5f);

  // q rows: [(b*16+h)*1024+s] x 128 fp16  (lc 0..63 | gc 64..127)
#pragma unroll
  for (int pp=t; pp<512; pp+=256){
    int h = pp>>5, p = pp&31;
    float c = cosT[s*32+p], sn = sinT[s*32+p];
    int d0 = h*64 + 2*p;
    ll base = (((ll)(b*16+h))*1024 + s)*128;
    float x0 = rl[d0]*rql*gql[d0];
    float x1 = rl[d0+1]*rql*gql[d0+1];
    float y0 = rg[d0]*rqg*gqg[d0];
    float y1 = rg[d0+1]*rqg*gqg[d0+1];
    *(uint32_t*)(qp+base+2*p)    = packh2(x0*c - x1*sn, x0*sn + x1*c);
    *(uint32_t*)(qp+base+64+2*p) = packh2(y0*c - y1*sn, y0*sn + y1*c);
  }
  // k rows: [(b*4+kh)*1024+s] x 128 fp16
  if (t < 128){
    int kh = t>>5, p = t&31;
    float c = cosT[s*32+p], sn = sinT[s*32+p];
    int gd = kh*64 + 2*p;
    ll base = (((ll)(b*4+kh))*1024 + s)*128;
    float x0 = rl[1024+gd]*rkl*gkl[gd];
    float x1 = rl[1024+gd+1]*rkl*gkl[gd+1];
    float y0 = rg[1024+gd]*rkg*gkg[gd];
    float y1 = rg[1024+gd+1]*rkg*gkg[gd+1];
    *(uint32_t*)(kp+base+2*p)    = packh2(x0*c - x1*sn, x0*sn + x1*c);
    *(uint32_t*)(kp+base+64+2*p) = packh2(y0*c - y1*sn, y0*sn + y1*c);
  }
}

// ---------------- final RMSNorm -> d_out ----------------
__global__ __launch_bounds__(256)
void rmsnorm_out(const float* __restrict__ y, const float* __restrict__ glc,
                 const float* __restrict__ ggc, float* __restrict__ out)
{
  const int row = blockIdx.x;
  const float* g = (row < 2048) ? glc : ggc;
  const float* r = y + (ll)row*1024;
  float* o = out + (ll)row*1024;
  const int t = threadIdx.x;
  float4 v = ((const float4*)r)[t];
  float ss = v.x*v.x + v.y*v.y + v.z*v.z + v.w*v.w;
  __shared__ float sm[8];
#pragma unroll
  for (int o2=16;o2;o2>>=1) ss += __shfl_xor_sync(0xffffffffu,ss,o2);
  const int w=t>>5, l=t&31;
  if (!l) sm[w]=ss;
  __syncthreads();
  ss = sm[0]+sm[1]+sm[2]+sm[3]+sm[4]+sm[5]+sm[6]+sm[7];
  const float rsq = rsqrtf(ss*(1.f/1024.f)+1e-5f);
  float4 gv = ((const float4*)g)[t];
  float4 ov = make_float4(v.x*rsq*gv.x, v.y*rsq*gv.y, v.z*rsq*gv.z, v.w*rsq*gv.w);
  ((float4*)o)[t]=ov;
}

// ---------------- launch ----------------
extern "C" void kernel_launch(void* const* d_in, const int* in_sizes, int n_in,
                              void* d_out, int out_size)
{
  (void)in_sizes; (void)n_in; (void)out_size;
  const float* local_c  = (const float*)d_in[0];
  const float* global_c = (const float*)d_in[1];
  const float* fcos     = (const float*)d_in[2];
  const float* fsin     = (const float*)d_in[3];
  const float* W_lc     = (const float*)d_in[4];
  const float* W_gc     = (const float*)d_in[5];
  const float* g_q_lc   = (const float*)d_in[6];
  const float* g_k_lc   = (const float*)d_in[7];
  const float* g_q_gc   = (const float*)d_in[8];
  const float* g_k_gc   = (const float*)d_in[9];
  const float* W_local  = (const float*)d_in[10];
  const float* b_local  = (const float*)d_in[11];
  const float* g_lc_out = (const float*)d_in[12];
  const float* W_global = (const float*)d_in[13];
  const float* b_global = (const float*)d_in[14];
  const float* g_gc_out = (const float*)d_in[15];

  __nv_bfloat16 *xp,*wq;
  __half *wp,*qp,*kp,*vtp,*aop;
  float *comb,*yy;
  cudaGetSymbolAddress((void**)&xp,  g_x_pack);
  cudaGetSymbolAddress((void**)&wq,  g_wqkv_pack);
  cudaGetSymbolAddress((void**)&wp,  g_wpr_pack);
  cudaGetSymbolAddress((void**)&comb, g_comb);
  cudaGetSymbolAddress((void**)&qp,  g_q);
  cudaGetSymbolAddress((void**)&kp,  g_k);
  cudaGetSymbolAddress((void**)&vtp, g_vT);
  cudaGetSymbolAddress((void**)&aop, g_ao);
  cudaGetSymbolAddress((void**)&yy,  g_yy);

  const int SM_QKV = 3*((128+96)*144);   // 96768
  const int SM_OUT = 3*((128+128)*144);  // 110592
  static int attr_done = 0;
  if (!attr_done){
    cudaFuncSetAttribute((const void*)gemm_mma<false,6,false,3>,
                         cudaFuncAttributeMaxDynamicSharedMemorySize, SM_QKV);
    cudaFuncSetAttribute((const void*)gemm_mma<true,8,true,1>,
                         cudaFuncAttributeMaxDynamicSharedMemorySize, SM_OUT);
    cudaFuncSetAttribute((const void*)flash_attn,
                         cudaFuncAttributeMaxDynamicSharedMemorySize, FSMEM);
    attr_done = 1;
  }

  // 0) operand packs
  packAll<<<5632,256>>>(local_c, global_c, W_lc, W_gc, W_local, W_global, xp, wq, wp);

  // 1) QKV projections, bf16 3-term, N-tile 96  (M=2048,N=1536,K=1024,lgn1=4)
  gemm_mma<false,6,false,3><<<dim3(16,16,2),256,SM_QKV>>>(xp, wq, comb, nullptr, nullptr,
     1024, 4, 2048, 2048, 1536, 2048LL*2048, 1536LL*2048, 2048LL*1536, 1.f);

  // 2) merged rmsnorm+rope (fp16 q/k) + V transpose (fp16)
  prep_qkv<<<3072,256>>>(comb, fcos, fsin, g_q_lc, g_k_lc, g_q_gc, g_k_gc, qp, kp, vtp);

  // 3) fused attention, all fp16 -> aop
  flash_attn<<<dim3(8,32),256,FSMEM>>>(qp, kp, vtp, aop);

  // 4) merged output projections, fp16 1-term + bias  (M=2048,N=2048,K=2048,lgn1=5)
  gemm_mma<true,8,true,1><<<dim3(16,16,1),256,SM_OUT>>>(
     (const __nv_bfloat16*)aop, (const __nv_bfloat16*)wp, yy, b_local, b_global,
     2048, 5, 2048, 2048, 1024, 0,0,0, 1.f);

  // 5) final rmsnorm -> d_out
  rmsnorm_out<<<4096,256>>>(yy, g_lc_out, g_gc_out, (float*)d_out);
}

// round 16
// speedup vs baseline: 5.1869x; 1.1755x over previous
#include <cuda_runtime.h>
#include <cuda_bf16.h>
#include <cuda_fp16.h>
#include <cstdint>

// B=2, S=1024, D=1024, H=16, KVH=4, HD=64, TOT=1536
// QKV projection: fp16 mma, 2-term (x split [hi|lo] exactly; W single fp16).
// Attention (QK, PV) + output projection: single-term fp16 mma.
// Flash-fused attention, flat 16-chunk cp.async pipeline; base-2 softmax.

typedef unsigned long long ull;
typedef long long ll;
#define DEVFN static __device__ __forceinline__

// ---------------- PTX helpers ----------------
DEVFN uint32_t smem_u32(const void* p){
  uint32_t a; asm("{ .reg .u64 t; cvta.to.shared.u64 t, %1; cvt.u32.u64 %0, t; }":"=r"(a):"l"(p)); return a;
}
DEVFN void ldsm_x4(uint32_t* r, uint32_t addr){
  asm volatile("ldmatrix.sync.aligned.m8n8.x4.shared.b16 {%0,%1,%2,%3}, [%4];"
    : "=r"(r[0]),"=r"(r[1]),"=r"(r[2]),"=r"(r[3]) : "r"(addr));
}
DEVFN void mma16816h(float* c, const uint32_t* a, const uint32_t* b){
  asm volatile("mma.sync.aligned.m16n8k16.row.col.f32.f16.f16.f32 "
    "{%0,%1,%2,%3}, {%4,%5,%6,%7}, {%8,%9}, {%0,%1,%2,%3};"
    : "+f"(c[0]),"+f"(c[1]),"+f"(c[2]),"+f"(c[3])
    : "r"(a[0]),"r"(a[1]),"r"(a[2]),"r"(a[3]), "r"(b[0]),"r"(b[1]));
}
DEVFN void cp_async16(uint32_t dst, const void* src){
  asm volatile("cp.async.cg.shared.global [%0], [%1], 16;" :: "r"(dst), "l"(src));
}
#define CP_COMMIT() asm volatile("cp.async.commit_group;" ::: "memory")
template<int N> DEVFN void cp_waitg(){ asm volatile("cp.async.wait_group %0;"::"n"(N):"memory"); }

DEVFN uint32_t packh2(float a, float b){
  __half2 t = __floats2half2_rn(a, b); return *(uint32_t*)&t;
}
DEVFN void hsplit(float x, __half &hi, __half &lo){
  hi = __float2half_rn(x);
  lo = __float2half_rn(x - __half2float(hi));
}
DEVFN uint32_t packhh(__half a, __half b){
  __half2 t(a, b); return *(uint32_t*)&t;
}

// ---------------- scratch (device globals) ----------------
__device__ __align__(128) __half g_x_pack   [2u*2048u*2048u];  // [lc|gc], rows [hi|lo] fp16
__device__ __align__(128) __half g_wqkv_pack[2u*1536u*1024u];  // fp16 single plane
__device__ __align__(128) __half g_wpr_pack [2u*1024u*2048u];  // fp16 single plane
__device__ __align__(128) float g_comb[2u*2048u*1536u];
__device__ __align__(128) __half g_q  [32u*1024u*128u];        // q*log2e/8, fp16
__device__ __align__(128) __half g_k  [8u*1024u*128u];         // fp16
__device__ __align__(128) __half g_vT [8u*128u*1024u];         // V^T fp16
__device__ __align__(128) __half g_ao [2048u*2048u];           // attn-out fp16
__device__ __align__(128) float g_yy[4096u*1024u];

// ---------------- merged pack ----------------
// blocks: [0,1024) xl split | [1024,2048) xg split | [2048,2816) wlc single
//         [2816,3584) wgc single | [3584,4608) wlo single | [4608,5632) wgo single
__global__ __launch_bounds__(256)
void packAll(const float* __restrict__ xl, const float* __restrict__ xg,
             const float* __restrict__ wlc, const float* __restrict__ wgc,
             const float* __restrict__ wlo, const float* __restrict__ wgo,
             __half* __restrict__ xp, __half* __restrict__ wq,
             __half* __restrict__ wp)
{
  int bx = blockIdx.x;
  if (bx >= 2048){
    // single-plane fp16 packs (layout identical to source)
    const float* src; __half* dst;
    if (bx < 3584){
      bx -= 2048;
      if (bx < 768){ src = wlc; dst = wq; }
      else { src = wgc; dst = wq + 1536u*1024u; bx -= 768; }
    } else {
      bx -= 3584;
      if (bx < 1024){ src = wlo; dst = wp; }
      else { src = wgo; dst = wp + 1024u*2048u; bx -= 1024; }
    }
    int idx = (bx*256 + threadIdx.x)*8;
    float4 v0 = *(const float4*)(src + idx);
    float4 v1 = *(const float4*)(src + idx + 4);
    uint4 hv = make_uint4(packh2(v0.x,v0.y), packh2(v0.z,v0.w),
                          packh2(v1.x,v1.y), packh2(v1.z,v1.w));
    *(uint4*)(dst + idx) = hv;
    return;
  }
  // x split pack: [R x 1024] f32 -> [R x 2048] fp16 [hi|lo]
  const float* src; __half* dst;
  if (bx < 1024){ src = xl; dst = xp; }
  else { src = xg; dst = xp + 2048u*2048u; bx -= 1024; }
  int idx = (bx*256 + threadIdx.x)*8;
  float4 v0 = *(const float4*)(src + idx);
  float4 v1 = *(const float4*)(src + idx + 4);
  int r = idx >> 10, k = idx & 1023;
  __half* d = dst + (ll)r*2048 + k;
  float vv[8] = {v0.x,v0.y,v0.z,v0.w,v1.x,v1.y,v1.z,v1.w};
  uint32_t hw[4], lw[4];
#pragma unroll
  for (int i=0;i<4;i++){
    __half h0,l0,h1,l1;
    hsplit(vv[2*i],h0,l0); hsplit(vv[2*i+1],h1,l1);
    hw[i] = packhh(h0,h1); lw[i] = packhh(l0,l1);
  }
  *(uint4*)(d)        = make_uint4(hw[0],hw[1],hw[2],hw[3]);
  *(uint4*)(d + 1024) = make_uint4(lw[0],lw[1],lw[2],lw[3]);
}

// ---------------- mma.sync GEMM template (fp16) ----------------
// TERMS virtual-K terms over A cols {0, Kreal, ...}; B col offset only at t==2.
#define ROWB2 144

template<bool SPLIT_N, int NT8, int TERMS>
__global__ __launch_bounds__(256, 2)
void gemm_mma(const __half* __restrict__ A, const __half* __restrict__ B,
              float* __restrict__ Cf,
              const float* __restrict__ bias0, const float* __restrict__ bias1,
              int Kreal, int lgn1, int lda, int ldb, int ldc,
              ll sA, ll sB, ll sC, float cscale)
{
  constexpr int NP    = NT8/2;
  constexpr int BROWS = NT8*16;
  constexpr int BIT   = NT8/2;
  constexpr int STGT  = (128 + BROWS)*ROWB2;

  extern __shared__ char smem[];
  const uint32_t sb = smem_u32(smem);
  const int tid = threadIdx.x, wid = tid>>5, lane = tid&31;
  const int z = blockIdx.z;
  const int m0 = blockIdx.y*128, n0 = blockIdx.x*(NT8*16);
  A += z*sA + (ll)m0*lda;
  B += z*sB + (ll)n0*ldb;
  Cf += z*sC;

  const int wm = wid>>1, wn = wid&1;
  const int n1m = (1<<lgn1) - 1;

  float acc[2][NT8][4];
#pragma unroll
  for (int i=0;i<2;i++)
#pragma unroll
    for (int j=0;j<NT8;j++)
#pragma unroll
      for (int q=0;q<4;q++) acc[i][j][q]=0.f;

  const int nch = TERMS << lgn1;

  auto loadStage = [&](int c, int s){
    int t = c >> lgn1, r = c & n1m;
    int acol = ((t==1) ? Kreal : 0) + r*64;
    int bcol = ((t==2) ? Kreal : 0) + r*64;
    const __half* Ak = A + acol;
    const __half* Bk = B + bcol;
    uint32_t abase = sb + s*STGT;
    uint32_t bbase = abase + 128*ROWB2;
#pragma unroll
    for (int i=0;i<4;i++){
      int f = tid + i*256;
      int rr = f>>3, q = f&7;
      cp_async16(abase + rr*ROWB2 + q*16, (const char*)(Ak + (ll)rr*lda) + q*16);
    }
#pragma unroll
    for (int i=0;i<BIT;i++){
      int f = tid + i*256;
      int rr = f>>3, q = f&7;
      cp_async16(bbase + rr*ROWB2 + q*16, (const char*)(Bk + (ll)rr*ldb) + q*16);
    }
  };

  loadStage(0, 0); CP_COMMIT();
  loadStage(1, 1); CP_COMMIT();

  for (int c=0; c<nch; c++){
    cp_waitg<1>();
    __syncthreads();
    if (c+2 < nch) loadStage(c+2, (c+2)%3);
    CP_COMMIT();

    const uint32_t abase = sb + (c%3)*STGT;
    const uint32_t bbase = abase + 128*ROWB2;
#pragma unroll
    for (int kk=0; kk<64; kk+=16){
      uint32_t a[2][4], b[NP][4];
#pragma unroll
      for (int h=0; h<2; h++)
        ldsm_x4(a[h], abase + (wm*32 + h*16 + (lane&15))*ROWB2
                             + (kk + ((lane>>4)<<3))*2);
#pragma unroll
      for (int p=0; p<NP; p++)
        ldsm_x4(b[p], bbase + (wn*(NT8*8) + p*16 + ((lane>>4)&1)*8 + (lane&7))*ROWB2
                             + (kk + (((lane>>3)&1)<<3))*2);
#pragma unroll
      for (int mi=0; mi<2; mi++)
#pragma unroll
        for (int p=0; p<NP; p++){
          mma16816h(acc[mi][2*p+0], a[mi], &b[p][0]);
          mma16816h(acc[mi][2*p+1], a[mi], &b[p][2]);
        }
    }
  }

#pragma unroll
  for (int mi=0; mi<2; mi++){
#pragma unroll
    for (int ni=0; ni<NT8; ni++){
      int mrow = m0 + wm*32 + mi*16 + (lane>>2);
      int ncol = n0 + wn*(NT8*8) + ni*8 + (lane&3)*2;
#pragma unroll
      for (int hh=0; hh<2; hh++){
        int m = mrow + hh*8;
        float v0 = acc[mi][ni][2*hh+0]*cscale;
        float v1 = acc[mi][ni][2*hh+1]*cscale;
        if (SPLIT_N){
          int nl = ncol & 1023;
          const float* bs = (ncol >= 1024) ? bias1 : bias0;
          v0 += bs[nl]; v1 += bs[nl+1];
          float* dst = Cf + ((ncol >= 1024) ? 2097152LL : 0LL) + (ll)m*1024 + nl;
          *(float2*)dst = make_float2(v0,v1);
        } else {
          *(float2*)(Cf + (ll)m*ldc + ncol) = make_float2(v0,v1);
        }
      }
    }
  }
}

// ---------------- fused flash attention (all fp16 single-term) ----------------
#define QROWB 272     // 256B (128 fp16) + 16 pad
#define KROWB 144     // 128B (64 fp16) + 16 pad
#define KSLOT 18432   // 128*144
#define VROWB 272
#define VBUF  34816   // 128*272
#define OFF_K  34816                  // Q = 128*272
#define OFF_V  90112                  // OFF_K + 3*KSLOT
#define FSMEM  159744                 // OFF_V + 2*VBUF

DEVFN void flash_issueK(uint32_t sb, const __half* Kc, int kcol, int slot, int tid){
  uint32_t kb = sb + OFF_K + slot*KSLOT;
#pragma unroll
  for (int i=0;i<4;i++){
    int f = tid + i*256;
    int r = f>>3, q = f&7;
    cp_async16(kb + r*KROWB + q*16, (const char*)(Kc + (ll)r*128 + kcol) + q*16);
  }
}
DEVFN void flash_issueV(uint32_t sb, const __half* Vc, int vbuf, int half, int tid){
  uint32_t vb = sb + OFF_V + vbuf*VBUF;
#pragma unroll
  for (int i=0;i<4;i++){
    int f = tid + i*256;
    int r = half*64 + (f>>4), c = f&15;
    cp_async16(vb + r*VROWB + c*16, (const char*)(Vc + (ll)r*1024) + c*16);
  }
}

__global__ __launch_bounds__(256, 1)
void flash_attn(const __half* __restrict__ qp,
                const __half* __restrict__ kp,
                const __half* __restrict__ vtp,
                __half* __restrict__ aop)
{
  extern __shared__ char smem[];
  const uint32_t sb = smem_u32(smem);
  const int tid = threadIdx.x, wid = tid>>5, lane = tid&31;
  const int z = blockIdx.y, b = z>>4, h = z&15;
  const int s0 = blockIdx.x*128;
  const __half* Qb = qp + ((ll)z*1024 + s0)*128;
  const __half* Kb = kp + (ll)(z>>2)*1024*128;
  const __half* Vb = vtp + (ll)(z>>2)*128*1024;

#pragma unroll
  for (int i=0;i<8;i++){
    int f = tid + i*256;
    int r = f>>4, c = f&15;
    cp_async16(sb + r*QROWB + c*16, (const char*)(Qb + (ll)r*128) + c*16);
  }
  CP_COMMIT();

  auto issueG = [&](int g){
    if (g < 16){
      int nc2 = g>>1, half = g&1;
      flash_issueK(sb, Kb + (ll)(nc2*128)*128, half*64, g%3, tid);
      flash_issueV(sb, Vb + nc2*128, nc2&1, half, tid);
    }
    CP_COMMIT();
  };
  issueG(0); issueG(1);

  float m0=-1e30f, m1=-1e30f, l0=0.f, l1=0.f;
  float o[16][4];
#pragma unroll
  for (int ni=0;ni<16;ni++){ o[ni][0]=0.f;o[ni][1]=0.f;o[ni][2]=0.f;o[ni][3]=0.f; }

#pragma unroll 1
  for (int nc=0; nc<8; nc++){
    float acc[16][4];
#pragma unroll
    for (int ni=0;ni<16;ni++){ acc[ni][0]=0.f;acc[ni][1]=0.f;acc[ni][2]=0.f;acc[ni][3]=0.f; }

#pragma unroll
    for (int kc=0; kc<2; kc++){
      const int g = nc*2 + kc;
      cp_waitg<1>();
      __syncthreads();
      issueG(g+2);
      const uint32_t kb = sb + OFF_K + (g%3)*KSLOT;
      const int qc = kc*64;
#pragma unroll
      for (int kk=0; kk<64; kk+=16){
        uint32_t a[4];
        ldsm_x4(a, sb + (wid*16 + (lane&15))*QROWB + (qc + kk + ((lane>>4)<<3))*2);
        uint32_t bf[8][4];
#pragma unroll
        for (int p=0;p<8;p++)
          ldsm_x4(bf[p], kb + (p*16 + ((lane>>4)&1)*8 + (lane&7))*KROWB
                            + (kk + (((lane>>3)&1)<<3))*2);
#pragma unroll
        for (int p=0;p<8;p++){
          mma16816h(acc[2*p+0], a, &bf[p][0]);
          mma16816h(acc[2*p+1], a, &bf[p][2]);
        }
      }
    }

    // ---- online softmax (base-2) ----
    float cm0=-1e30f, cm1=-1e30f;
#pragma unroll
    for (int ni=0;ni<16;ni++){
      cm0 = fmaxf(cm0, fmaxf(acc[ni][0], acc[ni][1]));
      cm1 = fmaxf(cm1, fmaxf(acc[ni][2], acc[ni][3]));
    }
    cm0 = fmaxf(cm0, __shfl_xor_sync(0xffffffffu, cm0, 1));
    cm0 = fmaxf(cm0, __shfl_xor_sync(0xffffffffu, cm0, 2));
    cm1 = fmaxf(cm1, __shfl_xor_sync(0xffffffffu, cm1, 1));
    cm1 = fmaxf(cm1, __shfl_xor_sync(0xffffffffu, cm1, 2));
    float mn0 = fmaxf(m0, cm0), mn1 = fmaxf(m1, cm1);
    float sc0 = exp2f(m0 - mn0), sc1 = exp2f(m1 - mn1);
    m0 = mn0; m1 = mn1;
    float rs0=0.f, rs1=0.f;
#pragma unroll
    for (int ni=0;ni<16;ni++){
      acc[ni][0]=exp2f(acc[ni][0]-m0); acc[ni][1]=exp2f(acc[ni][1]-m0);
      acc[ni][2]=exp2f(acc[ni][2]-m1); acc[ni][3]=exp2f(acc[ni][3]-m1);
      rs0 += acc[ni][0]+acc[ni][1];
      rs1 += acc[ni][2]+acc[ni][3];
    }
    rs0 += __shfl_xor_sync(0xffffffffu, rs0, 1);
    rs0 += __shfl_xor_sync(0xffffffffu, rs0, 2);
    rs1 += __shfl_xor_sync(0xffffffffu, rs1, 1);
    rs1 += __shfl_xor_sync(0xffffffffu, rs1, 2);
    l0 = l0*sc0 + rs0;
    l1 = l1*sc1 + rs1;
#pragma unroll
    for (int ni=0;ni<16;ni++){
      o[ni][0]*=sc0; o[ni][1]*=sc0; o[ni][2]*=sc1; o[ni][3]*=sc1;
    }

    // ---- PV: single-term fp16 ----
    const uint32_t vb = sb + OFF_V + (nc&1)*VBUF;
#pragma unroll
    for (int kg=0; kg<8; kg++){
      uint32_t ap[4];
      ap[0] = packh2(acc[2*kg][0],   acc[2*kg][1]);
      ap[1] = packh2(acc[2*kg][2],   acc[2*kg][3]);
      ap[2] = packh2(acc[2*kg+1][0], acc[2*kg+1][1]);
      ap[3] = packh2(acc[2*kg+1][2], acc[2*kg+1][3]);
#pragma unroll
      for (int p=0;p<8;p++){
        uint32_t bh[4];
        ldsm_x4(bh, vb + (p*16 + ((lane>>4)&1)*8 + (lane&7))*VROWB
                       + (kg*16 + (((lane>>3)&1)<<3))*2);
        mma16816h(o[2*p+0], ap, &bh[0]);
        mma16816h(o[2*p+1], ap, &bh[2]);
      }
    }
  }

  // ---- epilogue: normalize -> fp16 aop ----
  const float inv0 = 1.f/l0, inv1 = 1.f/l1;
  const int qrow0 = s0 + wid*16 + (lane>>2);
  const ll rb0 = ((ll)(b*1024 + qrow0))*2048 + h*128;
  const ll rb1 = rb0 + 8LL*2048;
#pragma unroll
  for (int ni=0;ni<16;ni++){
    int col = ni*8 + (lane&3)*2;
    *(uint32_t*)(aop + rb0 + col) = packh2(o[ni][0]*inv0, o[ni][1]*inv0);
    *(uint32_t*)(aop + rb1 + col) = packh2(o[ni][2]*inv1, o[ni][3]*inv1);
  }
}

// ---------------- merged prep: RMSNorm+RoPE (fp16 q/k) | V transpose ----------------
__global__ __launch_bounds__(256)
void prep_qkv(const float* __restrict__ comb,
              const float* __restrict__ cosT, const float* __restrict__ sinT,
              const float* __restrict__ gql, const float* __restrict__ gkl,
              const float* __restrict__ gqg, const float* __restrict__ gkg,
              __half* __restrict__ qp, __half* __restrict__ kp,
              __half* __restrict__ vp)
{
  __shared__ float shbuf[32*33];
  const int t = threadIdx.x;

  if (blockIdx.x >= 2048){
    int b2 = blockIdx.x - 2048;
    const int s0 = (b2 & 31)*32;
    const int c0 = ((b2>>5)&7)*32;
    const int zz = b2>>8;
    const int b = zz>>1, strm = zz&1;
    float (*tt)[33] = (float(*)[33])shbuf;
    const int tx = t&31, ty = t>>5;
    const float* base = comb + (ll)strm*2048*1536;
#pragma unroll
    for (int r=0;r<32;r+=8)
      tt[ty+r][tx] = base[(ll)(b*1024 + s0+ty+r)*1536 + 1280 + c0 + tx];
    __syncthreads();
#pragma unroll
    for (int r=0;r<32;r+=8){
      int v = c0 + ty + r;
      int kh = v>>6, d = v&63;
      ll row = (ll)(b*4+kh)*128 + strm*64 + d;
      vp[row*1024 + s0 + tx] = __float2half_rn(tt[tx][ty+r]);
    }
    return;
  }

  const int bs = blockIdx.x;
  const int b = bs >> 10, s = bs & 1023;
  const float* rl = comb + (ll)bs*1536;
  const float* rg = rl + (ll)2048*1536;

  float sql=0.f, sqg=0.f;
#pragma unroll
  for (int i=t;i<1024;i+=256){ float x=rl[i]; sql+=x*x; float y=rg[i]; sqg+=y*y; }
  float xk=rl[1024+t], yk=rg[1024+t];
  float skl = xk*xk, skg = yk*yk;

  float4* red = (float4*)shbuf;
  float4 v4 = make_float4(sql,sqg,skl,skg);
#pragma unroll
  for (int off=16;off;off>>=1){
    v4.x += __shfl_xor_sync(0xffffffffu, v4.x, off);
    v4.y += __shfl_xor_sync(0xffffffffu, v4.y, off);
    v4.z += __shfl_xor_sync(0xffffffffu, v4.z, off);
    v4.w += __shfl_xor_sync(0xffffffffu, v4.w, off);
  }
  const int w = t>>5, l = t&31;
  if (!l) red[w]=v4;
  __syncthreads();
  if (t==0){
    float4 a = red[0];
    for (int i=1;i<8;i++){ a.x+=red[i].x; a.y+=red[i].y; a.z+=red[i].z; a.w+=red[i].w; }
    red[0]=a;
  }
  __syncthreads();
  float4 tot = red[0];
  const float QF = 0.125f * 1.4426950408889634f;
  const float rql = rsqrtf(tot.x*(1.f/1024.f)+1e-5f) * QF;
  const float rqg = rsqrtf(tot.y*(1.f/1024.f)+1e-5f) * QF;
  const float rkl = rsqrtf(tot.z*(1.f/256.f)+1e-5f);
  const float rkg = rsqrtf(tot.w*(1.f/256.f)+1e-5f);

#pragma unroll
  for (int pp=t; pp<512; pp+=256){
    int h = pp>>5, p = pp&31;
    float c = cosT[s*32+p], sn = sinT[s*32+p];
    int d0 = h*64 + 2*p;
    ll base = (((ll)(b*16+h))*1024 + s)*128;
    float x0 = rl[d0]*rql*gql[d0];
    float x1 = rl[d0+1]*rql*gql[d0+1];
    float y0 = rg[d0]*rqg*gqg[d0];
    float y1 = rg[d0+1]*rqg*gqg[d0+1];
    *(uint32_t*)(qp+base+2*p)    = packh2(x0*c - x1*sn, x0*sn + x1*c);
    *(uint32_t*)(qp+base+64+2*p) = packh2(y0*c - y1*sn, y0*sn + y1*c);
  }
  if (t < 128){
    int kh = t>>5, p = t&31;
    float c = cosT[s*32+p], sn = sinT[s*32+p];
    int gd = kh*64 + 2*p;
    ll base = (((ll)(b*4+kh))*1024 + s)*128;
    float x0 = rl[1024+gd]*rkl*gkl[gd];
    float x1 = rl[1024+gd+1]*rkl*gkl[gd+1];
    float y0 = rg[1024+gd]*rkg*gkg[gd];
    float y1 = rg[1024+gd+1]*rkg*gkg[gd+1];
    *(uint32_t*)(kp+base+2*p)    = packh2(x0*c - x1*sn, x0*sn + x1*c);
    *(uint32_t*)(kp+base+64+2*p) = packh2(y0*c - y1*sn, y0*sn + y1*c);
  }
}

// ---------------- final RMSNorm -> d_out ----------------
__global__ __launch_bounds__(256)
void rmsnorm_out(const float* __restrict__ y, const float* __restrict__ glc,
                 const float* __restrict__ ggc, float* __restrict__ out)
{
  const int row = blockIdx.x;
  const float* g = (row < 2048) ? glc : ggc;
  const float* r = y + (ll)row*1024;
  float* o = out + (ll)row*1024;
  const int t = threadIdx.x;
  float4 v = ((const float4*)r)[t];
  float ss = v.x*v.x + v.y*v.y + v.z*v.z + v.w*v.w;
  __shared__ float sm[8];
#pragma unroll
  for (int o2=16;o2;o2>>=1) ss += __shfl_xor_sync(0xffffffffu,ss,o2);
  const int w=t>>5, l=t&31;
  if (!l) sm[w]=ss;
  __syncthreads();
  ss = sm[0]+sm[1]+sm[2]+sm[3]+sm[4]+sm[5]+sm[6]+sm[7];
  const float rsq = rsqrtf(ss*(1.f/1024.f)+1e-5f);
  float4 gv = ((const float4*)g)[t];
  float4 ov = make_float4(v.x*rsq*gv.x, v.y*rsq*gv.y, v.z*rsq*gv.z, v.w*rsq*gv.w);
  ((float4*)o)[t]=ov;
}

// ---------------- launch ----------------
extern "C" void kernel_launch(void* const* d_in, const int* in_sizes, int n_in,
                              void* d_out, int out_size)
{
  (void)in_sizes; (void)n_in; (void)out_size;
  const float* local_c  = (const float*)d_in[0];
  const float* global_c = (const float*)d_in[1];
  const float* fcos     = (const float*)d_in[2];
  const float* fsin     = (const float*)d_in[3];
  const float* W_lc     = (const float*)d_in[4];
  const float* W_gc     = (const float*)d_in[5];
  const float* g_q_lc   = (const float*)d_in[6];
  const float* g_k_lc   = (const float*)d_in[7];
  const float* g_q_gc   = (const float*)d_in[8];
  const float* g_k_gc   = (const float*)d_in[9];
  const float* W_local  = (const float*)d_in[10];
  const float* b_local  = (const float*)d_in[11];
  const float* g_lc_out = (const float*)d_in[12];
  const float* W_global = (const float*)d_in[13];
  const float* b_global = (const float*)d_in[14];
  const float* g_gc_out = (const float*)d_in[15];

  __half *xp,*wq,*wp,*qp,*kp,*vtp,*aop;
  float *comb,*yy;
  cudaGetSymbolAddress((void**)&xp,  g_x_pack);
  cudaGetSymbolAddress((void**)&wq,  g_wqkv_pack);
  cudaGetSymbolAddress((void**)&wp,  g_wpr_pack);
  cudaGetSymbolAddress((void**)&comb, g_comb);
  cudaGetSymbolAddress((void**)&qp,  g_q);
  cudaGetSymbolAddress((void**)&kp,  g_k);
  cudaGetSymbolAddress((void**)&vtp, g_vT);
  cudaGetSymbolAddress((void**)&aop, g_ao);
  cudaGetSymbolAddress((void**)&yy,  g_yy);

  const int SM_QKV = 3*((128+96)*144);   // 96768
  const int SM_OUT = 3*((128+128)*144);  // 110592
  static int attr_done = 0;
  if (!attr_done){
    cudaFuncSetAttribute((const void*)gemm_mma<false,6,2>,
                         cudaFuncAttributeMaxDynamicSharedMemorySize, SM_QKV);
    cudaFuncSetAttribute((const void*)gemm_mma<true,8,1>,
                         cudaFuncAttributeMaxDynamicSharedMemorySize, SM_OUT);
    cudaFuncSetAttribute((const void*)flash_attn,
                         cudaFuncAttributeMaxDynamicSharedMemorySize, FSMEM);
    attr_done = 1;
  }

  // 0) operand packs
  packAll<<<5632,256>>>(local_c, global_c, W_lc, W_gc, W_local, W_global, xp, wq, wp);

  // 1) QKV projections, fp16 2-term (x exact split, W fp16), N-tile 96
  //    M=2048, N=1536, Kreal=1024, lgn1=4
  gemm_mma<false,6,2><<<dim3(16,16,2),256,SM_QKV>>>(xp, wq, comb, nullptr, nullptr,
     1024, 4, 2048, 1024, 1536, 2048LL*2048, 1536LL*1024, 2048LL*1536, 1.f);

  // 2) merged rmsnorm+rope (fp16 q/k) + V transpose (fp16)
  prep_qkv<<<3072,256>>>(comb, fcos, fsin, g_q_lc, g_k_lc, g_q_gc, g_k_gc, qp, kp, vtp);

  // 3) fused attention, all fp16 -> aop
  flash_attn<<<dim3(8,32),256,FSMEM>>>(qp, kp, vtp, aop);

  // 4) merged output projections, fp16 1-term + bias  (M=2048,N=2048,K=2048,lgn1=5)
  gemm_mma<true,8,1><<<dim3(16,16,1),256,SM_OUT>>>(aop, wp, yy, b_local, b_global,
     2048, 5, 2048, 2048, 1024, 0,0,0, 1.f);

  // 5) final rmsnorm -> d_out
  rmsnorm_out<<<4096,256>>>(yy, g_lc_out, g_gc_out, (float*)d_out);
}